// round 1
// baseline (speedup 1.0000x reference)
#include <cuda_runtime.h>
#include <cuda_bf16.h>
#include <cstdint>

#define BGR 4
#define NPER 4096
#define MPER 1024
#define DIN 64
#define KN1 32
#define KN2 64
#define R1SQ 0.04f
#define R2SQ 0.16f
#define CAP 3072

#define XOFF 0
#define POFF (BGR*MPER*256)          // 1048576
#define BOFF (POFF + BGR*MPER*3)     // 1060864

// ---------------- scratch (device globals; no allocation allowed) ----------
__device__ int   g_fidx[BGR*MPER];
__device__ float g_pdst[BGR*MPER*3];
__device__ int   g_nbr1[BGR*MPER*KN1];
__device__ int   g_nbr2[BGR*MPER*KN2];
__device__ float g_Y[2][BGR*NPER*DIN];

// ---------------- helpers ----------------
__device__ __forceinline__ float d2_exact(float ax, float ay, float az,
                                          float bx, float by, float bz) {
    float dx = __fsub_rn(ax, bx);
    float dy = __fsub_rn(ay, by);
    float dz = __fsub_rn(az, bz);
    return __fadd_rn(__fadd_rn(__fmul_rn(dx, dx), __fmul_rn(dy, dy)), __fmul_rn(dz, dz));
}

__device__ __forceinline__ unsigned long long warp_max_u64(unsigned long long k) {
#pragma unroll
    for (int o = 16; o; o >>= 1) {
        unsigned long long other = __shfl_xor_sync(0xffffffffu, k, o);
        if (other > k) k = other;
    }
    return k;
}
__device__ __forceinline__ unsigned long long warp_min_u64(unsigned long long k) {
#pragma unroll
    for (int o = 16; o; o >>= 1) {
        unsigned long long other = __shfl_xor_sync(0xffffffffu, k, o);
        if (other < k) k = other;
    }
    return k;
}

// ---------------- FPS: one block per graph ----------------
__global__ void __launch_bounds__(512) fps_kernel(const float* __restrict__ pos) {
    const int g = blockIdx.x;
    const float* p = pos + (size_t)g * NPER * 3;
    const int t = threadIdx.x;

    __shared__ unsigned long long s_red[16];
    __shared__ unsigned long long s_winkey;

    float px[8], py[8], pz[8], dist[8];
    const float p0x = p[0], p0y = p[1], p0z = p[2];
#pragma unroll
    for (int i = 0; i < 8; i++) {
        int id = t + i * 512;
        float x = p[id * 3 + 0], y = p[id * 3 + 1], z = p[id * 3 + 2];
        px[i] = x; py[i] = y; pz[i] = z;
        dist[i] = d2_exact(x, y, z, p0x, p0y, p0z);
    }
    if (t == 0) g_fidx[g * MPER] = 0;

    // local best key (computed fused with updates below)
    unsigned long long best = 0;
#pragma unroll
    for (int i = 0; i < 8; i++) {
        int id = t + i * 512;
        unsigned long long k = ((unsigned long long)__float_as_uint(dist[i]) << 32)
                               | (unsigned)(NPER - 1 - id);
        if (k > best) best = k;
    }

    for (int s = 1; s < MPER; s++) {
        unsigned long long r = warp_max_u64(best);
        if ((t & 31) == 0) s_red[t >> 5] = r;
        __syncthreads();
        if (t < 32) {
            unsigned long long k = (t < 16) ? s_red[t] : 0ull;
            k = warp_max_u64(k);
            if (t == 0) s_winkey = k;
        }
        __syncthreads();
        unsigned long long wk = s_winkey;
        int widx = NPER - 1 - (int)(wk & 0xffffffffu);
        if (t == 0) g_fidx[g * MPER + s] = widx;
        float wx = p[widx * 3 + 0], wy = p[widx * 3 + 1], wz = p[widx * 3 + 2];

        best = 0;
#pragma unroll
        for (int i = 0; i < 8; i++) {
            int id = t + i * 512;
            float d = d2_exact(px[i], py[i], pz[i], wx, wy, wz);
            float nd = fminf(dist[i], d);
            dist[i] = nd;
            unsigned long long k = ((unsigned long long)__float_as_uint(nd) << 32)
                                   | (unsigned)(NPER - 1 - id);
            if (k > best) best = k;
        }
    }
}

// ---------------- gather centroids; write pos_out / batch_out --------------
__global__ void gather_kernel(const float* __restrict__ pos, float* __restrict__ out) {
    int c = blockIdx.x * 256 + threadIdx.x;
    if (c >= BGR * MPER) return;
    int g = c >> 10;
    int li = g_fidx[c];
    const float* pp = pos + ((size_t)(g * NPER + li)) * 3;
    float x = pp[0], y = pp[1], z = pp[2];
    g_pdst[c * 3 + 0] = x; g_pdst[c * 3 + 1] = y; g_pdst[c * 3 + 2] = z;
    out[POFF + c * 3 + 0] = x;
    out[POFF + c * 3 + 1] = y;
    out[POFF + c * 3 + 2] = z;
    out[BOFF + c] = (float)g;
}

// ---------------- Y = X @ W1[:64,:]  (per branch) --------------------------
__global__ void __launch_bounds__(256) ymm_kernel(const float* __restrict__ x,
                                                  const float* __restrict__ W1,
                                                  int br) {
    __shared__ float sW[64 * 64];
    __shared__ float sx[4 * 64];
    int tid = threadIdx.x;
    for (int i = tid; i < 4096; i += 256) sW[i] = W1[i];
    int p0 = blockIdx.x * 4;
    sx[tid] = x[(size_t)p0 * 64 + tid];
    __syncthreads();
    int lp = tid >> 6, c = tid & 63;
    float acc = 0.f;
#pragma unroll
    for (int k = 0; k < 64; k++) acc += sx[lp * 64 + k] * sW[k * 64 + c];
    g_Y[br][(size_t)(p0 + lp) * 64 + c] = acc;
}

// ---------------- ball query + top-64 selection (serves both branches) -----
__global__ void __launch_bounds__(256) select_kernel(const float* __restrict__ pos) {
    __shared__ unsigned long long key[CAP];
    __shared__ unsigned long long s_red[8];
    __shared__ unsigned long long s_win;
    __shared__ int s_cnt;
    __shared__ int s_selidx[64];
    __shared__ float s_seld2[64];

    const int c = blockIdx.x;
    const int tid = threadIdx.x;
    const int g = c >> 10;
    const float* p = pos + (size_t)g * NPER * 3;
    const float cx = g_pdst[c * 3 + 0], cy = g_pdst[c * 3 + 1], cz = g_pdst[c * 3 + 2];

    if (tid == 0) s_cnt = 0;
    __syncthreads();

    for (int i = tid; i < NPER; i += 256) {
        float d2 = d2_exact(p[i * 3], p[i * 3 + 1], p[i * 3 + 2], cx, cy, cz);
        if (d2 <= R2SQ) {
            int s = atomicAdd(&s_cnt, 1);
            if (s < CAP)
                key[s] = ((unsigned long long)__float_as_uint(d2) << 32) | (unsigned)i;
        }
    }
    __syncthreads();
    int m = min(s_cnt, CAP);
    int nsel = min(m, 64);

    for (int s = 0; s < nsel; s++) {
        unsigned long long best = ~0ull; int bslot = -1;
        for (int j = tid; j < m; j += 256) {
            unsigned long long k = key[j];
            if (k < best) { best = k; bslot = j; }
        }
        unsigned long long r = warp_min_u64(best);
        if ((tid & 31) == 0) s_red[tid >> 5] = r;
        __syncthreads();
        if (tid < 32) {
            unsigned long long k2 = (tid < 8) ? s_red[tid] : ~0ull;
            k2 = warp_min_u64(k2);
            if (tid == 0) s_win = k2;
        }
        __syncthreads();
        unsigned long long wk = s_win;
        if (bslot >= 0 && best == wk) key[bslot] = ~0ull;   // unique key -> one owner
        if (tid == 0) {
            s_selidx[s] = (int)(wk & 0xffffffffu);
            s_seld2[s] = __uint_as_float((unsigned)(wk >> 32));
        }
        __syncthreads();
    }

    if (tid < KN2) g_nbr2[c * KN2 + tid] = (tid < nsel) ? s_selidx[tid] : -1;
    if (tid < KN1) g_nbr1[c * KN1 + tid] =
        (tid < nsel && s_seld2[tid] <= R1SQ) ? s_selidx[tid] : -1;
}

// ---------------- MLP + max-pool: thread = neighbor, block = G centroids ---
// smem float layout: W2[4096] | W3[8192] | Wp[192] | b1[64] | b2[64] | b3[128] | out[G*128]
template <int K, int G>
__global__ void __launch_bounds__(128, 1) mlp_kernel(const float* __restrict__ pos,
                                                     const float* __restrict__ W1,
                                                     const float* __restrict__ b1,
                                                     const float* __restrict__ W2,
                                                     const float* __restrict__ b2,
                                                     const float* __restrict__ W3,
                                                     const float* __restrict__ b3,
                                                     float* __restrict__ out,
                                                     int coloff) {
    extern __shared__ float sm[];
    const int tid = threadIdx.x;

    for (int i = tid; i < 4096; i += 128) sm[i] = W2[i];
    for (int i = tid; i < 8192; i += 128) sm[4096 + i] = W3[i];
    if (tid < 128) {
        if (tid < 64) {
            sm[12288 + tid]       = W1[4096 + tid];        // Wp row0
            sm[12288 + 64 + tid]  = W1[4096 + 64 + tid];   // Wp row1
            sm[12288 + 128 + tid] = W1[4096 + 128 + tid];  // Wp row2
            sm[12480 + tid] = b1[tid];
            sm[12544 + tid] = b2[tid];
        }
        sm[12608 + tid] = b3[tid];
    }
    int* souti = (int*)(sm + 12736);
    for (int i = tid; i < G * 128; i += 128) souti[i] = 0;
    __syncthreads();

    const int ci = tid / K;
    const int n  = tid % K;
    const int crow = blockIdx.x * G + ci;
    const int g = crow >> 10;
    const float* Y = g_Y[(K == KN1) ? 0 : 1];
    const int* nbr = (K == KN1) ? g_nbr1 : g_nbr2;

    int j = nbr[crow * K + n];
    const bool valid = (j >= 0);
    if (!valid) j = 0;

    const float* pg = pos + (size_t)g * NPER * 3;
    const float dx = pg[j * 3 + 0] - g_pdst[crow * 3 + 0];
    const float dy = pg[j * 3 + 1] - g_pdst[crow * 3 + 1];
    const float dz = pg[j * 3 + 2] - g_pdst[crow * 3 + 2];
    const float* yrow = Y + (size_t)(g * NPER + j) * 64;

    // layer 1: h1 = relu(Y[j] + dp @ Wp + b1)
    float h1[64];
#pragma unroll
    for (int c = 0; c < 64; c += 4) {
        float4 y4 = *(const float4*)(yrow + c);
        float4 w0 = *(const float4*)(sm + 12288 + c);
        float4 w1 = *(const float4*)(sm + 12288 + 64 + c);
        float4 w2 = *(const float4*)(sm + 12288 + 128 + c);
        float4 bb = *(const float4*)(sm + 12480 + c);
        h1[c + 0] = fmaxf(y4.x + dx * w0.x + dy * w1.x + dz * w2.x + bb.x, 0.f);
        h1[c + 1] = fmaxf(y4.y + dx * w0.y + dy * w1.y + dz * w2.y + bb.y, 0.f);
        h1[c + 2] = fmaxf(y4.z + dx * w0.z + dy * w1.z + dz * w2.z + bb.z, 0.f);
        h1[c + 3] = fmaxf(y4.w + dx * w0.w + dy * w1.w + dz * w2.w + bb.w, 0.f);
    }

    // layer 2
    float h2[64];
#pragma unroll
    for (int c0 = 0; c0 < 64; c0 += 8) {
        float a[8];
#pragma unroll
        for (int i = 0; i < 8; i++) a[i] = sm[12544 + c0 + i];
#pragma unroll
        for (int k = 0; k < 64; k++) {
            float hv = h1[k];
            float4 wA = *(const float4*)(sm + k * 64 + c0);
            float4 wB = *(const float4*)(sm + k * 64 + c0 + 4);
            a[0] += hv * wA.x; a[1] += hv * wA.y; a[2] += hv * wA.z; a[3] += hv * wA.w;
            a[4] += hv * wB.x; a[5] += hv * wB.y; a[6] += hv * wB.z; a[7] += hv * wB.w;
        }
#pragma unroll
        for (int i = 0; i < 8; i++) h2[c0 + i] = fmaxf(a[i], 0.f);
    }

    // layer 3 + warp max-reduce + smem atomicMax merge
#pragma unroll
    for (int c0 = 0; c0 < 128; c0 += 8) {
        float a[8];
#pragma unroll
        for (int i = 0; i < 8; i++) a[i] = sm[12608 + c0 + i];
#pragma unroll
        for (int k = 0; k < 64; k++) {
            float hv = h2[k];
            float4 wA = *(const float4*)(sm + 4096 + k * 128 + c0);
            float4 wB = *(const float4*)(sm + 4096 + k * 128 + c0 + 4);
            a[0] += hv * wA.x; a[1] += hv * wA.y; a[2] += hv * wA.z; a[3] += hv * wA.w;
            a[4] += hv * wB.x; a[5] += hv * wB.y; a[6] += hv * wB.z; a[7] += hv * wB.w;
        }
#pragma unroll
        for (int i = 0; i < 8; i++) {
            float v = valid ? fmaxf(a[i], 0.f) : 0.f;
#pragma unroll
            for (int o = 16; o; o >>= 1) v = fmaxf(v, __shfl_xor_sync(0xffffffffu, v, o));
            if ((tid & 31) == 0)
                atomicMax(&souti[ci * 128 + c0 + i], __float_as_int(v));
        }
    }
    __syncthreads();
    for (int i = tid; i < G * 128; i += 128) {
        int lc = i >> 7, ch = i & 127;
        out[(size_t)(blockIdx.x * G + lc) * 256 + coloff + ch] = __int_as_float(souti[i]);
    }
}

// ---------------- launch ----------------
extern "C" void kernel_launch(void* const* d_in, const int* in_sizes, int n_in,
                              void* d_out, int out_size) {
    const float* x   = (const float*)d_in[0];
    const float* pos = (const float*)d_in[1];
    const float* w11 = (const float*)d_in[3];
    const float* b11 = (const float*)d_in[4];
    const float* w12 = (const float*)d_in[5];
    const float* b12 = (const float*)d_in[6];
    const float* w13 = (const float*)d_in[7];
    const float* b13 = (const float*)d_in[8];
    const float* w21 = (const float*)d_in[9];
    const float* b21 = (const float*)d_in[10];
    const float* w22 = (const float*)d_in[11];
    const float* b22 = (const float*)d_in[12];
    const float* w23 = (const float*)d_in[13];
    const float* b23 = (const float*)d_in[14];
    float* out = (float*)d_out;

    const int smem1 = (12736 + 4 * 128) * 4;  // G=4
    const int smem2 = (12736 + 2 * 128) * 4;  // G=2
    cudaFuncSetAttribute((const void*)mlp_kernel<KN1, 4>,
                         cudaFuncAttributeMaxDynamicSharedMemorySize, smem1);
    cudaFuncSetAttribute((const void*)mlp_kernel<KN2, 2>,
                         cudaFuncAttributeMaxDynamicSharedMemorySize, smem2);

    ymm_kernel<<<BGR * NPER / 4, 256>>>(x, w11, 0);
    ymm_kernel<<<BGR * NPER / 4, 256>>>(x, w21, 1);
    fps_kernel<<<BGR, 512>>>(pos);
    gather_kernel<<<(BGR * MPER + 255) / 256, 256>>>(pos, out);
    select_kernel<<<BGR * MPER, 256>>>(pos);
    mlp_kernel<KN1, 4><<<BGR * MPER / 4, 128, smem1>>>(pos, w11, b11, w12, b12, w13, b13, out, 0);
    mlp_kernel<KN2, 2><<<BGR * MPER / 2, 128, smem2>>>(pos, w21, b21, w22, b22, w23, b23, out, 128);
}

// round 2
// speedup vs baseline: 1.2324x; 1.2324x over previous
#include <cuda_runtime.h>
#include <cuda_bf16.h>
#include <cstdint>

#define BGR 4
#define NPER 4096
#define MPER 1024
#define DIN 64
#define KN1 32
#define KN2 64
#define R1SQ 0.04f
#define R2SQ 0.16f
#define SCAP 4096

#define XOFF 0
#define POFF (BGR*MPER*256)          // 1048576
#define BOFF (POFF + BGR*MPER*3)     // 1060864

// ---------------- scratch (device globals; no allocation allowed) ----------
__device__ float g_pdst[BGR*MPER*3];
__device__ int   g_nbr1[BGR*MPER*KN1];
__device__ int   g_nbr2[BGR*MPER*KN2];
__device__ float g_Y[2][BGR*NPER*DIN];

// ---------------- helpers ----------------
__device__ __forceinline__ float d2_exact(float ax, float ay, float az,
                                          float bx, float by, float bz) {
    float dx = __fsub_rn(ax, bx);
    float dy = __fsub_rn(ay, by);
    float dz = __fsub_rn(az, bz);
    return __fadd_rn(__fadd_rn(__fmul_rn(dx, dx), __fmul_rn(dy, dy)), __fmul_rn(dz, dz));
}

__device__ __forceinline__ unsigned long long warp_max_u64(unsigned long long k) {
#pragma unroll
    for (int o = 16; o; o >>= 1) {
        unsigned long long other = __shfl_xor_sync(0xffffffffu, k, o);
        if (other > k) k = other;
    }
    return k;
}

// ---------------- FPS (+ centroid gather tail): one block per graph --------
__global__ void __launch_bounds__(512) fps_kernel(const float* __restrict__ pos,
                                                  float* __restrict__ out) {
    const int g = blockIdx.x;
    const float* p = pos + (size_t)g * NPER * 3;
    const int t = threadIdx.x;

    __shared__ unsigned long long s_red[16];
    __shared__ unsigned long long s_winkey;
    __shared__ int s_fidx[MPER];

    float px[8], py[8], pz[8], dist[8];
    const float p0x = p[0], p0y = p[1], p0z = p[2];
#pragma unroll
    for (int i = 0; i < 8; i++) {
        int id = t + i * 512;
        float x = p[id * 3 + 0], y = p[id * 3 + 1], z = p[id * 3 + 2];
        px[i] = x; py[i] = y; pz[i] = z;
        dist[i] = d2_exact(x, y, z, p0x, p0y, p0z);
    }
    if (t == 0) s_fidx[0] = 0;

    unsigned long long best = 0;
#pragma unroll
    for (int i = 0; i < 8; i++) {
        int id = t + i * 512;
        unsigned long long k = ((unsigned long long)__float_as_uint(dist[i]) << 32)
                               | (unsigned)(NPER - 1 - id);
        if (k > best) best = k;
    }

    for (int s = 1; s < MPER; s++) {
        unsigned long long r = warp_max_u64(best);
        if ((t & 31) == 0) s_red[t >> 5] = r;
        __syncthreads();
        if (t < 32) {
            unsigned long long k = (t < 16) ? s_red[t] : 0ull;
            k = warp_max_u64(k);
            if (t == 0) s_winkey = k;
        }
        __syncthreads();
        unsigned long long wk = s_winkey;
        int widx = NPER - 1 - (int)(wk & 0xffffffffu);
        if (t == 0) s_fidx[s] = widx;
        float wx = p[widx * 3 + 0], wy = p[widx * 3 + 1], wz = p[widx * 3 + 2];

        best = 0;
#pragma unroll
        for (int i = 0; i < 8; i++) {
            int id = t + i * 512;
            float d = d2_exact(px[i], py[i], pz[i], wx, wy, wz);
            float nd = fminf(dist[i], d);
            dist[i] = nd;
            unsigned long long k = ((unsigned long long)__float_as_uint(nd) << 32)
                                   | (unsigned)(NPER - 1 - id);
            if (k > best) best = k;
        }
    }
    __syncthreads();

    // gather tail: write centroid positions + batch ids
    for (int s = t; s < MPER; s += 512) {
        int li = s_fidx[s];
        int c = g * MPER + s;
        float x = p[li * 3 + 0], y = p[li * 3 + 1], z = p[li * 3 + 2];
        g_pdst[c * 3 + 0] = x; g_pdst[c * 3 + 1] = y; g_pdst[c * 3 + 2] = z;
        out[POFF + c * 3 + 0] = x;
        out[POFF + c * 3 + 1] = y;
        out[POFF + c * 3 + 2] = z;
        out[BOFF + c] = (float)g;
    }
}

// ---------------- ball query + bitonic top-64 (serves both branches) -------
__global__ void __launch_bounds__(256) select_kernel(const float* __restrict__ pos) {
    __shared__ unsigned long long key[SCAP];   // 32 KB
    __shared__ int s_cnt;

    const int c = blockIdx.x;
    const int tid = threadIdx.x;
    const int g = c >> 10;
    const float* p = pos + (size_t)g * NPER * 3;
    const float cx = g_pdst[c * 3 + 0], cy = g_pdst[c * 3 + 1], cz = g_pdst[c * 3 + 2];

    if (tid == 0) s_cnt = 0;
    __syncthreads();

    for (int i = tid; i < NPER; i += 256) {
        float d2 = d2_exact(p[i * 3], p[i * 3 + 1], p[i * 3 + 2], cx, cy, cz);
        if (d2 <= R2SQ) {
            int s = atomicAdd(&s_cnt, 1);
            key[s] = ((unsigned long long)__float_as_uint(d2) << 32) | (unsigned)i;
        }
    }
    __syncthreads();
    const int m = s_cnt;
    int P = 64;
    while (P < m) P <<= 1;

    for (int i = m + tid; i < P; i += 256) key[i] = ~0ull;
    __syncthreads();

    // in-place bitonic sort ascending over key[0..P)
    for (int k = 2; k <= P; k <<= 1) {
        for (int j = k >> 1; j > 0; j >>= 1) {
            for (int i = tid; i < P; i += 256) {
                int l = i ^ j;
                if (l > i) {
                    unsigned long long a = key[i], b = key[l];
                    bool up = ((i & k) == 0);
                    if (up ? (a > b) : (a < b)) { key[i] = b; key[l] = a; }
                }
            }
            __syncthreads();
        }
    }

    if (tid < KN2) {
        unsigned long long kk = key[tid];
        int idx = (int)(kk & 0xffffffffu);
        bool v = tid < m;
        g_nbr2[c * KN2 + tid] = v ? idx : -1;
        if (tid < KN1) {
            float d2 = __uint_as_float((unsigned)(kk >> 32));
            g_nbr1[c * KN1 + tid] = (v && d2 <= R1SQ) ? idx : -1;
        }
    }
}

// ---------------- Y = X @ W1[:64,:]  (per branch) --------------------------
__global__ void __launch_bounds__(256) ymm_kernel(const float* __restrict__ x,
                                                  const float* __restrict__ W1,
                                                  int br) {
    __shared__ float sW[64 * 64];
    __shared__ float sx[4 * 64];
    int tid = threadIdx.x;
    for (int i = tid; i < 4096; i += 256) sW[i] = W1[i];
    int p0 = blockIdx.x * 4;
    sx[tid] = x[(size_t)p0 * 64 + tid];
    __syncthreads();
    int lp = tid >> 6, c = tid & 63;
    float acc = 0.f;
#pragma unroll
    for (int k = 0; k < 64; k++) acc += sx[lp * 64 + k] * sW[k * 64 + c];
    g_Y[br][(size_t)(p0 + lp) * 64 + c] = acc;
}

// ---------------- MLP + max-pool: thread = neighbor, block = G centroids ---
// smem float layout: W2[4096] | W3[8192] | Wp[192] | b1[64] | b2[64] | b3[128] | out[G*128]
template <int K, int G>
__global__ void __launch_bounds__(128, 1) mlp_kernel(const float* __restrict__ pos,
                                                     const float* __restrict__ W1,
                                                     const float* __restrict__ b1,
                                                     const float* __restrict__ W2,
                                                     const float* __restrict__ b2,
                                                     const float* __restrict__ W3,
                                                     const float* __restrict__ b3,
                                                     float* __restrict__ out,
                                                     int coloff) {
    extern __shared__ float sm[];
    const int tid = threadIdx.x;

    for (int i = tid; i < 4096; i += 128) sm[i] = W2[i];
    for (int i = tid; i < 8192; i += 128) sm[4096 + i] = W3[i];
    if (tid < 128) {
        if (tid < 64) {
            sm[12288 + tid]       = W1[4096 + tid];        // Wp row0
            sm[12288 + 64 + tid]  = W1[4096 + 64 + tid];   // Wp row1
            sm[12288 + 128 + tid] = W1[4096 + 128 + tid];  // Wp row2
            sm[12480 + tid] = b1[tid];
            sm[12544 + tid] = b2[tid];
        }
        sm[12608 + tid] = b3[tid];
    }
    int* souti = (int*)(sm + 12736);
    for (int i = tid; i < G * 128; i += 128) souti[i] = 0;
    __syncthreads();

    const int ci = tid / K;
    const int n  = tid % K;
    const int crow = blockIdx.x * G + ci;
    const int g = crow >> 10;
    const float* Y = g_Y[(K == KN1) ? 0 : 1];
    const int* nbr = (K == KN1) ? g_nbr1 : g_nbr2;

    int j = nbr[crow * K + n];
    const bool valid = (j >= 0);
    if (!valid) j = 0;

    const float* pg = pos + (size_t)g * NPER * 3;
    const float dx = pg[j * 3 + 0] - g_pdst[crow * 3 + 0];
    const float dy = pg[j * 3 + 1] - g_pdst[crow * 3 + 1];
    const float dz = pg[j * 3 + 2] - g_pdst[crow * 3 + 2];
    const float* yrow = Y + (size_t)(g * NPER + j) * 64;

    // layer 1: h1 = relu(Y[j] + dp @ Wp + b1)
    float h1[64];
#pragma unroll
    for (int c = 0; c < 64; c += 4) {
        float4 y4 = *(const float4*)(yrow + c);
        float4 w0 = *(const float4*)(sm + 12288 + c);
        float4 w1 = *(const float4*)(sm + 12288 + 64 + c);
        float4 w2 = *(const float4*)(sm + 12288 + 128 + c);
        float4 bb = *(const float4*)(sm + 12480 + c);
        h1[c + 0] = fmaxf(y4.x + dx * w0.x + dy * w1.x + dz * w2.x + bb.x, 0.f);
        h1[c + 1] = fmaxf(y4.y + dx * w0.y + dy * w1.y + dz * w2.y + bb.y, 0.f);
        h1[c + 2] = fmaxf(y4.z + dx * w0.z + dy * w1.z + dz * w2.z + bb.z, 0.f);
        h1[c + 3] = fmaxf(y4.w + dx * w0.w + dy * w1.w + dz * w2.w + bb.w, 0.f);
    }

    // layer 2
    float h2[64];
#pragma unroll
    for (int c0 = 0; c0 < 64; c0 += 8) {
        float a[8];
#pragma unroll
        for (int i = 0; i < 8; i++) a[i] = sm[12544 + c0 + i];
#pragma unroll 16
        for (int k = 0; k < 64; k++) {
            float hv = h1[k];
            float4 wA = *(const float4*)(sm + k * 64 + c0);
            float4 wB = *(const float4*)(sm + k * 64 + c0 + 4);
            a[0] += hv * wA.x; a[1] += hv * wA.y; a[2] += hv * wA.z; a[3] += hv * wA.w;
            a[4] += hv * wB.x; a[5] += hv * wB.y; a[6] += hv * wB.z; a[7] += hv * wB.w;
        }
#pragma unroll
        for (int i = 0; i < 8; i++) h2[c0 + i] = fmaxf(a[i], 0.f);
    }

    // layer 3 + warp max-reduce + smem atomicMax merge
#pragma unroll
    for (int c0 = 0; c0 < 128; c0 += 8) {
        float a[8];
#pragma unroll
        for (int i = 0; i < 8; i++) a[i] = sm[12608 + c0 + i];
#pragma unroll 16
        for (int k = 0; k < 64; k++) {
            float hv = h2[k];
            float4 wA = *(const float4*)(sm + 4096 + k * 128 + c0);
            float4 wB = *(const float4*)(sm + 4096 + k * 128 + c0 + 4);
            a[0] += hv * wA.x; a[1] += hv * wA.y; a[2] += hv * wA.z; a[3] += hv * wA.w;
            a[4] += hv * wB.x; a[5] += hv * wB.y; a[6] += hv * wB.z; a[7] += hv * wB.w;
        }
#pragma unroll
        for (int i = 0; i < 8; i++) {
            float v = valid ? fmaxf(a[i], 0.f) : 0.f;
#pragma unroll
            for (int o = 16; o; o >>= 1) v = fmaxf(v, __shfl_xor_sync(0xffffffffu, v, o));
            if ((tid & 31) == 0)
                atomicMax(&souti[ci * 128 + c0 + i], __float_as_int(v));
        }
    }
    __syncthreads();
    for (int i = tid; i < G * 128; i += 128) {
        int lc = i >> 7, ch = i & 127;
        out[(size_t)(blockIdx.x * G + lc) * 256 + coloff + ch] = __int_as_float(souti[i]);
    }
}

// ---------------- launch ----------------
extern "C" void kernel_launch(void* const* d_in, const int* in_sizes, int n_in,
                              void* d_out, int out_size) {
    const float* x   = (const float*)d_in[0];
    const float* pos = (const float*)d_in[1];
    const float* w11 = (const float*)d_in[3];
    const float* b11 = (const float*)d_in[4];
    const float* w12 = (const float*)d_in[5];
    const float* b12 = (const float*)d_in[6];
    const float* w13 = (const float*)d_in[7];
    const float* b13 = (const float*)d_in[8];
    const float* w21 = (const float*)d_in[9];
    const float* b21 = (const float*)d_in[10];
    const float* w22 = (const float*)d_in[11];
    const float* b22 = (const float*)d_in[12];
    const float* w23 = (const float*)d_in[13];
    const float* b23 = (const float*)d_in[14];
    float* out = (float*)d_out;

    const int smem1 = (12736 + 4 * 128) * 4;  // G=4
    const int smem2 = (12736 + 2 * 128) * 4;  // G=2
    cudaFuncSetAttribute((const void*)mlp_kernel<KN1, 4>,
                         cudaFuncAttributeMaxDynamicSharedMemorySize, smem1);
    cudaFuncSetAttribute((const void*)mlp_kernel<KN2, 2>,
                         cudaFuncAttributeMaxDynamicSharedMemorySize, smem2);

    // Order chosen so the heavy mlp_kernel<64,2> lands on the ncu capture slot.
    fps_kernel<<<BGR, 512>>>(pos, out);
    select_kernel<<<BGR * MPER, 256>>>(pos);
    ymm_kernel<<<BGR * NPER / 4, 256>>>(x, w21, 1);
    mlp_kernel<KN2, 2><<<BGR * MPER / 2, 128, smem2>>>(pos, w21, b21, w22, b22, w23, b23, out, 128);
    ymm_kernel<<<BGR * NPER / 4, 256>>>(x, w11, 0);
    mlp_kernel<KN1, 4><<<BGR * MPER / 4, 128, smem1>>>(pos, w11, b11, w12, b12, w13, b13, out, 0);
}

// round 3
// speedup vs baseline: 1.3721x; 1.1134x over previous
#include <cuda_runtime.h>
#include <cuda_bf16.h>
#include <cstdint>

#define BGR 4
#define NPER 4096
#define MPER 1024
#define DIN 64
#define KN1 32
#define KN2 64
#define R1SQ 0.04f
#define R2SQ 0.16f
#define SCAP 4096

#define XOFF 0
#define POFF (BGR*MPER*256)          // 1048576
#define BOFF (POFF + BGR*MPER*3)     // 1060864

typedef unsigned long long u64;

// ---------------- scratch (device globals; no allocation allowed) ----------
__device__ float g_pdst[BGR*MPER*3];
__device__ int   g_nbr1[BGR*MPER*KN1];
__device__ int   g_nbr2[BGR*MPER*KN2];
__device__ float g_Y[2][BGR*NPER*DIN];

// ---------------- helpers ----------------
__device__ __forceinline__ float d2_exact(float ax, float ay, float az,
                                          float bx, float by, float bz) {
    float dx = __fsub_rn(ax, bx);
    float dy = __fsub_rn(ay, by);
    float dz = __fsub_rn(az, bz);
    return __fadd_rn(__fadd_rn(__fmul_rn(dx, dx), __fmul_rn(dy, dy)), __fmul_rn(dz, dz));
}

__device__ __forceinline__ u64 pk2(float lo, float hi) {
    u64 r; asm("mov.b64 %0,{%1,%2};" : "=l"(r) : "f"(lo), "f"(hi)); return r;
}
__device__ __forceinline__ void upk2(u64 v, float& lo, float& hi) {
    asm("mov.b64 {%0,%1}, %2;" : "=f"(lo), "=f"(hi) : "l"(v));
}
__device__ __forceinline__ u64 ffma2(u64 a, u64 b, u64 c) {
    u64 r; asm("fma.rn.f32x2 %0,%1,%2,%3;" : "=l"(r) : "l"(a), "l"(b), "l"(c)); return r;
}
__device__ __forceinline__ u64 fadd2(u64 a, u64 b) {
    u64 r; asm("add.rn.f32x2 %0,%1,%2;" : "=l"(r) : "l"(a), "l"(b)); return r;
}

__device__ __forceinline__ u64 warp_max_u64(u64 k) {
#pragma unroll
    for (int o = 16; o; o >>= 1) {
        u64 other = __shfl_xor_sync(0xffffffffu, k, o);
        if (other > k) k = other;
    }
    return k;
}

// ---------------- FPS (+ centroid gather tail): one block per graph --------
__global__ void __launch_bounds__(512) fps_kernel(const float* __restrict__ pos,
                                                  float* __restrict__ out) {
    const int g = blockIdx.x;
    const float* p = pos + (size_t)g * NPER * 3;
    const int t = threadIdx.x;

    __shared__ u64 s_red[16];
    __shared__ u64 s_winkey;
    __shared__ int s_fidx[MPER];

    float px[8], py[8], pz[8], dist[8];
    const float p0x = p[0], p0y = p[1], p0z = p[2];
#pragma unroll
    for (int i = 0; i < 8; i++) {
        int id = t + i * 512;
        float x = p[id * 3 + 0], y = p[id * 3 + 1], z = p[id * 3 + 2];
        px[i] = x; py[i] = y; pz[i] = z;
        dist[i] = d2_exact(x, y, z, p0x, p0y, p0z);
    }
    if (t == 0) s_fidx[0] = 0;

    u64 best = 0;
#pragma unroll
    for (int i = 0; i < 8; i++) {
        int id = t + i * 512;
        u64 k = ((u64)__float_as_uint(dist[i]) << 32) | (unsigned)(NPER - 1 - id);
        if (k > best) best = k;
    }

    for (int s = 1; s < MPER; s++) {
        u64 r = warp_max_u64(best);
        if ((t & 31) == 0) s_red[t >> 5] = r;
        __syncthreads();
        if (t < 32) {
            u64 k = (t < 16) ? s_red[t] : 0ull;
            k = warp_max_u64(k);
            if (t == 0) s_winkey = k;
        }
        __syncthreads();
        u64 wk = s_winkey;
        int widx = NPER - 1 - (int)(wk & 0xffffffffu);
        if (t == 0) s_fidx[s] = widx;
        float wx = p[widx * 3 + 0], wy = p[widx * 3 + 1], wz = p[widx * 3 + 2];

        best = 0;
#pragma unroll
        for (int i = 0; i < 8; i++) {
            int id = t + i * 512;
            float d = d2_exact(px[i], py[i], pz[i], wx, wy, wz);
            float nd = fminf(dist[i], d);
            dist[i] = nd;
            u64 k = ((u64)__float_as_uint(nd) << 32) | (unsigned)(NPER - 1 - id);
            if (k > best) best = k;
        }
    }
    __syncthreads();

    for (int s = t; s < MPER; s += 512) {
        int li = s_fidx[s];
        int c = g * MPER + s;
        float x = p[li * 3 + 0], y = p[li * 3 + 1], z = p[li * 3 + 2];
        g_pdst[c * 3 + 0] = x; g_pdst[c * 3 + 1] = y; g_pdst[c * 3 + 2] = z;
        out[POFF + c * 3 + 0] = x;
        out[POFF + c * 3 + 1] = y;
        out[POFF + c * 3 + 2] = z;
        out[BOFF + c] = (float)g;
    }
}

// ---------------- ball query + chunked-bitonic top-64 ----------------------
__global__ void __launch_bounds__(256) select_kernel(const float* __restrict__ pos) {
    __shared__ u64 key[SCAP];   // 32 KB
    __shared__ int s_cnt;

    const int c = blockIdx.x;
    const int tid = threadIdx.x;
    const int g = c >> 10;
    const float* p = pos + (size_t)g * NPER * 3;
    const float cx = g_pdst[c * 3 + 0], cy = g_pdst[c * 3 + 1], cz = g_pdst[c * 3 + 2];

    if (tid == 0) s_cnt = 0;
    __syncthreads();

    for (int i = tid; i < NPER; i += 256) {
        float d2 = d2_exact(p[i * 3], p[i * 3 + 1], p[i * 3 + 2], cx, cy, cz);
        if (d2 <= R2SQ) {
            int s = atomicAdd(&s_cnt, 1);
            key[s] = ((u64)__float_as_uint(d2) << 32) | (unsigned)i;
        }
    }
    __syncthreads();
    const int m = s_cnt;
    int P = 64;
    while (P < m) P <<= 1;

    for (int i = m + tid; i < P; i += 256) key[i] = ~0ull;
    __syncthreads();

    // sort each 64-element segment ascending
    for (int k = 2; k <= 64; k <<= 1) {
        for (int j = k >> 1; j > 0; j >>= 1) {
            for (int i = tid; i < P; i += 256) {
                int l = i ^ j;
                if (l > i) {
                    u64 a = key[i], b = key[l];
                    bool up = ((i & k & 63) == 0);   // k=64 -> always ascending
                    if (up ? (a > b) : (a < b)) { key[i] = b; key[l] = a; }
                }
            }
            __syncthreads();
        }
    }

    // fold halves: keep 64 smallest of each sorted-64 pair, re-sort, repeat
    int len = P;
    while (len > 64) {
        int half = len >> 1;
        u64 v[8];                                    // half <= 2048 -> <=8/thread
        int cnt = 0;
        for (int i = tid; i < half; i += 256) {
            int s = i >> 6, pos2 = i & 63;
            u64 a = key[(s << 7) + pos2];
            u64 b = key[(s << 7) + 127 - pos2];
            v[cnt++] = a < b ? a : b;               // bitonic result per segment
        }
        __syncthreads();
        cnt = 0;
        for (int i = tid; i < half; i += 256) key[i] = v[cnt++];
        __syncthreads();
        for (int j = 32; j > 0; j >>= 1) {          // bitonic cleanup, ascending
            for (int i = tid; i < half; i += 256) {
                int l = i ^ j;
                if (l > i) {
                    u64 a = key[i], b = key[l];
                    if (a > b) { key[i] = b; key[l] = a; }
                }
            }
            __syncthreads();
        }
        len = half;
    }

    if (tid < KN2) {
        u64 kk = key[tid];
        int idx = (int)(kk & 0xffffffffu);
        bool v2 = tid < m;
        g_nbr2[c * KN2 + tid] = v2 ? idx : -1;
        if (tid < KN1) {
            float d2 = __uint_as_float((unsigned)(kk >> 32));
            g_nbr1[c * KN1 + tid] = (v2 && d2 <= R1SQ) ? idx : -1;
        }
    }
}

// ---------------- Y = X @ W1[:64,:]  (per branch) --------------------------
__global__ void __launch_bounds__(256) ymm_kernel(const float* __restrict__ x,
                                                  const float* __restrict__ W1,
                                                  int br) {
    __shared__ float sW[64 * 64];
    __shared__ float sx[4 * 64];
    int tid = threadIdx.x;
    for (int i = tid; i < 4096; i += 256) sW[i] = W1[i];
    int p0 = blockIdx.x * 4;
    sx[tid] = x[(size_t)p0 * 64 + tid];
    __syncthreads();
    int lp = tid >> 6, c = tid & 63;
    float acc = 0.f;
#pragma unroll
    for (int k = 0; k < 64; k++) acc += sx[lp * 64 + k] * sW[k * 64 + c];
    g_Y[br][(size_t)(p0 + lp) * 64 + c] = acc;
}

// ---------------- MLP + max-pool (f32x2 packed) ----------------------------
// smem float layout: W2[4096] | W3[8192] | Wp[192] | b1[64] | b2[64] | b3[128] | out[G*128]
template <int K, int G>
__global__ void __launch_bounds__(128, 1) mlp_kernel(const float* __restrict__ pos,
                                                     const float* __restrict__ W1,
                                                     const float* __restrict__ b1,
                                                     const float* __restrict__ W2,
                                                     const float* __restrict__ b2,
                                                     const float* __restrict__ W3,
                                                     const float* __restrict__ b3,
                                                     float* __restrict__ out,
                                                     int coloff) {
    extern __shared__ float sm[];
    const int tid = threadIdx.x;

    for (int i = tid; i < 4096; i += 128) sm[i] = W2[i];
    for (int i = tid; i < 8192; i += 128) sm[4096 + i] = W3[i];
    if (tid < 128) {
        if (tid < 64) {
            sm[12288 + tid]       = W1[4096 + tid];
            sm[12288 + 64 + tid]  = W1[4096 + 64 + tid];
            sm[12288 + 128 + tid] = W1[4096 + 128 + tid];
            sm[12480 + tid] = b1[tid];
            sm[12544 + tid] = b2[tid];
        }
        sm[12608 + tid] = b3[tid];
    }
    int* souti = (int*)(sm + 12736);
    for (int i = tid; i < G * 128; i += 128) souti[i] = 0;
    __syncthreads();

    const int ci = tid / K;
    const int n  = tid % K;
    const int crow = blockIdx.x * G + ci;
    const int g = crow >> 10;
    const float* Y = g_Y[(K == KN1) ? 0 : 1];
    const int* nbr = (K == KN1) ? g_nbr1 : g_nbr2;

    int j = nbr[crow * K + n];
    const bool valid = (j >= 0);
    if (!valid) j = 0;

    const float* pg = pos + (size_t)g * NPER * 3;
    const float dx = pg[j * 3 + 0] - g_pdst[crow * 3 + 0];
    const float dy = pg[j * 3 + 1] - g_pdst[crow * 3 + 1];
    const float dz = pg[j * 3 + 2] - g_pdst[crow * 3 + 2];
    const float* yrow = Y + (size_t)(g * NPER + j) * 64;

    const u64 dx2 = pk2(dx, dx), dy2 = pk2(dy, dy), dz2 = pk2(dz, dz);

    // layer 1: h1 = relu(Y[j] + dp @ Wp + b1)   (packed pairs)
    float h1[64];
#pragma unroll
    for (int c = 0; c < 64; c += 4) {
        ulonglong2 y2 = *(const ulonglong2*)(yrow + c);
        ulonglong2 w0 = *(const ulonglong2*)(sm + 12288 + c);
        ulonglong2 w1 = *(const ulonglong2*)(sm + 12352 + c);
        ulonglong2 w2 = *(const ulonglong2*)(sm + 12416 + c);
        ulonglong2 bb = *(const ulonglong2*)(sm + 12480 + c);
        u64 t0 = ffma2(dx2, w0.x, y2.x);
        t0 = ffma2(dy2, w1.x, t0);
        t0 = ffma2(dz2, w2.x, t0);
        t0 = fadd2(t0, bb.x);
        u64 t1 = ffma2(dx2, w0.y, y2.y);
        t1 = ffma2(dy2, w1.y, t1);
        t1 = ffma2(dz2, w2.y, t1);
        t1 = fadd2(t1, bb.y);
        float a0, a1, a2, a3;
        upk2(t0, a0, a1); upk2(t1, a2, a3);
        h1[c + 0] = fmaxf(a0, 0.f);
        h1[c + 1] = fmaxf(a1, 0.f);
        h1[c + 2] = fmaxf(a2, 0.f);
        h1[c + 3] = fmaxf(a3, 0.f);
    }

    // layer 2 (packed)
    float h2[64];
#pragma unroll
    for (int c0 = 0; c0 < 64; c0 += 8) {
        u64 a[4];
        {
            ulonglong2 bA = *(const ulonglong2*)(sm + 12544 + c0);
            ulonglong2 bB = *(const ulonglong2*)(sm + 12544 + c0 + 4);
            a[0] = bA.x; a[1] = bA.y; a[2] = bB.x; a[3] = bB.y;
        }
#pragma unroll 16
        for (int k = 0; k < 64; k++) {
            u64 hv = pk2(h1[k], h1[k]);
            ulonglong2 wA = *(const ulonglong2*)(sm + k * 64 + c0);
            ulonglong2 wB = *(const ulonglong2*)(sm + k * 64 + c0 + 4);
            a[0] = ffma2(hv, wA.x, a[0]);
            a[1] = ffma2(hv, wA.y, a[1]);
            a[2] = ffma2(hv, wB.x, a[2]);
            a[3] = ffma2(hv, wB.y, a[3]);
        }
#pragma unroll
        for (int i = 0; i < 4; i++) {
            float lo, hi; upk2(a[i], lo, hi);
            h2[c0 + 2 * i + 0] = fmaxf(lo, 0.f);
            h2[c0 + 2 * i + 1] = fmaxf(hi, 0.f);
        }
    }

    // layer 3 (packed) + warp max-reduce + smem atomicMax merge
#pragma unroll
    for (int c0 = 0; c0 < 128; c0 += 8) {
        u64 a[4];
        {
            ulonglong2 bA = *(const ulonglong2*)(sm + 12608 + c0);
            ulonglong2 bB = *(const ulonglong2*)(sm + 12608 + c0 + 4);
            a[0] = bA.x; a[1] = bA.y; a[2] = bB.x; a[3] = bB.y;
        }
#pragma unroll 16
        for (int k = 0; k < 64; k++) {
            u64 hv = pk2(h2[k], h2[k]);
            ulonglong2 wA = *(const ulonglong2*)(sm + 4096 + k * 128 + c0);
            ulonglong2 wB = *(const ulonglong2*)(sm + 4096 + k * 128 + c0 + 4);
            a[0] = ffma2(hv, wA.x, a[0]);
            a[1] = ffma2(hv, wA.y, a[1]);
            a[2] = ffma2(hv, wB.x, a[2]);
            a[3] = ffma2(hv, wB.y, a[3]);
        }
#pragma unroll
        for (int i = 0; i < 4; i++) {
            float lo, hi; upk2(a[i], lo, hi);
            float v0 = valid ? fmaxf(lo, 0.f) : 0.f;
            float v1 = valid ? fmaxf(hi, 0.f) : 0.f;
#pragma unroll
            for (int o = 16; o; o >>= 1) {
                v0 = fmaxf(v0, __shfl_xor_sync(0xffffffffu, v0, o));
                v1 = fmaxf(v1, __shfl_xor_sync(0xffffffffu, v1, o));
            }
            if ((tid & 31) == 0) {
                atomicMax(&souti[ci * 128 + c0 + 2 * i + 0], __float_as_int(v0));
                atomicMax(&souti[ci * 128 + c0 + 2 * i + 1], __float_as_int(v1));
            }
        }
    }
    __syncthreads();
    for (int i = tid; i < G * 128; i += 128) {
        int lc = i >> 7, ch = i & 127;
        out[(size_t)(blockIdx.x * G + lc) * 256 + coloff + ch] = __int_as_float(souti[i]);
    }
}

// ---------------- launch ----------------
extern "C" void kernel_launch(void* const* d_in, const int* in_sizes, int n_in,
                              void* d_out, int out_size) {
    const float* x   = (const float*)d_in[0];
    const float* pos = (const float*)d_in[1];
    const float* w11 = (const float*)d_in[3];
    const float* b11 = (const float*)d_in[4];
    const float* w12 = (const float*)d_in[5];
    const float* b12 = (const float*)d_in[6];
    const float* w13 = (const float*)d_in[7];
    const float* b13 = (const float*)d_in[8];
    const float* w21 = (const float*)d_in[9];
    const float* b21 = (const float*)d_in[10];
    const float* w22 = (const float*)d_in[11];
    const float* b22 = (const float*)d_in[12];
    const float* w23 = (const float*)d_in[13];
    const float* b23 = (const float*)d_in[14];
    float* out = (float*)d_out;

    const int smem1 = (12736 + 4 * 128) * 4;  // G=4
    const int smem2 = (12736 + 2 * 128) * 4;  // G=2
    cudaFuncSetAttribute((const void*)mlp_kernel<KN1, 4>,
                         cudaFuncAttributeMaxDynamicSharedMemorySize, smem1);
    cudaFuncSetAttribute((const void*)mlp_kernel<KN2, 2>,
                         cudaFuncAttributeMaxDynamicSharedMemorySize, smem2);

    // Order keeps mlp_kernel<64,2> on the ncu capture slot for A/B comparison.
    fps_kernel<<<BGR, 512>>>(pos, out);
    select_kernel<<<BGR * MPER, 256>>>(pos);
    ymm_kernel<<<BGR * NPER / 4, 256>>>(x, w21, 1);
    mlp_kernel<KN2, 2><<<BGR * MPER / 2, 128, smem2>>>(pos, w21, b21, w22, b22, w23, b23, out, 128);
    ymm_kernel<<<BGR * NPER / 4, 256>>>(x, w11, 0);
    mlp_kernel<KN1, 4><<<BGR * MPER / 4, 128, smem1>>>(pos, w11, b11, w12, b12, w13, b13, out, 0);
}

// round 4
// speedup vs baseline: 1.9429x; 1.4160x over previous
#include <cuda_runtime.h>
#include <cuda_bf16.h>
#include <cstdint>

#define BGR 4
#define NPER 4096
#define MPER 1024
#define DIN 64
#define KN1 32
#define KN2 64
#define R1SQ 0.04f
#define R2SQ 0.16f
#define SCAP 4096

#define POFF (BGR*MPER*256)          // 1048576
#define BOFF (POFF + BGR*MPER*3)     // 1060864

typedef unsigned long long u64;

// smem float offsets for mlp kernel
#define OFF_W2   0                   // [64][68]
#define OFF_W3   4352                // [64][132]
#define OFF_H    12800               // [64][132]  transposed activations (h1 then h2)
#define OFF_WP   21248               // [3][64]
#define OFF_B1   21440
#define OFF_B2   21504
#define OFF_B3   21568               // [128]
#define OFF_VALID 21696              // [128] ints
#define OFF_OUT  21824               // [G*128] ints

// ---------------- scratch (device globals; no allocation allowed) ----------
__device__ float g_pdst[BGR*MPER*3];
__device__ int   g_nbr1[BGR*MPER*KN1];
__device__ int   g_nbr2[BGR*MPER*KN2];
__device__ float g_Y[2][BGR*NPER*DIN];

// ---------------- helpers ----------------
__device__ __forceinline__ float d2_exact(float ax, float ay, float az,
                                          float bx, float by, float bz) {
    float dx = __fsub_rn(ax, bx);
    float dy = __fsub_rn(ay, by);
    float dz = __fsub_rn(az, bz);
    return __fadd_rn(__fadd_rn(__fmul_rn(dx, dx), __fmul_rn(dy, dy)), __fmul_rn(dz, dz));
}

__device__ __forceinline__ u64 pk2(float lo, float hi) {
    u64 r; asm("mov.b64 %0,{%1,%2};" : "=l"(r) : "f"(lo), "f"(hi)); return r;
}
__device__ __forceinline__ void upk2(u64 v, float& lo, float& hi) {
    asm("mov.b64 {%0,%1}, %2;" : "=f"(lo), "=f"(hi) : "l"(v));
}
__device__ __forceinline__ u64 ffma2(u64 a, u64 b, u64 c) {
    u64 r; asm("fma.rn.f32x2 %0,%1,%2,%3;" : "=l"(r) : "l"(a), "l"(b), "l"(c)); return r;
}
__device__ __forceinline__ u64 fadd2(u64 a, u64 b) {
    u64 r; asm("add.rn.f32x2 %0,%1,%2;" : "=l"(r) : "l"(a), "l"(b)); return r;
}
__device__ __forceinline__ unsigned redux_max(unsigned v) {
    unsigned r; asm("redux.sync.max.u32 %0, %1, 0xffffffff;" : "=r"(r) : "r"(v)); return r;
}
// warp argmax on key=(distbits<<32)|lowkey, identical semantics to u64-max
__device__ __forceinline__ u64 warp_amax2(u64 key) {
    unsigned d = (unsigned)(key >> 32), lk = (unsigned)key;
    unsigned rd = redux_max(d);
    unsigned cand = (d == rd) ? lk : 0u;
    unsigned ri = redux_max(cand);
    return ((u64)rd << 32) | ri;
}

// ---------------- FPS (+ centroid gather tail): one block per graph --------
__global__ void __launch_bounds__(512) fps_kernel(const float* __restrict__ pos,
                                                  float* __restrict__ out) {
    const int g = blockIdx.x;
    const float* p = pos + (size_t)g * NPER * 3;
    const int t = threadIdx.x;

    __shared__ u64 s_red[16];
    __shared__ u64 s_winkey;
    __shared__ int s_fidx[MPER];

    float px[8], py[8], pz[8], dist[8];
    const float p0x = p[0], p0y = p[1], p0z = p[2];
#pragma unroll
    for (int i = 0; i < 8; i++) {
        int id = t + i * 512;
        float x = p[id * 3 + 0], y = p[id * 3 + 1], z = p[id * 3 + 2];
        px[i] = x; py[i] = y; pz[i] = z;
        dist[i] = d2_exact(x, y, z, p0x, p0y, p0z);
    }
    if (t == 0) s_fidx[0] = 0;

    u64 best = 0;
#pragma unroll
    for (int i = 0; i < 8; i++) {
        int id = t + i * 512;
        u64 k = ((u64)__float_as_uint(dist[i]) << 32) | (unsigned)(NPER - 1 - id);
        if (k > best) best = k;
    }

    for (int s = 1; s < MPER; s++) {
        u64 r = warp_amax2(best);
        if ((t & 31) == 0) s_red[t >> 5] = r;
        __syncthreads();
        if (t < 32) {
            u64 k = (t < 16) ? s_red[t] : 0ull;
            k = warp_amax2(k);
            if (t == 0) s_winkey = k;
        }
        __syncthreads();
        u64 wk = s_winkey;
        int widx = NPER - 1 - (int)(wk & 0xffffffffu);
        if (t == 0) s_fidx[s] = widx;
        float wx = p[widx * 3 + 0], wy = p[widx * 3 + 1], wz = p[widx * 3 + 2];

        best = 0;
#pragma unroll
        for (int i = 0; i < 8; i++) {
            int id = t + i * 512;
            float d = d2_exact(px[i], py[i], pz[i], wx, wy, wz);
            float nd = fminf(dist[i], d);
            dist[i] = nd;
            u64 k = ((u64)__float_as_uint(nd) << 32) | (unsigned)(NPER - 1 - id);
            if (k > best) best = k;
        }
    }
    __syncthreads();

    for (int s = t; s < MPER; s += 512) {
        int li = s_fidx[s];
        int c = g * MPER + s;
        float x = p[li * 3 + 0], y = p[li * 3 + 1], z = p[li * 3 + 2];
        g_pdst[c * 3 + 0] = x; g_pdst[c * 3 + 1] = y; g_pdst[c * 3 + 2] = z;
        out[POFF + c * 3 + 0] = x;
        out[POFF + c * 3 + 1] = y;
        out[POFF + c * 3 + 2] = z;
        out[BOFF + c] = (float)g;
    }
}

// ---------------- ball query + chunked-bitonic top-64 ----------------------
__global__ void __launch_bounds__(256) select_kernel(const float* __restrict__ pos) {
    __shared__ u64 key[SCAP];   // 32 KB
    __shared__ int s_cnt;

    const int c = blockIdx.x;
    const int tid = threadIdx.x;
    const int g = c >> 10;
    const float* p = pos + (size_t)g * NPER * 3;
    const float cx = g_pdst[c * 3 + 0], cy = g_pdst[c * 3 + 1], cz = g_pdst[c * 3 + 2];

    if (tid == 0) s_cnt = 0;
    __syncthreads();

    for (int i = tid; i < NPER; i += 256) {
        float d2 = d2_exact(p[i * 3], p[i * 3 + 1], p[i * 3 + 2], cx, cy, cz);
        if (d2 <= R2SQ) {
            int s = atomicAdd(&s_cnt, 1);
            key[s] = ((u64)__float_as_uint(d2) << 32) | (unsigned)i;
        }
    }
    __syncthreads();
    const int m = s_cnt;
    int P = 64;
    while (P < m) P <<= 1;

    for (int i = m + tid; i < P; i += 256) key[i] = ~0ull;
    __syncthreads();

    // sort each 64-element segment ascending
    for (int k = 2; k <= 64; k <<= 1) {
        for (int j = k >> 1; j > 0; j >>= 1) {
            for (int i = tid; i < P; i += 256) {
                int l = i ^ j;
                if (l > i) {
                    u64 a = key[i], b = key[l];
                    bool up = ((i & k & 63) == 0);
                    if (up ? (a > b) : (a < b)) { key[i] = b; key[l] = a; }
                }
            }
            __syncthreads();
        }
    }

    // fold halves: keep 64 smallest of each sorted-64 pair, re-sort, repeat
    int len = P;
    while (len > 64) {
        int half = len >> 1;
        u64 v[8];
        int cnt = 0;
        for (int i = tid; i < half; i += 256) {
            int s = i >> 6, pos2 = i & 63;
            u64 a = key[(s << 7) + pos2];
            u64 b = key[(s << 7) + 127 - pos2];
            v[cnt++] = a < b ? a : b;
        }
        __syncthreads();
        cnt = 0;
        for (int i = tid; i < half; i += 256) key[i] = v[cnt++];
        __syncthreads();
        for (int j = 32; j > 0; j >>= 1) {
            for (int i = tid; i < half; i += 256) {
                int l = i ^ j;
                if (l > i) {
                    u64 a = key[i], b = key[l];
                    if (a > b) { key[i] = b; key[l] = a; }
                }
            }
            __syncthreads();
        }
        len = half;
    }

    if (tid < KN2) {
        u64 kk = key[tid];
        int idx = (int)(kk & 0xffffffffu);
        bool v2 = tid < m;
        g_nbr2[c * KN2 + tid] = v2 ? idx : -1;
        if (tid < KN1) {
            float d2 = __uint_as_float((unsigned)(kk >> 32));
            g_nbr1[c * KN1 + tid] = (v2 && d2 <= R1SQ) ? idx : -1;
        }
    }
}

// ---------------- Y = X @ W1[:64,:]  (per branch) --------------------------
__global__ void __launch_bounds__(256) ymm_kernel(const float* __restrict__ x,
                                                  const float* __restrict__ W1,
                                                  int br) {
    __shared__ float sW[64 * 64];
    __shared__ float sx[4 * 64];
    int tid = threadIdx.x;
    for (int i = tid; i < 4096; i += 256) sW[i] = W1[i];
    int p0 = blockIdx.x * 4;
    sx[tid] = x[(size_t)p0 * 64 + tid];
    __syncthreads();
    int lp = tid >> 6, c = tid & 63;
    float acc = 0.f;
#pragma unroll
    for (int k = 0; k < 64; k++) acc += sx[lp * 64 + k] * sW[k * 64 + c];
    g_Y[br][(size_t)(p0 + lp) * 64 + c] = acc;
}

// ---------------- MLP + max-pool: register-tiled GEMM ----------------------
// 128 threads, rows = G*K = 128 (neighbor-rows). Warp = 32 rows x 64 cols.
// Thread (w, rg, cg): rows w*32+rg*8..+7; cols {4cg..+3} U {32+4cg..+3}.
// Activations staged transposed in smem: h[k][row], stride 132, row index
// XOR-swizzled by 4*(k>>3) for bank-clean vec4 access.
template <int K, int G>
__global__ void __launch_bounds__(128, 1) mlp_kernel(const float* __restrict__ pos,
                                                     const float* __restrict__ W1,
                                                     const float* __restrict__ b1,
                                                     const float* __restrict__ W2,
                                                     const float* __restrict__ b2,
                                                     const float* __restrict__ W3,
                                                     const float* __restrict__ b3,
                                                     float* __restrict__ out,
                                                     int coloff) {
    extern __shared__ float sm[];
    const int tid = threadIdx.x;
    const int lane = tid & 31, w = tid >> 5;
    const int rg = lane >> 3, cg = lane & 7;
    const int base_r = w * 32 + rg * 8;
    const int colA = 4 * cg, colB = 32 + 4 * cg;

    // ---- stage weights/biases ----
    for (int i = tid; i < 4096; i += 128) sm[OFF_W2 + (i >> 6) * 68 + (i & 63)] = W2[i];
    for (int i = tid; i < 8192; i += 128) sm[OFF_W3 + (i >> 7) * 132 + (i & 127)] = W3[i];
    if (tid < 64) {
        sm[OFF_WP + tid]        = W1[4096 + tid];
        sm[OFF_WP + 64 + tid]   = W1[4096 + 64 + tid];
        sm[OFF_WP + 128 + tid]  = W1[4096 + 128 + tid];
        sm[OFF_B1 + tid] = b1[tid];
        sm[OFF_B2 + tid] = b2[tid];
    }
    sm[OFF_B3 + tid] = b3[tid];
    int* souti = (int*)(sm + OFF_OUT);
    for (int i = tid; i < G * 128; i += 128) souti[i] = 0;
    __syncthreads();

    // ---- phase 1: layer 1 per row (thread = row), write h1 transposed -----
    {
        const int ci = tid / K;
        const int n  = tid % K;
        const int crow = blockIdx.x * G + ci;
        const int g = crow >> 10;
        const float* Y = g_Y[(K == KN1) ? 0 : 1];
        const int* nbr = (K == KN1) ? g_nbr1 : g_nbr2;

        int j = nbr[crow * K + n];
        const bool valid = (j >= 0);
        if (!valid) j = 0;
        ((int*)(sm + OFF_VALID))[tid] = valid ? 1 : 0;

        const float* pg = pos + (size_t)g * NPER * 3;
        const float dx = pg[j * 3 + 0] - g_pdst[crow * 3 + 0];
        const float dy = pg[j * 3 + 1] - g_pdst[crow * 3 + 1];
        const float dz = pg[j * 3 + 2] - g_pdst[crow * 3 + 2];
        const float* yrow = Y + (size_t)(g * NPER + j) * 64;

        const u64 dx2 = pk2(dx, dx), dy2 = pk2(dy, dy), dz2 = pk2(dz, dz);

        float h1[64];
#pragma unroll
        for (int c = 0; c < 64; c += 4) {
            ulonglong2 y2 = *(const ulonglong2*)(yrow + c);
            ulonglong2 w0 = *(const ulonglong2*)(sm + OFF_WP + c);
            ulonglong2 w1 = *(const ulonglong2*)(sm + OFF_WP + 64 + c);
            ulonglong2 w2 = *(const ulonglong2*)(sm + OFF_WP + 128 + c);
            ulonglong2 bb = *(const ulonglong2*)(sm + OFF_B1 + c);
            u64 t0 = ffma2(dx2, w0.x, y2.x);
            t0 = ffma2(dy2, w1.x, t0);
            t0 = ffma2(dz2, w2.x, t0);
            t0 = fadd2(t0, bb.x);
            u64 t1 = ffma2(dx2, w0.y, y2.y);
            t1 = ffma2(dy2, w1.y, t1);
            t1 = ffma2(dz2, w2.y, t1);
            t1 = fadd2(t1, bb.y);
            float a0, a1, a2, a3;
            upk2(t0, a0, a1); upk2(t1, a2, a3);
            h1[c + 0] = fmaxf(a0, 0.f);
            h1[c + 1] = fmaxf(a1, 0.f);
            h1[c + 2] = fmaxf(a2, 0.f);
            h1[c + 3] = fmaxf(a3, 0.f);
        }
#pragma unroll
        for (int c = 0; c < 64; c++)
            sm[OFF_H + c * 132 + (tid ^ (4 * (c >> 3)))] = h1[c];
    }
    __syncthreads();

    // valid flags for this thread's 8 rows
    int vld[8];
#pragma unroll
    for (int r = 0; r < 8; r++) vld[r] = ((int*)(sm + OFF_VALID))[base_r + r];

    // ---- layer 2 GEMM: h2 = relu(h1 @ W2 + b2) ----
    u64 acc[8][4];
    {
        float4 bA = *(const float4*)(sm + OFF_B2 + colA);
        float4 bB = *(const float4*)(sm + OFF_B2 + colB);
        u64 i0 = pk2(bA.x, bA.y), i1 = pk2(bA.z, bA.w);
        u64 i2 = pk2(bB.x, bB.y), i3 = pk2(bB.z, bB.w);
#pragma unroll
        for (int r = 0; r < 8; r++) { acc[r][0] = i0; acc[r][1] = i1; acc[r][2] = i2; acc[r][3] = i3; }
    }
#pragma unroll 4
    for (int k = 0; k < 64; k++) {
        int sw = 4 * (k >> 3);
        const float* hrow = sm + OFF_H + k * 132;
        float4 a0 = *(const float4*)(hrow + (base_r ^ sw));
        float4 a1 = *(const float4*)(hrow + ((base_r + 4) ^ sw));
        ulonglong2 wA = *(const ulonglong2*)(sm + OFF_W2 + k * 68 + colA);
        ulonglong2 wB = *(const ulonglong2*)(sm + OFF_W2 + k * 68 + colB);
        float av[8] = {a0.x, a0.y, a0.z, a0.w, a1.x, a1.y, a1.z, a1.w};
#pragma unroll
        for (int r = 0; r < 8; r++) {
            u64 ar = pk2(av[r], av[r]);
            acc[r][0] = ffma2(ar, wA.x, acc[r][0]);
            acc[r][1] = ffma2(ar, wA.y, acc[r][1]);
            acc[r][2] = ffma2(ar, wB.x, acc[r][2]);
            acc[r][3] = ffma2(ar, wB.y, acc[r][3]);
        }
    }
    __syncthreads();   // all h1 reads done before overwrite
    // relu + store h2 transposed (col-major rows, same swizzle)
#pragma unroll
    for (int p = 0; p < 4; p++) {
        int c0 = (p < 2) ? (colA + 2 * p) : (colB + 2 * (p - 2));
        float va[8], vb[8];
#pragma unroll
        for (int r = 0; r < 8; r++) {
            float x, y; upk2(acc[r][p], x, y);
            va[r] = fmaxf(x, 0.f); vb[r] = fmaxf(y, 0.f);
        }
        int sw = 4 * (c0 >> 3);
        float* d0 = sm + OFF_H + c0 * 132;
        float* d1 = d0 + 132;
        *(float4*)(d0 + (base_r ^ sw))       = make_float4(va[0], va[1], va[2], va[3]);
        *(float4*)(d0 + ((base_r + 4) ^ sw)) = make_float4(va[4], va[5], va[6], va[7]);
        *(float4*)(d1 + (base_r ^ sw))       = make_float4(vb[0], vb[1], vb[2], vb[3]);
        *(float4*)(d1 + ((base_r + 4) ^ sw)) = make_float4(vb[4], vb[5], vb[6], vb[7]);
    }
    __syncthreads();

    // ---- layer 3 GEMM (2 passes of 64 cols) + max-pool ----
    const int ci = (K == KN2) ? (w >> 1) : w;
#pragma unroll
    for (int po = 0; po < 128; po += 64) {
        {
            float4 bA = *(const float4*)(sm + OFF_B3 + po + colA);
            float4 bB = *(const float4*)(sm + OFF_B3 + po + colB);
            u64 i0 = pk2(bA.x, bA.y), i1 = pk2(bA.z, bA.w);
            u64 i2 = pk2(bB.x, bB.y), i3 = pk2(bB.z, bB.w);
#pragma unroll
            for (int r = 0; r < 8; r++) { acc[r][0] = i0; acc[r][1] = i1; acc[r][2] = i2; acc[r][3] = i3; }
        }
#pragma unroll 4
        for (int k = 0; k < 64; k++) {
            int sw = 4 * (k >> 3);
            const float* hrow = sm + OFF_H + k * 132;
            float4 a0 = *(const float4*)(hrow + (base_r ^ sw));
            float4 a1 = *(const float4*)(hrow + ((base_r + 4) ^ sw));
            ulonglong2 wA = *(const ulonglong2*)(sm + OFF_W3 + k * 132 + po + colA);
            ulonglong2 wB = *(const ulonglong2*)(sm + OFF_W3 + k * 132 + po + colB);
            float av[8] = {a0.x, a0.y, a0.z, a0.w, a1.x, a1.y, a1.z, a1.w};
#pragma unroll
            for (int r = 0; r < 8; r++) {
                u64 ar = pk2(av[r], av[r]);
                acc[r][0] = ffma2(ar, wA.x, acc[r][0]);
                acc[r][1] = ffma2(ar, wA.y, acc[r][1]);
                acc[r][2] = ffma2(ar, wB.x, acc[r][2]);
                acc[r][3] = ffma2(ar, wB.y, acc[r][3]);
            }
        }
        // relu + valid mask + local 8-row max + cross-rg shuffle + merge
#pragma unroll
        for (int p = 0; p < 4; p++) {
            int c0 = (p < 2) ? (colA + 2 * p) : (colB + 2 * (p - 2));
            float m0 = 0.f, m1 = 0.f;
#pragma unroll
            for (int r = 0; r < 8; r++) {
                float x, y; upk2(acc[r][p], x, y);
                float fx = vld[r] ? fmaxf(x, 0.f) : 0.f;
                float fy = vld[r] ? fmaxf(y, 0.f) : 0.f;
                m0 = fmaxf(m0, fx); m1 = fmaxf(m1, fy);
            }
            m0 = fmaxf(m0, __shfl_xor_sync(0xffffffffu, m0, 8));
            m0 = fmaxf(m0, __shfl_xor_sync(0xffffffffu, m0, 16));
            m1 = fmaxf(m1, __shfl_xor_sync(0xffffffffu, m1, 8));
            m1 = fmaxf(m1, __shfl_xor_sync(0xffffffffu, m1, 16));
            if (lane < 8) {
                atomicMax(&souti[ci * 128 + po + c0],     __float_as_int(m0));
                atomicMax(&souti[ci * 128 + po + c0 + 1], __float_as_int(m1));
            }
        }
    }
    __syncthreads();
    for (int i = tid; i < G * 128; i += 128) {
        int lc = i >> 7, ch = i & 127;
        out[(size_t)(blockIdx.x * G + lc) * 256 + coloff + ch] = __int_as_float(souti[i]);
    }
}

// ---------------- launch ----------------
extern "C" void kernel_launch(void* const* d_in, const int* in_sizes, int n_in,
                              void* d_out, int out_size) {
    const float* x   = (const float*)d_in[0];
    const float* pos = (const float*)d_in[1];
    const float* w11 = (const float*)d_in[3];
    const float* b11 = (const float*)d_in[4];
    const float* w12 = (const float*)d_in[5];
    const float* b12 = (const float*)d_in[6];
    const float* w13 = (const float*)d_in[7];
    const float* b13 = (const float*)d_in[8];
    const float* w21 = (const float*)d_in[9];
    const float* b21 = (const float*)d_in[10];
    const float* w22 = (const float*)d_in[11];
    const float* b22 = (const float*)d_in[12];
    const float* w23 = (const float*)d_in[13];
    const float* b23 = (const float*)d_in[14];
    float* out = (float*)d_out;

    const int smem1 = (OFF_OUT + 4 * 128) * 4;  // G=4
    const int smem2 = (OFF_OUT + 2 * 128) * 4;  // G=2
    cudaFuncSetAttribute((const void*)mlp_kernel<KN1, 4>,
                         cudaFuncAttributeMaxDynamicSharedMemorySize, smem1);
    cudaFuncSetAttribute((const void*)mlp_kernel<KN2, 2>,
                         cudaFuncAttributeMaxDynamicSharedMemorySize, smem2);

    // Order keeps mlp_kernel<64,2> on the ncu capture slot for A/B comparison.
    fps_kernel<<<BGR, 512>>>(pos, out);
    select_kernel<<<BGR * MPER, 256>>>(pos);
    ymm_kernel<<<BGR * NPER / 4, 256>>>(x, w21, 1);
    mlp_kernel<KN2, 2><<<BGR * MPER / 2, 128, smem2>>>(pos, w21, b21, w22, b22, w23, b23, out, 128);
    ymm_kernel<<<BGR * NPER / 4, 256>>>(x, w11, 0);
    mlp_kernel<KN1, 4><<<BGR * MPER / 4, 128, smem1>>>(pos, w11, b11, w12, b12, w13, b13, out, 0);
}

// round 5
// speedup vs baseline: 2.3235x; 1.1959x over previous
#include <cuda_runtime.h>
#include <cuda_bf16.h>
#include <cstdint>

#define BGR 4
#define NPER 4096
#define MPER 1024
#define DIN 64
#define KN1 32
#define KN2 64
#define R1SQ 0.04f
#define R2SQ 0.16f

#define POFF (BGR*MPER*256)          // 1048576
#define BOFF (POFF + BGR*MPER*3)     // 1060864

typedef unsigned long long u64;

// smem float offsets for mlp kernel
#define OFF_W2   0                   // [64][68]
#define OFF_W3   4352                // [64][132]
#define OFF_H    12800               // [64][132]
#define OFF_WP   21248               // [3][64]
#define OFF_B1   21440
#define OFF_B2   21504
#define OFF_B3   21568               // [128]
#define OFF_VALID 21696              // [128] ints
#define OFF_OUT  21824               // [G*128] ints

// ---------------- scratch (device globals; no allocation allowed) ----------
__device__ float g_pdst[BGR*MPER*3];
__device__ int   g_nbr1[BGR*MPER*KN1];
__device__ int   g_nbr2[BGR*MPER*KN2];
__device__ float g_Y[2][BGR*NPER*DIN];

// ---------------- helpers ----------------
__device__ __forceinline__ float d2_exact(float ax, float ay, float az,
                                          float bx, float by, float bz) {
    float dx = __fsub_rn(ax, bx);
    float dy = __fsub_rn(ay, by);
    float dz = __fsub_rn(az, bz);
    return __fadd_rn(__fadd_rn(__fmul_rn(dx, dx), __fmul_rn(dy, dy)), __fmul_rn(dz, dz));
}

__device__ __forceinline__ u64 pk2(float lo, float hi) {
    u64 r; asm("mov.b64 %0,{%1,%2};" : "=l"(r) : "f"(lo), "f"(hi)); return r;
}
__device__ __forceinline__ void upk2(u64 v, float& lo, float& hi) {
    asm("mov.b64 {%0,%1}, %2;" : "=f"(lo), "=f"(hi) : "l"(v));
}
__device__ __forceinline__ u64 ffma2(u64 a, u64 b, u64 c) {
    u64 r; asm("fma.rn.f32x2 %0,%1,%2,%3;" : "=l"(r) : "l"(a), "l"(b), "l"(c)); return r;
}
__device__ __forceinline__ u64 fadd2(u64 a, u64 b) {
    u64 r; asm("add.rn.f32x2 %0,%1,%2;" : "=l"(r) : "l"(a), "l"(b)); return r;
}
__device__ __forceinline__ u64 fmul2(u64 a, u64 b) {
    u64 r; asm("mul.rn.f32x2 %0,%1,%2;" : "=l"(r) : "l"(a), "l"(b)); return r;
}
// key = (floatbits(d) << 32) | lo   -- free register-pair build
__device__ __forceinline__ u64 mku64(unsigned lo, float d) {
    u64 r; asm("mov.b64 %0,{%1,%2};" : "=l"(r) : "r"(lo), "f"(d)); return r;
}
__device__ __forceinline__ unsigned redux_max(unsigned v) {
    unsigned r; asm("redux.sync.max.u32 %0, %1, 0xffffffff;" : "=r"(r) : "r"(v)); return r;
}
// warp argmax on key=(distbits<<32)|lowkey; ties -> max lowkey (= smallest id)
__device__ __forceinline__ u64 warp_amax2(u64 key) {
    unsigned d = (unsigned)(key >> 32), lk = (unsigned)key;
    unsigned rd = redux_max(d);
    unsigned cand = (d == rd) ? lk : 0u;
    unsigned ri = redux_max(cand);
    return ((u64)rd << 32) | ri;
}

// ---------------- FPS (+ centroid gather tail): one block per graph --------
// dynamic smem: pos[12288] floats | fidx[1024] ints | red[2][16] u64
#define FPS_OFF_FIDX 12288
#define FPS_OFF_RED  13312
#define FPS_SMEM     ((13312 + 2*16*2 + 4) * 4)
__global__ void __launch_bounds__(512) fps_kernel(const float* __restrict__ pos,
                                                  float* __restrict__ out) {
    extern __shared__ float fsm[];
    int* s_fidx = (int*)(fsm + FPS_OFF_FIDX);
    u64* s_red  = (u64*)(fsm + FPS_OFF_RED);

    const int g = blockIdx.x;
    const float* p = pos + (size_t)g * NPER * 3;
    const int t = threadIdx.x;
    const int lane = t & 31, wid = t >> 5;

    u64 px2[4], py2[4], pz2[4];
    float dist[8];
    unsigned lk[8];
    const float p0x = p[0], p0y = p[1], p0z = p[2];
    const u64 nw0x = pk2(-p0x, -p0x), nw0y = pk2(-p0y, -p0y), nw0z = pk2(-p0z, -p0z);
#pragma unroll
    for (int i = 0; i < 4; i++) {
        int id0 = t + (2 * i) * 512, id1 = t + (2 * i + 1) * 512;
        float x0 = p[id0 * 3 + 0], y0 = p[id0 * 3 + 1], z0 = p[id0 * 3 + 2];
        float x1 = p[id1 * 3 + 0], y1 = p[id1 * 3 + 1], z1 = p[id1 * 3 + 2];
        fsm[id0 * 3 + 0] = x0; fsm[id0 * 3 + 1] = y0; fsm[id0 * 3 + 2] = z0;
        fsm[id1 * 3 + 0] = x1; fsm[id1 * 3 + 1] = y1; fsm[id1 * 3 + 2] = z1;
        px2[i] = pk2(x0, x1); py2[i] = pk2(y0, y1); pz2[i] = pk2(z0, z1);
        lk[2 * i] = (unsigned)(NPER - 1 - id0);
        lk[2 * i + 1] = (unsigned)(NPER - 1 - id1);
        u64 dx = fadd2(px2[i], nw0x), dy = fadd2(py2[i], nw0y), dz = fadd2(pz2[i], nw0z);
        u64 ss = fadd2(fadd2(fmul2(dx, dx), fmul2(dy, dy)), fmul2(dz, dz));
        float s0, s1; upk2(ss, s0, s1);
        dist[2 * i] = s0; dist[2 * i + 1] = s1;
    }
    if (t == 0) s_fidx[0] = 0;

    u64 best = 0;
#pragma unroll
    for (int i = 0; i < 8; i++) {
        u64 k = mku64(lk[i], dist[i]);
        if (k > best) best = k;
    }

    for (int s = 1; s < MPER; s++) {
        u64 r = warp_amax2(best);
        u64* buf = s_red + (s & 1) * 16;
        if (lane == 0) buf[wid] = r;
        __syncthreads();
        u64 k = (lane < 16) ? buf[lane] : 0ull;
        k = warp_amax2(k);
        int widx = NPER - 1 - (int)(k & 0xffffffffu);
        if (t == 0) s_fidx[s] = widx;
        float wx = fsm[widx * 3 + 0], wy = fsm[widx * 3 + 1], wz = fsm[widx * 3 + 2];
        u64 nwx = pk2(-wx, -wx), nwy = pk2(-wy, -wy), nwz = pk2(-wz, -wz);
        best = 0;
#pragma unroll
        for (int i = 0; i < 4; i++) {
            u64 dx = fadd2(px2[i], nwx), dy = fadd2(py2[i], nwy), dz = fadd2(pz2[i], nwz);
            u64 ss = fadd2(fadd2(fmul2(dx, dx), fmul2(dy, dy)), fmul2(dz, dz));
            float s0, s1; upk2(ss, s0, s1);
            float n0 = fminf(dist[2 * i], s0), n1 = fminf(dist[2 * i + 1], s1);
            dist[2 * i] = n0; dist[2 * i + 1] = n1;
            u64 k0 = mku64(lk[2 * i], n0); if (k0 > best) best = k0;
            u64 k1 = mku64(lk[2 * i + 1], n1); if (k1 > best) best = k1;
        }
    }
    __syncthreads();

    for (int s = t; s < MPER; s += 512) {
        int li = s_fidx[s];
        int c = g * MPER + s;
        float x = fsm[li * 3 + 0], y = fsm[li * 3 + 1], z = fsm[li * 3 + 2];
        g_pdst[c * 3 + 0] = x; g_pdst[c * 3 + 1] = y; g_pdst[c * 3 + 2] = z;
        out[POFF + c * 3 + 0] = x;
        out[POFF + c * 3 + 1] = y;
        out[POFF + c * 3 + 2] = z;
        out[BOFF + c] = (float)g;
    }
}

// ---------------- ball query + radix-bucket top-64 -------------------------
#define HISTN 512
#define SELCAP 1024
__global__ void __launch_bounds__(256) select_kernel(const float* __restrict__ pos) {
    __shared__ u64 key[NPER];        // 32 KB (cannot overflow)
    __shared__ int hist[HISTN];      // 2 KB
    __shared__ u64 selbuf[SELCAP];   // 8 KB
    __shared__ unsigned s_wsum[8];
    __shared__ int s_cnt, s_bstar, s_base, s_sel;

    const int c = blockIdx.x;
    const int tid = threadIdx.x;
    const int lane = tid & 31, w = tid >> 5;
    const int g = c >> 10;
    const float* p = pos + (size_t)g * NPER * 3;
    const float cx = g_pdst[c * 3 + 0], cy = g_pdst[c * 3 + 1], cz = g_pdst[c * 3 + 2];

    if (tid == 0) { s_cnt = 0; s_bstar = 0x7fffffff; s_sel = 0; }
    for (int i = tid; i < HISTN; i += 256) hist[i] = 0;
    __syncthreads();

    // pass 1: candidates -> compact keys + bucket histogram (warp-aggregated)
    for (int i = tid; i < NPER; i += 256) {
        float d2 = d2_exact(p[i * 3], p[i * 3 + 1], p[i * 3 + 2], cx, cy, cz);
        if (d2 <= R2SQ) {
            unsigned bits = __float_as_uint(d2);
            int b = (int)(bits >> 21);               // < 512 for d2 <= 0.16
            unsigned am = __activemask();
            // aggregated compaction
            int rank = __popc(am & ((1u << lane) - 1));
            int ldr = __ffs(am) - 1;
            int base;
            if (lane == ldr) base = atomicAdd(&s_cnt, __popc(am));
            base = __shfl_sync(am, base, ldr);
            key[base + rank] = ((u64)bits << 32) | (unsigned)i;
            // aggregated histogram
            unsigned mm = __match_any_sync(am, b);
            if (lane == (__ffs(mm) - 1)) atomicAdd(&hist[b], __popc(mm));
        }
    }
    __syncthreads();
    const int m = s_cnt;
    const int need = (m < 64) ? m : 64;

    // prefix scan over hist (2 buckets / thread), find boundary bucket b*
    {
        int h0 = hist[2 * tid], h1 = hist[2 * tid + 1];
        unsigned l = (unsigned)(h0 + h1);
        unsigned v = l;
#pragma unroll
        for (int o = 1; o < 32; o <<= 1) {
            unsigned n = __shfl_up_sync(0xffffffffu, v, o);
            if (lane >= o) v += n;
        }
        if (lane == 31) s_wsum[w] = v;
        __syncthreads();
        unsigned woff = 0;
#pragma unroll
        for (int q = 0; q < 8; q++) woff += (q < w) ? s_wsum[q] : 0;
        unsigned ex = woff + v - l;                  // exclusive prefix
        int cum0 = (int)ex + h0;
        int cum1 = cum0 + h1;
        int cand = 0x7fffffff;
        if (cum0 >= need) cand = 2 * tid;
        else if (cum1 >= need) cand = 2 * tid + 1;
        if (cand != 0x7fffffff) atomicMin(&s_bstar, cand);
        __syncthreads();
        int bs = s_bstar;
        if (bs == 2 * tid) s_base = (int)ex;
        else if (bs == 2 * tid + 1) s_base = cum0;
        __syncthreads();
    }
    const int bstar = s_bstar;

    // pass 2: collect keys with bucket <= b*
    for (int i = tid; i < m; i += 256) {
        u64 kk = key[i];
        int b = (int)((unsigned)(kk >> 32) >> 21);
        if (b <= bstar) {
            int s = atomicAdd(&s_sel, 1);
            if (s < SELCAP) selbuf[s] = kk;
        }
    }
    __syncthreads();
    int S = s_sel; if (S > SELCAP) S = SELCAP;
    int P2 = 64; while (P2 < S) P2 <<= 1;
    for (int i = S + tid; i < P2; i += 256) selbuf[i] = ~0ull;
    __syncthreads();

    // bitonic sort ascending over selbuf[0..P2)
    for (int k2 = 2; k2 <= P2; k2 <<= 1) {
        for (int j = k2 >> 1; j > 0; j >>= 1) {
            for (int i = tid; i < P2; i += 256) {
                int l = i ^ j;
                if (l > i) {
                    u64 a = selbuf[i], b = selbuf[l];
                    bool up = ((i & k2) == 0);
                    if (up ? (a > b) : (a < b)) { selbuf[i] = b; selbuf[l] = a; }
                }
            }
            __syncthreads();
        }
    }

    if (tid < KN2) {
        u64 kk = selbuf[tid];
        int idx = (int)(kk & 0xffffffffu);
        bool v2 = tid < m;
        g_nbr2[c * KN2 + tid] = v2 ? idx : -1;
        if (tid < KN1) {
            float d2 = __uint_as_float((unsigned)(kk >> 32));
            g_nbr1[c * KN1 + tid] = (v2 && d2 <= R1SQ) ? idx : -1;
        }
    }
}

// ---------------- Y = X @ W1[:64,:]  (per branch) --------------------------
__global__ void __launch_bounds__(256) ymm_kernel(const float* __restrict__ x,
                                                  const float* __restrict__ W1,
                                                  int br) {
    __shared__ float sW[64 * 64];
    __shared__ float sx[4 * 64];
    int tid = threadIdx.x;
    for (int i = tid; i < 4096; i += 256) sW[i] = W1[i];
    int p0 = blockIdx.x * 4;
    sx[tid] = x[(size_t)p0 * 64 + tid];
    __syncthreads();
    int lp = tid >> 6, c = tid & 63;
    float acc = 0.f;
#pragma unroll
    for (int k = 0; k < 64; k++) acc += sx[lp * 64 + k] * sW[k * 64 + c];
    g_Y[br][(size_t)(p0 + lp) * 64 + c] = acc;
}

// ---------------- MLP + max-pool: register-tiled GEMM ----------------------
template <int K, int G>
__global__ void __launch_bounds__(128, 1) mlp_kernel(const float* __restrict__ pos,
                                                     const float* __restrict__ W1,
                                                     const float* __restrict__ b1,
                                                     const float* __restrict__ W2,
                                                     const float* __restrict__ b2,
                                                     const float* __restrict__ W3,
                                                     const float* __restrict__ b3,
                                                     float* __restrict__ out,
                                                     int coloff) {
    extern __shared__ float sm[];
    const int tid = threadIdx.x;
    const int lane = tid & 31, w = tid >> 5;
    const int rg = lane >> 3, cg = lane & 7;
    const int base_r = w * 32 + rg * 8;
    const int colA = 4 * cg, colB = 32 + 4 * cg;

    for (int i = tid; i < 4096; i += 128) sm[OFF_W2 + (i >> 6) * 68 + (i & 63)] = W2[i];
    for (int i = tid; i < 8192; i += 128) sm[OFF_W3 + (i >> 7) * 132 + (i & 127)] = W3[i];
    if (tid < 64) {
        sm[OFF_WP + tid]        = W1[4096 + tid];
        sm[OFF_WP + 64 + tid]   = W1[4096 + 64 + tid];
        sm[OFF_WP + 128 + tid]  = W1[4096 + 128 + tid];
        sm[OFF_B1 + tid] = b1[tid];
        sm[OFF_B2 + tid] = b2[tid];
    }
    sm[OFF_B3 + tid] = b3[tid];
    int* souti = (int*)(sm + OFF_OUT);
    for (int i = tid; i < G * 128; i += 128) souti[i] = 0;
    __syncthreads();

    {
        const int ci = tid / K;
        const int n  = tid % K;
        const int crow = blockIdx.x * G + ci;
        const int g = crow >> 10;
        const float* Y = g_Y[(K == KN1) ? 0 : 1];
        const int* nbr = (K == KN1) ? g_nbr1 : g_nbr2;

        int j = nbr[crow * K + n];
        const bool valid = (j >= 0);
        if (!valid) j = 0;
        ((int*)(sm + OFF_VALID))[tid] = valid ? 1 : 0;

        const float* pg = pos + (size_t)g * NPER * 3;
        const float dx = pg[j * 3 + 0] - g_pdst[crow * 3 + 0];
        const float dy = pg[j * 3 + 1] - g_pdst[crow * 3 + 1];
        const float dz = pg[j * 3 + 2] - g_pdst[crow * 3 + 2];
        const float* yrow = Y + (size_t)(g * NPER + j) * 64;

        const u64 dx2 = pk2(dx, dx), dy2 = pk2(dy, dy), dz2 = pk2(dz, dz);

        float h1[64];
#pragma unroll
        for (int c = 0; c < 64; c += 4) {
            ulonglong2 y2 = *(const ulonglong2*)(yrow + c);
            ulonglong2 w0 = *(const ulonglong2*)(sm + OFF_WP + c);
            ulonglong2 w1 = *(const ulonglong2*)(sm + OFF_WP + 64 + c);
            ulonglong2 w2 = *(const ulonglong2*)(sm + OFF_WP + 128 + c);
            ulonglong2 bb = *(const ulonglong2*)(sm + OFF_B1 + c);
            u64 t0 = ffma2(dx2, w0.x, y2.x);
            t0 = ffma2(dy2, w1.x, t0);
            t0 = ffma2(dz2, w2.x, t0);
            t0 = fadd2(t0, bb.x);
            u64 t1 = ffma2(dx2, w0.y, y2.y);
            t1 = ffma2(dy2, w1.y, t1);
            t1 = ffma2(dz2, w2.y, t1);
            t1 = fadd2(t1, bb.y);
            float a0, a1, a2, a3;
            upk2(t0, a0, a1); upk2(t1, a2, a3);
            h1[c + 0] = fmaxf(a0, 0.f);
            h1[c + 1] = fmaxf(a1, 0.f);
            h1[c + 2] = fmaxf(a2, 0.f);
            h1[c + 3] = fmaxf(a3, 0.f);
        }
#pragma unroll
        for (int c = 0; c < 64; c++)
            sm[OFF_H + c * 132 + (tid ^ (4 * (c >> 3)))] = h1[c];
    }
    __syncthreads();

    int vld[8];
#pragma unroll
    for (int r = 0; r < 8; r++) vld[r] = ((int*)(sm + OFF_VALID))[base_r + r];

    u64 acc[8][4];
    {
        float4 bA = *(const float4*)(sm + OFF_B2 + colA);
        float4 bB = *(const float4*)(sm + OFF_B2 + colB);
        u64 i0 = pk2(bA.x, bA.y), i1 = pk2(bA.z, bA.w);
        u64 i2 = pk2(bB.x, bB.y), i3 = pk2(bB.z, bB.w);
#pragma unroll
        for (int r = 0; r < 8; r++) { acc[r][0] = i0; acc[r][1] = i1; acc[r][2] = i2; acc[r][3] = i3; }
    }
#pragma unroll 4
    for (int k = 0; k < 64; k++) {
        int sw = 4 * (k >> 3);
        const float* hrow = sm + OFF_H + k * 132;
        float4 a0 = *(const float4*)(hrow + (base_r ^ sw));
        float4 a1 = *(const float4*)(hrow + ((base_r + 4) ^ sw));
        ulonglong2 wA = *(const ulonglong2*)(sm + OFF_W2 + k * 68 + colA);
        ulonglong2 wB = *(const ulonglong2*)(sm + OFF_W2 + k * 68 + colB);
        float av[8] = {a0.x, a0.y, a0.z, a0.w, a1.x, a1.y, a1.z, a1.w};
#pragma unroll
        for (int r = 0; r < 8; r++) {
            u64 ar = pk2(av[r], av[r]);
            acc[r][0] = ffma2(ar, wA.x, acc[r][0]);
            acc[r][1] = ffma2(ar, wA.y, acc[r][1]);
            acc[r][2] = ffma2(ar, wB.x, acc[r][2]);
            acc[r][3] = ffma2(ar, wB.y, acc[r][3]);
        }
    }
    __syncthreads();
#pragma unroll
    for (int p = 0; p < 4; p++) {
        int c0 = (p < 2) ? (colA + 2 * p) : (colB + 2 * (p - 2));
        float va[8], vb[8];
#pragma unroll
        for (int r = 0; r < 8; r++) {
            float x, y; upk2(acc[r][p], x, y);
            va[r] = fmaxf(x, 0.f); vb[r] = fmaxf(y, 0.f);
        }
        int sw = 4 * (c0 >> 3);
        float* d0 = sm + OFF_H + c0 * 132;
        float* d1 = d0 + 132;
        *(float4*)(d0 + (base_r ^ sw))       = make_float4(va[0], va[1], va[2], va[3]);
        *(float4*)(d0 + ((base_r + 4) ^ sw)) = make_float4(va[4], va[5], va[6], va[7]);
        *(float4*)(d1 + (base_r ^ sw))       = make_float4(vb[0], vb[1], vb[2], vb[3]);
        *(float4*)(d1 + ((base_r + 4) ^ sw)) = make_float4(vb[4], vb[5], vb[6], vb[7]);
    }
    __syncthreads();

    const int ci = (K == KN2) ? (w >> 1) : w;
#pragma unroll
    for (int po = 0; po < 128; po += 64) {
        {
            float4 bA = *(const float4*)(sm + OFF_B3 + po + colA);
            float4 bB = *(const float4*)(sm + OFF_B3 + po + colB);
            u64 i0 = pk2(bA.x, bA.y), i1 = pk2(bA.z, bA.w);
            u64 i2 = pk2(bB.x, bB.y), i3 = pk2(bB.z, bB.w);
#pragma unroll
            for (int r = 0; r < 8; r++) { acc[r][0] = i0; acc[r][1] = i1; acc[r][2] = i2; acc[r][3] = i3; }
        }
#pragma unroll 4
        for (int k = 0; k < 64; k++) {
            int sw = 4 * (k >> 3);
            const float* hrow = sm + OFF_H + k * 132;
            float4 a0 = *(const float4*)(hrow + (base_r ^ sw));
            float4 a1 = *(const float4*)(hrow + ((base_r + 4) ^ sw));
            ulonglong2 wA = *(const ulonglong2*)(sm + OFF_W3 + k * 132 + po + colA);
            ulonglong2 wB = *(const ulonglong2*)(sm + OFF_W3 + k * 132 + po + colB);
            float av[8] = {a0.x, a0.y, a0.z, a0.w, a1.x, a1.y, a1.z, a1.w};
#pragma unroll
            for (int r = 0; r < 8; r++) {
                u64 ar = pk2(av[r], av[r]);
                acc[r][0] = ffma2(ar, wA.x, acc[r][0]);
                acc[r][1] = ffma2(ar, wA.y, acc[r][1]);
                acc[r][2] = ffma2(ar, wB.x, acc[r][2]);
                acc[r][3] = ffma2(ar, wB.y, acc[r][3]);
            }
        }
#pragma unroll
        for (int p = 0; p < 4; p++) {
            int c0 = (p < 2) ? (colA + 2 * p) : (colB + 2 * (p - 2));
            float m0 = 0.f, m1 = 0.f;
#pragma unroll
            for (int r = 0; r < 8; r++) {
                float x, y; upk2(acc[r][p], x, y);
                float fx = vld[r] ? fmaxf(x, 0.f) : 0.f;
                float fy = vld[r] ? fmaxf(y, 0.f) : 0.f;
                m0 = fmaxf(m0, fx); m1 = fmaxf(m1, fy);
            }
            m0 = fmaxf(m0, __shfl_xor_sync(0xffffffffu, m0, 8));
            m0 = fmaxf(m0, __shfl_xor_sync(0xffffffffu, m0, 16));
            m1 = fmaxf(m1, __shfl_xor_sync(0xffffffffu, m1, 8));
            m1 = fmaxf(m1, __shfl_xor_sync(0xffffffffu, m1, 16));
            if (lane < 8) {
                atomicMax(&souti[ci * 128 + po + c0],     __float_as_int(m0));
                atomicMax(&souti[ci * 128 + po + c0 + 1], __float_as_int(m1));
            }
        }
    }
    __syncthreads();
    for (int i = tid; i < G * 128; i += 128) {
        int lc = i >> 7, ch = i & 127;
        out[(size_t)(blockIdx.x * G + lc) * 256 + coloff + ch] = __int_as_float(souti[i]);
    }
}

// ---------------- launch ----------------
extern "C" void kernel_launch(void* const* d_in, const int* in_sizes, int n_in,
                              void* d_out, int out_size) {
    const float* x   = (const float*)d_in[0];
    const float* pos = (const float*)d_in[1];
    const float* w11 = (const float*)d_in[3];
    const float* b11 = (const float*)d_in[4];
    const float* w12 = (const float*)d_in[5];
    const float* b12 = (const float*)d_in[6];
    const float* w13 = (const float*)d_in[7];
    const float* b13 = (const float*)d_in[8];
    const float* w21 = (const float*)d_in[9];
    const float* b21 = (const float*)d_in[10];
    const float* w22 = (const float*)d_in[11];
    const float* b22 = (const float*)d_in[12];
    const float* w23 = (const float*)d_in[13];
    const float* b23 = (const float*)d_in[14];
    float* out = (float*)d_out;

    const int smem1 = (OFF_OUT + 4 * 128) * 4;  // G=4
    const int smem2 = (OFF_OUT + 2 * 128) * 4;  // G=2
    cudaFuncSetAttribute((const void*)mlp_kernel<KN1, 4>,
                         cudaFuncAttributeMaxDynamicSharedMemorySize, smem1);
    cudaFuncSetAttribute((const void*)mlp_kernel<KN2, 2>,
                         cudaFuncAttributeMaxDynamicSharedMemorySize, smem2);
    cudaFuncSetAttribute((const void*)fps_kernel,
                         cudaFuncAttributeMaxDynamicSharedMemorySize, FPS_SMEM);

    // Order puts select_kernel (new) on the ncu capture slot (4th launch).
    ymm_kernel<<<BGR * NPER / 4, 256>>>(x, w21, 1);
    ymm_kernel<<<BGR * NPER / 4, 256>>>(x, w11, 0);
    fps_kernel<<<BGR, 512, FPS_SMEM>>>(pos, out);
    select_kernel<<<BGR * MPER, 256>>>(pos);
    mlp_kernel<KN2, 2><<<BGR * MPER / 2, 128, smem2>>>(pos, w21, b21, w22, b22, w23, b23, out, 128);
    mlp_kernel<KN1, 4><<<BGR * MPER / 4, 128, smem1>>>(pos, w11, b11, w12, b12, w13, b13, out, 0);
}

// round 7
// speedup vs baseline: 2.3544x; 1.0133x over previous
#include <cuda_runtime.h>
#include <cuda_bf16.h>
#include <cstdint>

#define BGR 4
#define NPER 4096
#define MPER 1024
#define DIN 64
#define KN1 32
#define KN2 64
#define R1SQ 0.04f
#define R2SQ 0.16f

#define POFF (BGR*MPER*256)          // 1048576
#define BOFF (POFF + BGR*MPER*3)     // 1060864

typedef unsigned long long u64;

// smem float offsets for mlp kernel
#define OFF_W2   0                   // [64][68]
#define OFF_W3   4352                // [64][132]
#define OFF_H    12800               // [64][132]
#define OFF_WP   21248               // [3][64]
#define OFF_B1   21440
#define OFF_B2   21504
#define OFF_B3   21568               // [128]
#define OFF_VALID 21696              // [128] ints
#define OFF_OUT  21824               // [up to 512] ints

// ---------------- scratch (device globals; no allocation allowed) ----------
__device__ float g_pdst[BGR*MPER*3];
__device__ int   g_nbr1[BGR*MPER*KN1];
__device__ int   g_nbr2[BGR*MPER*KN2];
__device__ float g_Y[2][BGR*NPER*DIN];

// ---------------- helpers ----------------
__device__ __forceinline__ float d2_exact(float ax, float ay, float az,
                                          float bx, float by, float bz) {
    float dx = __fsub_rn(ax, bx);
    float dy = __fsub_rn(ay, by);
    float dz = __fsub_rn(az, bz);
    return __fadd_rn(__fadd_rn(__fmul_rn(dx, dx), __fmul_rn(dy, dy)), __fmul_rn(dz, dz));
}

__device__ __forceinline__ u64 pk2(float lo, float hi) {
    u64 r; asm("mov.b64 %0,{%1,%2};" : "=l"(r) : "f"(lo), "f"(hi)); return r;
}
__device__ __forceinline__ void upk2(u64 v, float& lo, float& hi) {
    asm("mov.b64 {%0,%1}, %2;" : "=f"(lo), "=f"(hi) : "l"(v));
}
__device__ __forceinline__ u64 ffma2(u64 a, u64 b, u64 c) {
    u64 r; asm("fma.rn.f32x2 %0,%1,%2,%3;" : "=l"(r) : "l"(a), "l"(b), "l"(c)); return r;
}
__device__ __forceinline__ u64 fadd2(u64 a, u64 b) {
    u64 r; asm("add.rn.f32x2 %0,%1,%2;" : "=l"(r) : "l"(a), "l"(b)); return r;
}
__device__ __forceinline__ u64 fmul2(u64 a, u64 b) {
    u64 r; asm("mul.rn.f32x2 %0,%1,%2;" : "=l"(r) : "l"(a), "l"(b)); return r;
}
__device__ __forceinline__ unsigned redux_max(unsigned v) {
    unsigned r; asm("redux.sync.max.u32 %0, %1, 0xffffffff;" : "=r"(r) : "r"(v)); return r;
}
__device__ __forceinline__ unsigned redux_min(unsigned v) {
    unsigned r; asm("redux.sync.min.u32 %0, %1, 0xffffffff;" : "=r"(r) : "r"(v)); return r;
}

// ---------------- FPS (+ centroid gather tail): one block per graph --------
// dynamic smem: pos[12288] floats | fidx[1024] ints | best[2],idx[2] unsigned
#define FPS_OFF_FIDX 12288
#define FPS_OFF_RED  13312
#define FPS_SMEM     ((13312 + 8) * 4)
__global__ void __launch_bounds__(512) fps_kernel(const float* __restrict__ pos,
                                                  float* __restrict__ out) {
    extern __shared__ float fsm[];
    int* s_fidx = (int*)(fsm + FPS_OFF_FIDX);
    unsigned* s_best = (unsigned*)(fsm + FPS_OFF_RED);   // [2]
    unsigned* s_idx  = s_best + 2;                       // [2]

    const int g = blockIdx.x;
    const float* p = pos + (size_t)g * NPER * 3;
    const int t = threadIdx.x;

    u64 px2[4], py2[4], pz2[4];
    float dist[8];
    const float p0x = p[0], p0y = p[1], p0z = p[2];
    const u64 nw0x = pk2(-p0x, -p0x), nw0y = pk2(-p0y, -p0y), nw0z = pk2(-p0z, -p0z);
#pragma unroll
    for (int i = 0; i < 4; i++) {
        int id0 = t + (2 * i) * 512, id1 = t + (2 * i + 1) * 512;
        float x0 = p[id0 * 3 + 0], y0 = p[id0 * 3 + 1], z0 = p[id0 * 3 + 2];
        float x1 = p[id1 * 3 + 0], y1 = p[id1 * 3 + 1], z1 = p[id1 * 3 + 2];
        fsm[id0 * 3 + 0] = x0; fsm[id0 * 3 + 1] = y0; fsm[id0 * 3 + 2] = z0;
        fsm[id1 * 3 + 0] = x1; fsm[id1 * 3 + 1] = y1; fsm[id1 * 3 + 2] = z1;
        px2[i] = pk2(x0, x1); py2[i] = pk2(y0, y1); pz2[i] = pk2(z0, z1);
        u64 dx = fadd2(px2[i], nw0x), dy = fadd2(py2[i], nw0y), dz = fadd2(pz2[i], nw0z);
        u64 ss = fadd2(fadd2(fmul2(dx, dx), fmul2(dy, dy)), fmul2(dz, dz));
        float s0, s1; upk2(ss, s0, s1);
        dist[2 * i] = s0; dist[2 * i + 1] = s1;
    }
    if (t == 0) {
        s_fidx[0] = 0;
        s_best[0] = 0u; s_best[1] = 0u;
        s_idx[0] = 0xffffffffu; s_idx[1] = 0xffffffffu;
    }
    unsigned bb = 0;
#pragma unroll
    for (int i = 0; i < 8; i++) bb = max(bb, __float_as_uint(dist[i]));
    __syncthreads();

    for (int s = 1; s < MPER; s++) {
        const int par = s & 1;
        unsigned rd = redux_max(bb);
        if ((t & 31) == 0) atomicMax(&s_best[par], rd);
        __syncthreads();
        const unsigned bits = s_best[par];
        if (t == 0) { s_best[1 - par] = 0u; s_idx[1 - par] = 0xffffffffu; }
        if (rd == bits) {                       // warp-uniform predicate
            unsigned cand = 0xffffffffu;
#pragma unroll
            for (int i = 0; i < 8; i++) {
                if (__float_as_uint(dist[i]) == bits) cand = min(cand, (unsigned)(t + i * 512));
            }
            cand = redux_min(cand);
            if ((t & 31) == 0) atomicMin(&s_idx[par], cand);
        }
        __syncthreads();
        const int widx = (int)s_idx[par];
        if (t == 0) s_fidx[s] = widx;
        const float wx = fsm[widx * 3 + 0], wy = fsm[widx * 3 + 1], wz = fsm[widx * 3 + 2];
        const u64 nwx = pk2(-wx, -wx), nwy = pk2(-wy, -wy), nwz = pk2(-wz, -wz);
        bb = 0;
#pragma unroll
        for (int i = 0; i < 4; i++) {
            u64 dx = fadd2(px2[i], nwx), dy = fadd2(py2[i], nwy), dz = fadd2(pz2[i], nwz);
            u64 ss = fadd2(fadd2(fmul2(dx, dx), fmul2(dy, dy)), fmul2(dz, dz));
            float s0, s1; upk2(ss, s0, s1);
            float n0 = fminf(dist[2 * i], s0), n1 = fminf(dist[2 * i + 1], s1);
            dist[2 * i] = n0; dist[2 * i + 1] = n1;
            bb = max(bb, __float_as_uint(n0));
            bb = max(bb, __float_as_uint(n1));
        }
    }
    __syncthreads();

    for (int s = t; s < MPER; s += 512) {
        int li = s_fidx[s];
        int c = g * MPER + s;
        float x = fsm[li * 3 + 0], y = fsm[li * 3 + 1], z = fsm[li * 3 + 2];
        g_pdst[c * 3 + 0] = x; g_pdst[c * 3 + 1] = y; g_pdst[c * 3 + 2] = z;
        out[POFF + c * 3 + 0] = x;
        out[POFF + c * 3 + 1] = y;
        out[POFF + c * 3 + 2] = z;
        out[BOFF + c] = (float)g;
    }
}

// ---------------- ball query + radix-bucket top-64 -------------------------
#define HISTN 512
#define SELCAP 1024
__global__ void __launch_bounds__(256) select_kernel(const float* __restrict__ pos) {
    __shared__ u64 key[NPER];
    __shared__ int hist[HISTN];
    __shared__ u64 selbuf[SELCAP];
    __shared__ unsigned s_wsum[8];
    __shared__ int s_cnt, s_bstar, s_base, s_sel;

    const int c = blockIdx.x;
    const int tid = threadIdx.x;
    const int lane = tid & 31, w = tid >> 5;
    const int g = c >> 10;
    const float* p = pos + (size_t)g * NPER * 3;
    const float cx = g_pdst[c * 3 + 0], cy = g_pdst[c * 3 + 1], cz = g_pdst[c * 3 + 2];

    if (tid == 0) { s_cnt = 0; s_bstar = 0x7fffffff; s_sel = 0; }
    for (int i = tid; i < HISTN; i += 256) hist[i] = 0;
    __syncthreads();

    for (int i = tid; i < NPER; i += 256) {
        float d2 = d2_exact(p[i * 3], p[i * 3 + 1], p[i * 3 + 2], cx, cy, cz);
        if (d2 <= R2SQ) {
            unsigned bits = __float_as_uint(d2);
            int b = (int)(bits >> 21);
            unsigned am = __activemask();
            int rank = __popc(am & ((1u << lane) - 1));
            int ldr = __ffs(am) - 1;
            int base;
            if (lane == ldr) base = atomicAdd(&s_cnt, __popc(am));
            base = __shfl_sync(am, base, ldr);
            key[base + rank] = ((u64)bits << 32) | (unsigned)i;
            unsigned mm = __match_any_sync(am, b);
            if (lane == (__ffs(mm) - 1)) atomicAdd(&hist[b], __popc(mm));
        }
    }
    __syncthreads();
    const int m = s_cnt;
    const int need = (m < 64) ? m : 64;

    {
        int h0 = hist[2 * tid], h1 = hist[2 * tid + 1];
        unsigned l = (unsigned)(h0 + h1);
        unsigned v = l;
#pragma unroll
        for (int o = 1; o < 32; o <<= 1) {
            unsigned n = __shfl_up_sync(0xffffffffu, v, o);
            if (lane >= o) v += n;
        }
        if (lane == 31) s_wsum[w] = v;
        __syncthreads();
        unsigned woff = 0;
#pragma unroll
        for (int q = 0; q < 8; q++) woff += (q < w) ? s_wsum[q] : 0;
        unsigned ex = woff + v - l;
        int cum0 = (int)ex + h0;
        int cum1 = cum0 + h1;
        int cand = 0x7fffffff;
        if (cum0 >= need) cand = 2 * tid;
        else if (cum1 >= need) cand = 2 * tid + 1;
        if (cand != 0x7fffffff) atomicMin(&s_bstar, cand);
        __syncthreads();
        int bs = s_bstar;
        if (bs == 2 * tid) s_base = (int)ex;
        else if (bs == 2 * tid + 1) s_base = cum0;
        __syncthreads();
    }
    const int bstar = s_bstar;

    for (int i = tid; i < m; i += 256) {
        u64 kk = key[i];
        int b = (int)((unsigned)(kk >> 32) >> 21);
        if (b <= bstar) {
            int s = atomicAdd(&s_sel, 1);
            if (s < SELCAP) selbuf[s] = kk;
        }
    }
    __syncthreads();
    int S = s_sel; if (S > SELCAP) S = SELCAP;
    int P2 = 64; while (P2 < S) P2 <<= 1;
    for (int i = S + tid; i < P2; i += 256) selbuf[i] = ~0ull;
    __syncthreads();

    for (int k2 = 2; k2 <= P2; k2 <<= 1) {
        for (int j = k2 >> 1; j > 0; j >>= 1) {
            for (int i = tid; i < P2; i += 256) {
                int l = i ^ j;
                if (l > i) {
                    u64 a = selbuf[i], b = selbuf[l];
                    bool up = ((i & k2) == 0);
                    if (up ? (a > b) : (a < b)) { selbuf[i] = b; selbuf[l] = a; }
                }
            }
            __syncthreads();
        }
    }

    if (tid < KN2) {
        u64 kk = selbuf[tid];
        int idx = (int)(kk & 0xffffffffu);
        bool v2 = tid < m;
        g_nbr2[c * KN2 + tid] = v2 ? idx : -1;
        if (tid < KN1) {
            float d2 = __uint_as_float((unsigned)(kk >> 32));
            g_nbr1[c * KN1 + tid] = (v2 && d2 <= R1SQ) ? idx : -1;
        }
    }
}

// ---------------- Y = X @ W1[:64,:]  (merged branches, base-offset) --------
__global__ void __launch_bounds__(256) ymm_kernel(const float* __restrict__ x,
                                                  const float* __restrict__ w11,
                                                  const float* __restrict__ w21,
                                                  int base) {
    __shared__ float sW[64 * 64];
    __shared__ float sx[4 * 64];
    int vb = blockIdx.x + base;             // 0..8191
    int br = (vb < 4096) ? 1 : 0;           // first half: branch 1 (w21)
    const float* W1 = (br == 1) ? w21 : w11;
    int tid = threadIdx.x;
    for (int i = tid; i < 4096; i += 256) sW[i] = W1[i];
    int p0 = (vb & 4095) * 4;
    sx[tid] = x[(size_t)p0 * 64 + tid];
    __syncthreads();
    int lp = tid >> 6, c = tid & 63;
    float acc = 0.f;
#pragma unroll
    for (int k = 0; k < 64; k++) acc += sx[lp * 64 + k] * sW[k * 64 + c];
    g_Y[br][(size_t)(p0 + lp) * 64 + c] = acc;
}

// ---------------- MLP + max-pool: merged register-tiled GEMM ---------------
// grid 3072: bid<2048 -> branch2 (K=64,G=2,coloff=128); else branch1 (K=32,G=4).
__global__ void __launch_bounds__(128, 1) mlp_kernel(const float* __restrict__ pos,
                                                     const float* __restrict__ w11,
                                                     const float* __restrict__ b11,
                                                     const float* __restrict__ w12,
                                                     const float* __restrict__ b12,
                                                     const float* __restrict__ w13,
                                                     const float* __restrict__ b13,
                                                     const float* __restrict__ w21,
                                                     const float* __restrict__ b21,
                                                     const float* __restrict__ w22,
                                                     const float* __restrict__ b22,
                                                     const float* __restrict__ w23,
                                                     const float* __restrict__ b23,
                                                     float* __restrict__ out) {
    extern __shared__ float sm[];
    const int tid = threadIdx.x;
    const int lane = tid & 31, w = tid >> 5;
    const int rg = lane >> 3, cg = lane & 7;
    const int base_r = w * 32 + rg * 8;
    const int colA = 4 * cg, colB = 32 + 4 * cg;

    const bool br2 = blockIdx.x < 2048;
    const int bid2 = br2 ? blockIdx.x : (blockIdx.x - 2048);
    const int G = br2 ? 2 : 4;
    const int coloff = br2 ? 128 : 0;
    const float* W1 = br2 ? w21 : w11;
    const float* B1 = br2 ? b21 : b11;
    const float* W2 = br2 ? w22 : w12;
    const float* B2 = br2 ? b22 : b12;
    const float* W3 = br2 ? w23 : w13;
    const float* B3 = br2 ? b23 : b13;
    const float* Y  = g_Y[br2 ? 1 : 0];
    const int* nbr  = br2 ? g_nbr2 : g_nbr1;
    const int K     = br2 ? KN2 : KN1;

    for (int i = tid; i < 4096; i += 128) sm[OFF_W2 + (i >> 6) * 68 + (i & 63)] = W2[i];
    for (int i = tid; i < 8192; i += 128) sm[OFF_W3 + (i >> 7) * 132 + (i & 127)] = W3[i];
    if (tid < 64) {
        sm[OFF_WP + tid]        = W1[4096 + tid];
        sm[OFF_WP + 64 + tid]   = W1[4096 + 64 + tid];
        sm[OFF_WP + 128 + tid]  = W1[4096 + 128 + tid];
        sm[OFF_B1 + tid] = B1[tid];
        sm[OFF_B2 + tid] = B2[tid];
    }
    sm[OFF_B3 + tid] = B3[tid];
    int* souti = (int*)(sm + OFF_OUT);
    for (int i = tid; i < G * 128; i += 128) souti[i] = 0;
    __syncthreads();

    {
        const int ci = br2 ? (tid >> 6) : (tid >> 5);
        const int n  = tid & (K - 1);
        const int crow = bid2 * G + ci;
        const int g = crow >> 10;

        int j = nbr[crow * K + n];
        const bool valid = (j >= 0);
        if (!valid) j = 0;
        ((int*)(sm + OFF_VALID))[tid] = valid ? 1 : 0;

        const float* pg = pos + (size_t)g * NPER * 3;
        const float dx = pg[j * 3 + 0] - g_pdst[crow * 3 + 0];
        const float dy = pg[j * 3 + 1] - g_pdst[crow * 3 + 1];
        const float dz = pg[j * 3 + 2] - g_pdst[crow * 3 + 2];
        const float* yrow = Y + (size_t)(g * NPER + j) * 64;

        const u64 dx2 = pk2(dx, dx), dy2 = pk2(dy, dy), dz2 = pk2(dz, dz);

        float h1[64];
#pragma unroll
        for (int c = 0; c < 64; c += 4) {
            ulonglong2 y2 = *(const ulonglong2*)(yrow + c);
            ulonglong2 w0 = *(const ulonglong2*)(sm + OFF_WP + c);
            ulonglong2 w1 = *(const ulonglong2*)(sm + OFF_WP + 64 + c);
            ulonglong2 w2 = *(const ulonglong2*)(sm + OFF_WP + 128 + c);
            ulonglong2 bb = *(const ulonglong2*)(sm + OFF_B1 + c);
            u64 t0 = ffma2(dx2, w0.x, y2.x);
            t0 = ffma2(dy2, w1.x, t0);
            t0 = ffma2(dz2, w2.x, t0);
            t0 = fadd2(t0, bb.x);
            u64 t1 = ffma2(dx2, w0.y, y2.y);
            t1 = ffma2(dy2, w1.y, t1);
            t1 = ffma2(dz2, w2.y, t1);
            t1 = fadd2(t1, bb.y);
            float a0, a1, a2, a3;
            upk2(t0, a0, a1); upk2(t1, a2, a3);
            h1[c + 0] = fmaxf(a0, 0.f);
            h1[c + 1] = fmaxf(a1, 0.f);
            h1[c + 2] = fmaxf(a2, 0.f);
            h1[c + 3] = fmaxf(a3, 0.f);
        }
#pragma unroll
        for (int c = 0; c < 64; c++)
            sm[OFF_H + c * 132 + (tid ^ (4 * (c >> 3)))] = h1[c];
    }
    __syncthreads();

    int vld[8];
#pragma unroll
    for (int r = 0; r < 8; r++) vld[r] = ((int*)(sm + OFF_VALID))[base_r + r];

    u64 acc[8][4];
    {
        float4 bA = *(const float4*)(sm + OFF_B2 + colA);
        float4 bB = *(const float4*)(sm + OFF_B2 + colB);
        u64 i0 = pk2(bA.x, bA.y), i1 = pk2(bA.z, bA.w);
        u64 i2 = pk2(bB.x, bB.y), i3 = pk2(bB.z, bB.w);
#pragma unroll
        for (int r = 0; r < 8; r++) { acc[r][0] = i0; acc[r][1] = i1; acc[r][2] = i2; acc[r][3] = i3; }
    }
#pragma unroll 4
    for (int k = 0; k < 64; k++) {
        int sw = 4 * (k >> 3);
        const float* hrow = sm + OFF_H + k * 132;
        float4 a0 = *(const float4*)(hrow + (base_r ^ sw));
        float4 a1 = *(const float4*)(hrow + ((base_r + 4) ^ sw));
        ulonglong2 wA = *(const ulonglong2*)(sm + OFF_W2 + k * 68 + colA);
        ulonglong2 wB = *(const ulonglong2*)(sm + OFF_W2 + k * 68 + colB);
        float av[8] = {a0.x, a0.y, a0.z, a0.w, a1.x, a1.y, a1.z, a1.w};
#pragma unroll
        for (int r = 0; r < 8; r++) {
            u64 ar = pk2(av[r], av[r]);
            acc[r][0] = ffma2(ar, wA.x, acc[r][0]);
            acc[r][1] = ffma2(ar, wA.y, acc[r][1]);
            acc[r][2] = ffma2(ar, wB.x, acc[r][2]);
            acc[r][3] = ffma2(ar, wB.y, acc[r][3]);
        }
    }
    __syncthreads();
#pragma unroll
    for (int p = 0; p < 4; p++) {
        int c0 = (p < 2) ? (colA + 2 * p) : (colB + 2 * (p - 2));
        float va[8], vb[8];
#pragma unroll
        for (int r = 0; r < 8; r++) {
            float x, y; upk2(acc[r][p], x, y);
            va[r] = fmaxf(x, 0.f); vb[r] = fmaxf(y, 0.f);
        }
        int sw = 4 * (c0 >> 3);
        float* d0 = sm + OFF_H + c0 * 132;
        float* d1 = d0 + 132;
        *(float4*)(d0 + (base_r ^ sw))       = make_float4(va[0], va[1], va[2], va[3]);
        *(float4*)(d0 + ((base_r + 4) ^ sw)) = make_float4(va[4], va[5], va[6], va[7]);
        *(float4*)(d1 + (base_r ^ sw))       = make_float4(vb[0], vb[1], vb[2], vb[3]);
        *(float4*)(d1 + ((base_r + 4) ^ sw)) = make_float4(vb[4], vb[5], vb[6], vb[7]);
    }
    __syncthreads();

    const int ci = br2 ? (w >> 1) : w;
#pragma unroll
    for (int po = 0; po < 128; po += 64) {
        {
            float4 bA = *(const float4*)(sm + OFF_B3 + po + colA);
            float4 bB = *(const float4*)(sm + OFF_B3 + po + colB);
            u64 i0 = pk2(bA.x, bA.y), i1 = pk2(bA.z, bA.w);
            u64 i2 = pk2(bB.x, bB.y), i3 = pk2(bB.z, bB.w);
#pragma unroll
            for (int r = 0; r < 8; r++) { acc[r][0] = i0; acc[r][1] = i1; acc[r][2] = i2; acc[r][3] = i3; }
        }
#pragma unroll 4
        for (int k = 0; k < 64; k++) {
            int sw = 4 * (k >> 3);
            const float* hrow = sm + OFF_H + k * 132;
            float4 a0 = *(const float4*)(hrow + (base_r ^ sw));
            float4 a1 = *(const float4*)(hrow + ((base_r + 4) ^ sw));
            ulonglong2 wA = *(const ulonglong2*)(sm + OFF_W3 + k * 132 + po + colA);
            ulonglong2 wB = *(const ulonglong2*)(sm + OFF_W3 + k * 132 + po + colB);
            float av[8] = {a0.x, a0.y, a0.z, a0.w, a1.x, a1.y, a1.z, a1.w};
#pragma unroll
            for (int r = 0; r < 8; r++) {
                u64 ar = pk2(av[r], av[r]);
                acc[r][0] = ffma2(ar, wA.x, acc[r][0]);
                acc[r][1] = ffma2(ar, wA.y, acc[r][1]);
                acc[r][2] = ffma2(ar, wB.x, acc[r][2]);
                acc[r][3] = ffma2(ar, wB.y, acc[r][3]);
            }
        }
#pragma unroll
        for (int p = 0; p < 4; p++) {
            int c0 = (p < 2) ? (colA + 2 * p) : (colB + 2 * (p - 2));
            float m0 = 0.f, m1 = 0.f;
#pragma unroll
            for (int r = 0; r < 8; r++) {
                float x, y; upk2(acc[r][p], x, y);
                float fx = vld[r] ? fmaxf(x, 0.f) : 0.f;
                float fy = vld[r] ? fmaxf(y, 0.f) : 0.f;
                m0 = fmaxf(m0, fx); m1 = fmaxf(m1, fy);
            }
            m0 = fmaxf(m0, __shfl_xor_sync(0xffffffffu, m0, 8));
            m0 = fmaxf(m0, __shfl_xor_sync(0xffffffffu, m0, 16));
            m1 = fmaxf(m1, __shfl_xor_sync(0xffffffffu, m1, 8));
            m1 = fmaxf(m1, __shfl_xor_sync(0xffffffffu, m1, 16));
            if (lane < 8) {
                atomicMax(&souti[ci * 128 + po + c0],     __float_as_int(m0));
                atomicMax(&souti[ci * 128 + po + c0 + 1], __float_as_int(m1));
            }
        }
    }
    __syncthreads();
    for (int i = tid; i < G * 128; i += 128) {
        int lc = i >> 7, ch = i & 127;
        out[(size_t)(bid2 * G + lc) * 256 + coloff + ch] = __int_as_float(souti[i]);
    }
}

// ---------------- launch ----------------
extern "C" void kernel_launch(void* const* d_in, const int* in_sizes, int n_in,
                              void* d_out, int out_size) {
    const float* x   = (const float*)d_in[0];
    const float* pos = (const float*)d_in[1];
    const float* w11 = (const float*)d_in[3];
    const float* b11 = (const float*)d_in[4];
    const float* w12 = (const float*)d_in[5];
    const float* b12 = (const float*)d_in[6];
    const float* w13 = (const float*)d_in[7];
    const float* b13 = (const float*)d_in[8];
    const float* w21 = (const float*)d_in[9];
    const float* b21 = (const float*)d_in[10];
    const float* w22 = (const float*)d_in[11];
    const float* b22 = (const float*)d_in[12];
    const float* w23 = (const float*)d_in[13];
    const float* b23 = (const float*)d_in[14];
    float* out = (float*)d_out;

    const int smemM = (OFF_OUT + 512) * 4;
    cudaFuncSetAttribute((const void*)mlp_kernel,
                         cudaFuncAttributeMaxDynamicSharedMemorySize, smemM);
    cudaFuncSetAttribute((const void*)fps_kernel,
                         cudaFuncAttributeMaxDynamicSharedMemorySize, FPS_SMEM);

    // ymm split 3 ways so fps_kernel lands on the ncu capture slot (4th).
    ymm_kernel<<<3072, 256>>>(x, w11, w21, 0);
    ymm_kernel<<<3072, 256>>>(x, w11, w21, 3072);
    ymm_kernel<<<2048, 256>>>(x, w11, w21, 6144);
    fps_kernel<<<BGR, 512, FPS_SMEM>>>(pos, out);
    select_kernel<<<BGR * MPER, 256>>>(pos);
    mlp_kernel<<<3072, 128, smemM>>>(pos, w11, b11, w12, b12, w13, b13,
                                     w21, b21, w22, b22, w23, b23, out);
}

// round 8
// speedup vs baseline: 2.4535x; 1.0421x over previous
#include <cuda_runtime.h>
#include <cuda_bf16.h>
#include <cstdint>

#define BGR 4
#define NPER 4096
#define MPER 1024
#define DIN 64
#define KN1 32
#define KN2 64
#define R1SQ 0.04f
#define R2SQ 0.16f

#define POFF (BGR*MPER*256)          // 1048576
#define BOFF (POFF + BGR*MPER*3)     // 1060864

typedef unsigned long long u64;

// smem float offsets for mlp kernel
#define OFF_W2   0                   // [64][68]
#define OFF_W3   4352                // [64][132]
#define OFF_H    12800               // [64][132]
#define OFF_WP   21248               // [3][64]
#define OFF_B1   21440
#define OFF_B2   21504
#define OFF_B3   21568               // [128]
#define OFF_VALID 21696              // [128] ints
#define OFF_OUT  21824               // [up to 512] ints

// ---------------- scratch (device globals; no allocation allowed) ----------
__device__ float g_pdst[BGR*MPER*3];
__device__ int   g_nbr1[BGR*MPER*KN1];
__device__ int   g_nbr2[BGR*MPER*KN2];
__device__ float g_Y[2][BGR*NPER*DIN];

// ---------------- helpers ----------------
__device__ __forceinline__ float d2_exact(float ax, float ay, float az,
                                          float bx, float by, float bz) {
    float dx = __fsub_rn(ax, bx);
    float dy = __fsub_rn(ay, by);
    float dz = __fsub_rn(az, bz);
    return __fadd_rn(__fadd_rn(__fmul_rn(dx, dx), __fmul_rn(dy, dy)), __fmul_rn(dz, dz));
}

__device__ __forceinline__ u64 pk2(float lo, float hi) {
    u64 r; asm("mov.b64 %0,{%1,%2};" : "=l"(r) : "f"(lo), "f"(hi)); return r;
}
__device__ __forceinline__ void upk2(u64 v, float& lo, float& hi) {
    asm("mov.b64 {%0,%1}, %2;" : "=f"(lo), "=f"(hi) : "l"(v));
}
__device__ __forceinline__ u64 ffma2(u64 a, u64 b, u64 c) {
    u64 r; asm("fma.rn.f32x2 %0,%1,%2,%3;" : "=l"(r) : "l"(a), "l"(b), "l"(c)); return r;
}
__device__ __forceinline__ u64 fadd2(u64 a, u64 b) {
    u64 r; asm("add.rn.f32x2 %0,%1,%2;" : "=l"(r) : "l"(a), "l"(b)); return r;
}
__device__ __forceinline__ u64 fmul2(u64 a, u64 b) {
    u64 r; asm("mul.rn.f32x2 %0,%1,%2;" : "=l"(r) : "l"(a), "l"(b)); return r;
}
__device__ __forceinline__ unsigned redux_max(unsigned v) {
    unsigned r; asm("redux.sync.max.u32 %0, %1, 0xffffffff;" : "=r"(r) : "r"(v)); return r;
}
__device__ __forceinline__ unsigned redux_min(unsigned v) {
    unsigned r; asm("redux.sync.min.u32 %0, %1, 0xffffffff;" : "=r"(r) : "r"(v)); return r;
}

// ---------------- fused FPS + ymm: blocks 0..3 FPS, 4..4099 ymm -----------
// fps dynamic smem: pos[12288] floats | fidx[1024] ints | red[2][16] u64
#define FPS_OFF_FIDX 12288
#define FPS_OFF_RED  13312
#define FPS_SMEM     ((13312 + 64) * 4)     // 53504 B
__global__ void __launch_bounds__(512) fps_ymm_kernel(const float* __restrict__ pos,
                                                      const float* __restrict__ x,
                                                      const float* __restrict__ w11,
                                                      const float* __restrict__ w21,
                                                      float* __restrict__ out) {
    extern __shared__ float fsm[];
    const int t = threadIdx.x;

    if (blockIdx.x >= BGR) {
        // ---- ymm path: Y = X @ W1[:64,:], 8 rows per block ----
        int vb = blockIdx.x - BGR;               // 0..4095
        int br = (vb < 2048) ? 1 : 0;
        const float* W1 = br ? w21 : w11;
        float* sW = fsm;                          // 4096 floats
        float* sx = fsm + 4096;                   // 512 floats
        for (int i = t; i < 4096; i += 512) sW[i] = W1[i];
        int p0 = (vb & 2047) * 8;
        sx[t] = x[(size_t)p0 * 64 + t];
        __syncthreads();
        int lp = t >> 6, c = t & 63;
        float acc = 0.f;
#pragma unroll
        for (int k = 0; k < 64; k++) acc += sx[lp * 64 + k] * sW[k * 64 + c];
        g_Y[br][(size_t)(p0 + lp) * 64 + c] = acc;
        return;
    }

    // ---- fps path ----
    int* s_fidx = (int*)(fsm + FPS_OFF_FIDX);
    u64* s_red  = (u64*)(fsm + FPS_OFF_RED);      // [2][16] double-buffered

    const int g = blockIdx.x;
    const float* p = pos + (size_t)g * NPER * 3;
    const int lane = t & 31, wid = t >> 5;

    u64 px2[4], py2[4], pz2[4];
    float dist[8];
    const float p0x = p[0], p0y = p[1], p0z = p[2];
    const u64 nw0x = pk2(-p0x, -p0x), nw0y = pk2(-p0y, -p0y), nw0z = pk2(-p0z, -p0z);
    float bbf = 0.f;
#pragma unroll
    for (int i = 0; i < 4; i++) {
        int id0 = t + (2 * i) * 512, id1 = t + (2 * i + 1) * 512;
        float x0 = p[id0 * 3 + 0], y0 = p[id0 * 3 + 1], z0 = p[id0 * 3 + 2];
        float x1 = p[id1 * 3 + 0], y1 = p[id1 * 3 + 1], z1 = p[id1 * 3 + 2];
        fsm[id0 * 3 + 0] = x0; fsm[id0 * 3 + 1] = y0; fsm[id0 * 3 + 2] = z0;
        fsm[id1 * 3 + 0] = x1; fsm[id1 * 3 + 1] = y1; fsm[id1 * 3 + 2] = z1;
        px2[i] = pk2(x0, x1); py2[i] = pk2(y0, y1); pz2[i] = pk2(z0, z1);
        u64 dx = fadd2(px2[i], nw0x), dy = fadd2(py2[i], nw0y), dz = fadd2(pz2[i], nw0z);
        u64 ss = fadd2(fadd2(fmul2(dx, dx), fmul2(dy, dy)), fmul2(dz, dz));
        float s0, s1; upk2(ss, s0, s1);
        dist[2 * i] = s0; dist[2 * i + 1] = s1;
        bbf = fmaxf(bbf, fmaxf(s0, s1));
    }
    if (t == 0) s_fidx[0] = 0;

    for (int s = 1; s < MPER; s++) {
        // per-warp speculative (max bits, min index achieving it)
        unsigned cand = 0xffffffffu;
#pragma unroll
        for (int i = 0; i < 8; i++) {
            if (dist[i] == bbf) cand = min(cand, (unsigned)(t + i * 512));
        }
        unsigned bits = __float_as_uint(bbf);      // dist >= 0: float order == uint order
        unsigned wbits = redux_max(bits);
        unsigned c2 = (bits == wbits) ? cand : 0xffffffffu;
        c2 = redux_min(c2);
        u64* buf = s_red + (s & 1) * 16;
        if (lane == 0) buf[wid] = ((u64)wbits << 32) | c2;
        __syncthreads();
        // every warp redundantly reduces the 16 warp entries (no 2nd barrier)
        u64 v = (lane < 16) ? buf[lane] : 0x00000000ffffffffull;
        unsigned b16 = (unsigned)(v >> 32);
        unsigned rd = redux_max(b16);
        unsigned c3 = (b16 == rd) ? (unsigned)v : 0xffffffffu;
        unsigned widx = redux_min(c3);
        if (t == 0) s_fidx[s] = (int)widx;

        const float wx = fsm[widx * 3 + 0], wy = fsm[widx * 3 + 1], wz = fsm[widx * 3 + 2];
        const u64 nwx = pk2(-wx, -wx), nwy = pk2(-wy, -wy), nwz = pk2(-wz, -wz);
        bbf = 0.f;
#pragma unroll
        for (int i = 0; i < 4; i++) {
            u64 dx = fadd2(px2[i], nwx), dy = fadd2(py2[i], nwy), dz = fadd2(pz2[i], nwz);
            u64 ss = fadd2(fadd2(fmul2(dx, dx), fmul2(dy, dy)), fmul2(dz, dz));
            float s0, s1; upk2(ss, s0, s1);
            float n0 = fminf(dist[2 * i], s0), n1 = fminf(dist[2 * i + 1], s1);
            dist[2 * i] = n0; dist[2 * i + 1] = n1;
            bbf = fmaxf(bbf, fmaxf(n0, n1));
        }
    }
    __syncthreads();

    for (int s = t; s < MPER; s += 512) {
        int li = s_fidx[s];
        int c = g * MPER + s;
        float xx = fsm[li * 3 + 0], yy = fsm[li * 3 + 1], zz = fsm[li * 3 + 2];
        g_pdst[c * 3 + 0] = xx; g_pdst[c * 3 + 1] = yy; g_pdst[c * 3 + 2] = zz;
        out[POFF + c * 3 + 0] = xx;
        out[POFF + c * 3 + 1] = yy;
        out[POFF + c * 3 + 2] = zz;
        out[BOFF + c] = (float)g;
    }
}

// ---------------- ball query + radix-bucket top-64 -------------------------
#define HISTN 512
#define SELCAP 1024
__global__ void __launch_bounds__(256) select_kernel(const float* __restrict__ pos) {
    __shared__ u64 key[NPER];
    __shared__ int hist[HISTN];
    __shared__ u64 selbuf[SELCAP];
    __shared__ unsigned s_wsum[8];
    __shared__ int s_cnt, s_bstar, s_base, s_sel;

    const int c = blockIdx.x;
    const int tid = threadIdx.x;
    const int lane = tid & 31, w = tid >> 5;
    const int g = c >> 10;
    const float* p = pos + (size_t)g * NPER * 3;
    const float cx = g_pdst[c * 3 + 0], cy = g_pdst[c * 3 + 1], cz = g_pdst[c * 3 + 2];

    if (tid == 0) { s_cnt = 0; s_bstar = 0x7fffffff; s_sel = 0; }
    for (int i = tid; i < HISTN; i += 256) hist[i] = 0;
    __syncthreads();

    for (int i = tid; i < NPER; i += 256) {
        float d2 = d2_exact(p[i * 3], p[i * 3 + 1], p[i * 3 + 2], cx, cy, cz);
        if (d2 <= R2SQ) {
            unsigned bits = __float_as_uint(d2);
            int b = (int)(bits >> 21);
            unsigned am = __activemask();
            int rank = __popc(am & ((1u << lane) - 1));
            int ldr = __ffs(am) - 1;
            int base;
            if (lane == ldr) base = atomicAdd(&s_cnt, __popc(am));
            base = __shfl_sync(am, base, ldr);
            key[base + rank] = ((u64)bits << 32) | (unsigned)i;
            unsigned mm = __match_any_sync(am, b);
            if (lane == (__ffs(mm) - 1)) atomicAdd(&hist[b], __popc(mm));
        }
    }
    __syncthreads();
    const int m = s_cnt;
    const int need = (m < 64) ? m : 64;

    {
        int h0 = hist[2 * tid], h1 = hist[2 * tid + 1];
        unsigned l = (unsigned)(h0 + h1);
        unsigned v = l;
#pragma unroll
        for (int o = 1; o < 32; o <<= 1) {
            unsigned n = __shfl_up_sync(0xffffffffu, v, o);
            if (lane >= o) v += n;
        }
        if (lane == 31) s_wsum[w] = v;
        __syncthreads();
        unsigned woff = 0;
#pragma unroll
        for (int q = 0; q < 8; q++) woff += (q < w) ? s_wsum[q] : 0;
        unsigned ex = woff + v - l;
        int cum0 = (int)ex + h0;
        int cum1 = cum0 + h1;
        int cand = 0x7fffffff;
        if (cum0 >= need) cand = 2 * tid;
        else if (cum1 >= need) cand = 2 * tid + 1;
        if (cand != 0x7fffffff) atomicMin(&s_bstar, cand);
        __syncthreads();
        int bs = s_bstar;
        if (bs == 2 * tid) s_base = (int)ex;
        else if (bs == 2 * tid + 1) s_base = cum0;
        __syncthreads();
    }
    const int bstar = s_bstar;

    for (int i = tid; i < m; i += 256) {
        u64 kk = key[i];
        int b = (int)((unsigned)(kk >> 32) >> 21);
        if (b <= bstar) {
            int s = atomicAdd(&s_sel, 1);
            if (s < SELCAP) selbuf[s] = kk;
        }
    }
    __syncthreads();
    int S = s_sel; if (S > SELCAP) S = SELCAP;
    int P2 = 64; while (P2 < S) P2 <<= 1;
    for (int i = S + tid; i < P2; i += 256) selbuf[i] = ~0ull;
    __syncthreads();

    for (int k2 = 2; k2 <= P2; k2 <<= 1) {
        for (int j = k2 >> 1; j > 0; j >>= 1) {
            for (int i = tid; i < P2; i += 256) {
                int l = i ^ j;
                if (l > i) {
                    u64 a = selbuf[i], b = selbuf[l];
                    bool up = ((i & k2) == 0);
                    if (up ? (a > b) : (a < b)) { selbuf[i] = b; selbuf[l] = a; }
                }
            }
            __syncthreads();
        }
    }

    if (tid < KN2) {
        u64 kk = selbuf[tid];
        int idx = (int)(kk & 0xffffffffu);
        bool v2 = tid < m;
        g_nbr2[c * KN2 + tid] = v2 ? idx : -1;
        if (tid < KN1) {
            float d2 = __uint_as_float((unsigned)(kk >> 32));
            g_nbr1[c * KN1 + tid] = (v2 && d2 <= R1SQ) ? idx : -1;
        }
    }
}

// ---------------- MLP + max-pool: merged register-tiled GEMM ---------------
// grid 3072: bid<2048 -> branch2 (K=64,G=2,coloff=128); else branch1 (K=32,G=4).
__global__ void __launch_bounds__(128, 1) mlp_kernel(const float* __restrict__ pos,
                                                     const float* __restrict__ w11,
                                                     const float* __restrict__ b11,
                                                     const float* __restrict__ w12,
                                                     const float* __restrict__ b12,
                                                     const float* __restrict__ w13,
                                                     const float* __restrict__ b13,
                                                     const float* __restrict__ w21,
                                                     const float* __restrict__ b21,
                                                     const float* __restrict__ w22,
                                                     const float* __restrict__ b22,
                                                     const float* __restrict__ w23,
                                                     const float* __restrict__ b23,
                                                     float* __restrict__ out) {
    extern __shared__ float sm[];
    const int tid = threadIdx.x;
    const int lane = tid & 31, w = tid >> 5;
    const int rg = lane >> 3, cg = lane & 7;
    const int base_r = w * 32 + rg * 8;
    const int colA = 4 * cg, colB = 32 + 4 * cg;

    const bool br2 = blockIdx.x < 2048;
    const int bid2 = br2 ? blockIdx.x : (blockIdx.x - 2048);
    const int G = br2 ? 2 : 4;
    const int coloff = br2 ? 128 : 0;
    const float* W1 = br2 ? w21 : w11;
    const float* B1 = br2 ? b21 : b11;
    const float* W2 = br2 ? w22 : w12;
    const float* B2 = br2 ? b22 : b12;
    const float* W3 = br2 ? w23 : w13;
    const float* B3 = br2 ? b23 : b13;
    const float* Y  = g_Y[br2 ? 1 : 0];
    const int* nbr  = br2 ? g_nbr2 : g_nbr1;
    const int K     = br2 ? KN2 : KN1;

    for (int i = tid; i < 4096; i += 128) sm[OFF_W2 + (i >> 6) * 68 + (i & 63)] = W2[i];
    for (int i = tid; i < 8192; i += 128) sm[OFF_W3 + (i >> 7) * 132 + (i & 127)] = W3[i];
    if (tid < 64) {
        sm[OFF_WP + tid]        = W1[4096 + tid];
        sm[OFF_WP + 64 + tid]   = W1[4096 + 64 + tid];
        sm[OFF_WP + 128 + tid]  = W1[4096 + 128 + tid];
        sm[OFF_B1 + tid] = B1[tid];
        sm[OFF_B2 + tid] = B2[tid];
    }
    sm[OFF_B3 + tid] = B3[tid];
    int* souti = (int*)(sm + OFF_OUT);
    for (int i = tid; i < G * 128; i += 128) souti[i] = 0;
    __syncthreads();

    {
        const int ci = br2 ? (tid >> 6) : (tid >> 5);
        const int n  = tid & (K - 1);
        const int crow = bid2 * G + ci;
        const int g = crow >> 10;

        int j = nbr[crow * K + n];
        const bool valid = (j >= 0);
        if (!valid) j = 0;
        ((int*)(sm + OFF_VALID))[tid] = valid ? 1 : 0;

        const float* pg = pos + (size_t)g * NPER * 3;
        const float dx = pg[j * 3 + 0] - g_pdst[crow * 3 + 0];
        const float dy = pg[j * 3 + 1] - g_pdst[crow * 3 + 1];
        const float dz = pg[j * 3 + 2] - g_pdst[crow * 3 + 2];
        const float* yrow = Y + (size_t)(g * NPER + j) * 64;

        const u64 dx2 = pk2(dx, dx), dy2 = pk2(dy, dy), dz2 = pk2(dz, dz);

        float h1[64];
#pragma unroll
        for (int c = 0; c < 64; c += 4) {
            ulonglong2 y2 = *(const ulonglong2*)(yrow + c);
            ulonglong2 w0 = *(const ulonglong2*)(sm + OFF_WP + c);
            ulonglong2 w1 = *(const ulonglong2*)(sm + OFF_WP + 64 + c);
            ulonglong2 w2 = *(const ulonglong2*)(sm + OFF_WP + 128 + c);
            ulonglong2 bb = *(const ulonglong2*)(sm + OFF_B1 + c);
            u64 t0 = ffma2(dx2, w0.x, y2.x);
            t0 = ffma2(dy2, w1.x, t0);
            t0 = ffma2(dz2, w2.x, t0);
            t0 = fadd2(t0, bb.x);
            u64 t1 = ffma2(dx2, w0.y, y2.y);
            t1 = ffma2(dy2, w1.y, t1);
            t1 = ffma2(dz2, w2.y, t1);
            t1 = fadd2(t1, bb.y);
            float a0, a1, a2, a3;
            upk2(t0, a0, a1); upk2(t1, a2, a3);
            h1[c + 0] = fmaxf(a0, 0.f);
            h1[c + 1] = fmaxf(a1, 0.f);
            h1[c + 2] = fmaxf(a2, 0.f);
            h1[c + 3] = fmaxf(a3, 0.f);
        }
#pragma unroll
        for (int c = 0; c < 64; c++)
            sm[OFF_H + c * 132 + (tid ^ (4 * (c >> 3)))] = h1[c];
    }
    __syncthreads();

    int vld[8];
#pragma unroll
    for (int r = 0; r < 8; r++) vld[r] = ((int*)(sm + OFF_VALID))[base_r + r];

    u64 acc[8][4];
    {
        float4 bA = *(const float4*)(sm + OFF_B2 + colA);
        float4 bB = *(const float4*)(sm + OFF_B2 + colB);
        u64 i0 = pk2(bA.x, bA.y), i1 = pk2(bA.z, bA.w);
        u64 i2 = pk2(bB.x, bB.y), i3 = pk2(bB.z, bB.w);
#pragma unroll
        for (int r = 0; r < 8; r++) { acc[r][0] = i0; acc[r][1] = i1; acc[r][2] = i2; acc[r][3] = i3; }
    }
#pragma unroll 4
    for (int k = 0; k < 64; k++) {
        int sw = 4 * (k >> 3);
        const float* hrow = sm + OFF_H + k * 132;
        float4 a0 = *(const float4*)(hrow + (base_r ^ sw));
        float4 a1 = *(const float4*)(hrow + ((base_r + 4) ^ sw));
        ulonglong2 wA = *(const ulonglong2*)(sm + OFF_W2 + k * 68 + colA);
        ulonglong2 wB = *(const ulonglong2*)(sm + OFF_W2 + k * 68 + colB);
        float av[8] = {a0.x, a0.y, a0.z, a0.w, a1.x, a1.y, a1.z, a1.w};
#pragma unroll
        for (int r = 0; r < 8; r++) {
            u64 ar = pk2(av[r], av[r]);
            acc[r][0] = ffma2(ar, wA.x, acc[r][0]);
            acc[r][1] = ffma2(ar, wA.y, acc[r][1]);
            acc[r][2] = ffma2(ar, wB.x, acc[r][2]);
            acc[r][3] = ffma2(ar, wB.y, acc[r][3]);
        }
    }
    __syncthreads();
#pragma unroll
    for (int p = 0; p < 4; p++) {
        int c0 = (p < 2) ? (colA + 2 * p) : (colB + 2 * (p - 2));
        float va[8], vb[8];
#pragma unroll
        for (int r = 0; r < 8; r++) {
            float x, y; upk2(acc[r][p], x, y);
            va[r] = fmaxf(x, 0.f); vb[r] = fmaxf(y, 0.f);
        }
        int sw = 4 * (c0 >> 3);
        float* d0 = sm + OFF_H + c0 * 132;
        float* d1 = d0 + 132;
        *(float4*)(d0 + (base_r ^ sw))       = make_float4(va[0], va[1], va[2], va[3]);
        *(float4*)(d0 + ((base_r + 4) ^ sw)) = make_float4(va[4], va[5], va[6], va[7]);
        *(float4*)(d1 + (base_r ^ sw))       = make_float4(vb[0], vb[1], vb[2], vb[3]);
        *(float4*)(d1 + ((base_r + 4) ^ sw)) = make_float4(vb[4], vb[5], vb[6], vb[7]);
    }
    __syncthreads();

    const int ci = br2 ? (w >> 1) : w;
#pragma unroll
    for (int po = 0; po < 128; po += 64) {
        {
            float4 bA = *(const float4*)(sm + OFF_B3 + po + colA);
            float4 bB = *(const float4*)(sm + OFF_B3 + po + colB);
            u64 i0 = pk2(bA.x, bA.y), i1 = pk2(bA.z, bA.w);
            u64 i2 = pk2(bB.x, bB.y), i3 = pk2(bB.z, bB.w);
#pragma unroll
            for (int r = 0; r < 8; r++) { acc[r][0] = i0; acc[r][1] = i1; acc[r][2] = i2; acc[r][3] = i3; }
        }
#pragma unroll 4
        for (int k = 0; k < 64; k++) {
            int sw = 4 * (k >> 3);
            const float* hrow = sm + OFF_H + k * 132;
            float4 a0 = *(const float4*)(hrow + (base_r ^ sw));
            float4 a1 = *(const float4*)(hrow + ((base_r + 4) ^ sw));
            ulonglong2 wA = *(const ulonglong2*)(sm + OFF_W3 + k * 132 + po + colA);
            ulonglong2 wB = *(const ulonglong2*)(sm + OFF_W3 + k * 132 + po + colB);
            float av[8] = {a0.x, a0.y, a0.z, a0.w, a1.x, a1.y, a1.z, a1.w};
#pragma unroll
            for (int r = 0; r < 8; r++) {
                u64 ar = pk2(av[r], av[r]);
                acc[r][0] = ffma2(ar, wA.x, acc[r][0]);
                acc[r][1] = ffma2(ar, wA.y, acc[r][1]);
                acc[r][2] = ffma2(ar, wB.x, acc[r][2]);
                acc[r][3] = ffma2(ar, wB.y, acc[r][3]);
            }
        }
#pragma unroll
        for (int p = 0; p < 4; p++) {
            int c0 = (p < 2) ? (colA + 2 * p) : (colB + 2 * (p - 2));
            float m0 = 0.f, m1 = 0.f;
#pragma unroll
            for (int r = 0; r < 8; r++) {
                float x, y; upk2(acc[r][p], x, y);
                float fx = vld[r] ? fmaxf(x, 0.f) : 0.f;
                float fy = vld[r] ? fmaxf(y, 0.f) : 0.f;
                m0 = fmaxf(m0, fx); m1 = fmaxf(m1, fy);
            }
            m0 = fmaxf(m0, __shfl_xor_sync(0xffffffffu, m0, 8));
            m0 = fmaxf(m0, __shfl_xor_sync(0xffffffffu, m0, 16));
            m1 = fmaxf(m1, __shfl_xor_sync(0xffffffffu, m1, 8));
            m1 = fmaxf(m1, __shfl_xor_sync(0xffffffffu, m1, 16));
            if (lane < 8) {
                atomicMax(&souti[ci * 128 + po + c0],     __float_as_int(m0));
                atomicMax(&souti[ci * 128 + po + c0 + 1], __float_as_int(m1));
            }
        }
    }
    __syncthreads();
    for (int i = tid; i < G * 128; i += 128) {
        int lc = i >> 7, ch = i & 127;
        out[(size_t)(bid2 * G + lc) * 256 + coloff + ch] = __int_as_float(souti[i]);
    }
}

// ---------------- launch ----------------
extern "C" void kernel_launch(void* const* d_in, const int* in_sizes, int n_in,
                              void* d_out, int out_size) {
    const float* x   = (const float*)d_in[0];
    const float* pos = (const float*)d_in[1];
    const float* w11 = (const float*)d_in[3];
    const float* b11 = (const float*)d_in[4];
    const float* w12 = (const float*)d_in[5];
    const float* b12 = (const float*)d_in[6];
    const float* w13 = (const float*)d_in[7];
    const float* b13 = (const float*)d_in[8];
    const float* w21 = (const float*)d_in[9];
    const float* b21 = (const float*)d_in[10];
    const float* w22 = (const float*)d_in[11];
    const float* b22 = (const float*)d_in[12];
    const float* w23 = (const float*)d_in[13];
    const float* b23 = (const float*)d_in[14];
    float* out = (float*)d_out;

    const int smemM = (OFF_OUT + 512) * 4;
    cudaFuncSetAttribute((const void*)mlp_kernel,
                         cudaFuncAttributeMaxDynamicSharedMemorySize, smemM);
    cudaFuncSetAttribute((const void*)fps_ymm_kernel,
                         cudaFuncAttributeMaxDynamicSharedMemorySize, FPS_SMEM);

    fps_ymm_kernel<<<BGR + 4096, 512, FPS_SMEM>>>(pos, x, w11, w21, out);
    select_kernel<<<BGR * MPER, 256>>>(pos);
    mlp_kernel<<<3072, 128, smemM>>>(pos, w11, b11, w12, b12, w13, b13,
                                     w21, b21, w22, b22, w23, b23, out);
}

// round 10
// speedup vs baseline: 2.5403x; 1.0353x over previous
#include <cuda_runtime.h>
#include <cuda_bf16.h>
#include <cstdint>

#define BGR 4
#define NPER 4096
#define MPER 1024
#define DIN 64
#define KN1 32
#define KN2 64
#define R1SQ 0.04f
#define R2SQ 0.16f

#define POFF (BGR*MPER*256)          // 1048576
#define BOFF (POFF + BGR*MPER*3)     // 1060864

typedef unsigned long long u64;

// smem float offsets for mlp kernel
#define OFF_W2   0                   // [64][68]
#define OFF_W3   4352                // [64][132]
#define OFF_H    12800               // [64][132]
#define OFF_WP   21248               // [3][64]
#define OFF_B1   21440
#define OFF_B2   21504
#define OFF_B3   21568               // [128]
#define OFF_VALID 21696              // [128] ints
#define OFF_OUT  21824               // [up to 512] ints

// ---------------- scratch (device globals; no allocation allowed) ----------
__device__ float g_pdst[BGR*MPER*3];
__device__ int   g_nbr1[BGR*MPER*KN1];
__device__ int   g_nbr2[BGR*MPER*KN2];
__device__ float g_Y[2][BGR*NPER*DIN];

// ---------------- helpers ----------------
__device__ __forceinline__ float d2_exact(float ax, float ay, float az,
                                          float bx, float by, float bz) {
    float dx = __fsub_rn(ax, bx);
    float dy = __fsub_rn(ay, by);
    float dz = __fsub_rn(az, bz);
    return __fadd_rn(__fadd_rn(__fmul_rn(dx, dx), __fmul_rn(dy, dy)), __fmul_rn(dz, dz));
}

__device__ __forceinline__ u64 pk2(float lo, float hi) {
    u64 r; asm("mov.b64 %0,{%1,%2};" : "=l"(r) : "f"(lo), "f"(hi)); return r;
}
__device__ __forceinline__ void upk2(u64 v, float& lo, float& hi) {
    asm("mov.b64 {%0,%1}, %2;" : "=f"(lo), "=f"(hi) : "l"(v));
}
__device__ __forceinline__ u64 ffma2(u64 a, u64 b, u64 c) {
    u64 r; asm("fma.rn.f32x2 %0,%1,%2,%3;" : "=l"(r) : "l"(a), "l"(b), "l"(c)); return r;
}
__device__ __forceinline__ u64 fadd2(u64 a, u64 b) {
    u64 r; asm("add.rn.f32x2 %0,%1,%2;" : "=l"(r) : "l"(a), "l"(b)); return r;
}
__device__ __forceinline__ u64 fmul2(u64 a, u64 b) {
    u64 r; asm("mul.rn.f32x2 %0,%1,%2;" : "=l"(r) : "l"(a), "l"(b)); return r;
}
__device__ __forceinline__ unsigned redux_max(unsigned v) {
    unsigned r; asm("redux.sync.max.u32 %0, %1, 0xffffffff;" : "=r"(r) : "r"(v)); return r;
}
__device__ __forceinline__ unsigned redux_min(unsigned v) {
    unsigned r; asm("redux.sync.min.u32 %0, %1, 0xffffffff;" : "=r"(r) : "r"(v)); return r;
}

// ---------------- fused FPS + ymm: blocks 0..3 FPS, 4..2051 ymm ------------
// fps dynamic smem: pos[12288] floats | fidx[1024] ints | red[2][32] u64
#define FPS_OFF_FIDX 12288
#define FPS_OFF_RED  13312
#define FPS_SMEM     ((13312 + 128) * 4)     // 53760 B
__global__ void __launch_bounds__(1024) fps_ymm_kernel(const float* __restrict__ pos,
                                                       const float* __restrict__ x,
                                                       const float* __restrict__ w11,
                                                       const float* __restrict__ w21,
                                                       float* __restrict__ out) {
    extern __shared__ float fsm[];
    const int t = threadIdx.x;

    if (blockIdx.x >= BGR) {
        // ---- ymm path: Y = X @ W1[:64,:], 16 rows per block, 1024/branch --
        int vb = blockIdx.x - BGR;               // 0..2047
        int br = (vb < 1024) ? 1 : 0;
        const float* W1 = br ? w21 : w11;
        float* sW = fsm;                          // 4096 floats
        float* sx = fsm + 4096;                   // 1024 floats
        for (int i = t; i < 4096; i += 1024) sW[i] = W1[i];
        int p0 = (vb & 1023) * 16;
        sx[t] = x[(size_t)p0 * 64 + t];
        __syncthreads();
        int lp = t >> 6, c = t & 63;
        float acc = 0.f;
#pragma unroll
        for (int k = 0; k < 64; k++) acc += sx[lp * 64 + k] * sW[k * 64 + c];
        g_Y[br][(size_t)(p0 + lp) * 64 + c] = acc;
        return;
    }

    // ---- fps path: 1024 threads, 4 points/thread ----
    int* s_fidx = (int*)(fsm + FPS_OFF_FIDX);
    u64* s_red  = (u64*)(fsm + FPS_OFF_RED);      // [2][32] double-buffered

    const int g = blockIdx.x;
    const float* p = pos + (size_t)g * NPER * 3;
    const int lane = t & 31, wid = t >> 5;

    u64 px2[2], py2[2], pz2[2];
    float dist[4];
    const float p0x = p[0], p0y = p[1], p0z = p[2];
    const u64 nw0x = pk2(-p0x, -p0x), nw0y = pk2(-p0y, -p0y), nw0z = pk2(-p0z, -p0z);
    float bbf = 0.f;
#pragma unroll
    for (int i = 0; i < 2; i++) {
        int id0 = t + (2 * i) * 1024, id1 = t + (2 * i + 1) * 1024;
        float x0 = p[id0 * 3 + 0], y0 = p[id0 * 3 + 1], z0 = p[id0 * 3 + 2];
        float x1 = p[id1 * 3 + 0], y1 = p[id1 * 3 + 1], z1 = p[id1 * 3 + 2];
        fsm[id0 * 3 + 0] = x0; fsm[id0 * 3 + 1] = y0; fsm[id0 * 3 + 2] = z0;
        fsm[id1 * 3 + 0] = x1; fsm[id1 * 3 + 1] = y1; fsm[id1 * 3 + 2] = z1;
        px2[i] = pk2(x0, x1); py2[i] = pk2(y0, y1); pz2[i] = pk2(z0, z1);
        u64 dx = fadd2(px2[i], nw0x), dy = fadd2(py2[i], nw0y), dz = fadd2(pz2[i], nw0z);
        u64 ss = fadd2(fadd2(fmul2(dx, dx), fmul2(dy, dy)), fmul2(dz, dz));
        float s0, s1; upk2(ss, s0, s1);
        dist[2 * i] = s0; dist[2 * i + 1] = s1;
        bbf = fmaxf(bbf, fmaxf(s0, s1));
    }
    if (t == 0) s_fidx[0] = 0;

    for (int s = 1; s < MPER; s++) {
        // per-warp speculative (max bits, min index achieving it)
        unsigned cand = 0xffffffffu;
#pragma unroll
        for (int i = 0; i < 4; i++) {
            if (dist[i] == bbf) cand = min(cand, (unsigned)(t + i * 1024));
        }
        unsigned bits = __float_as_uint(bbf);      // dist >= 0: float order == uint order
        unsigned wbits = redux_max(bits);
        unsigned c2 = (bits == wbits) ? cand : 0xffffffffu;
        c2 = redux_min(c2);
        u64* buf = s_red + (s & 1) * 32;
        if (lane == 0) buf[wid] = ((u64)wbits << 32) | c2;
        __syncthreads();
        // every warp redundantly reduces the 32 warp entries (no 2nd barrier)
        u64 v = buf[lane];
        unsigned b32 = (unsigned)(v >> 32);
        unsigned rd = redux_max(b32);
        unsigned c3 = (b32 == rd) ? (unsigned)v : 0xffffffffu;
        unsigned widx = redux_min(c3);
        if (t == 0) s_fidx[s] = (int)widx;

        const float wx = fsm[widx * 3 + 0], wy = fsm[widx * 3 + 1], wz = fsm[widx * 3 + 2];
        const u64 nwx = pk2(-wx, -wx), nwy = pk2(-wy, -wy), nwz = pk2(-wz, -wz);
        bbf = 0.f;
#pragma unroll
        for (int i = 0; i < 2; i++) {
            u64 dx = fadd2(px2[i], nwx), dy = fadd2(py2[i], nwy), dz = fadd2(pz2[i], nwz);
            u64 ss = fadd2(fadd2(fmul2(dx, dx), fmul2(dy, dy)), fmul2(dz, dz));
            float s0, s1; upk2(ss, s0, s1);
            float n0 = fminf(dist[2 * i], s0), n1 = fminf(dist[2 * i + 1], s1);
            dist[2 * i] = n0; dist[2 * i + 1] = n1;
            bbf = fmaxf(bbf, fmaxf(n0, n1));
        }
    }
    __syncthreads();

    for (int s = t; s < MPER; s += 1024) {
        int li = s_fidx[s];
        int c = g * MPER + s;
        float xx = fsm[li * 3 + 0], yy = fsm[li * 3 + 1], zz = fsm[li * 3 + 2];
        g_pdst[c * 3 + 0] = xx; g_pdst[c * 3 + 1] = yy; g_pdst[c * 3 + 2] = zz;
        out[POFF + c * 3 + 0] = xx;
        out[POFF + c * 3 + 1] = yy;
        out[POFF + c * 3 + 2] = zz;
        out[BOFF + c] = (float)g;
    }
}

// ---------------- ball query + radix-bucket top-64 -------------------------
#define HISTN 512
#define SELCAP 1024
__global__ void __launch_bounds__(256) select_kernel(const float* __restrict__ pos) {
    __shared__ u64 key[NPER];
    __shared__ int hist[HISTN];
    __shared__ u64 selbuf[SELCAP];
    __shared__ unsigned s_wsum[8];
    __shared__ int s_cnt, s_bstar, s_base, s_sel;

    const int c = blockIdx.x;
    const int tid = threadIdx.x;
    const int lane = tid & 31, w = tid >> 5;
    const int g = c >> 10;
    const float* p = pos + (size_t)g * NPER * 3;
    const float cx = g_pdst[c * 3 + 0], cy = g_pdst[c * 3 + 1], cz = g_pdst[c * 3 + 2];

    if (tid == 0) { s_cnt = 0; s_bstar = 0x7fffffff; s_sel = 0; }
    for (int i = tid; i < HISTN; i += 256) hist[i] = 0;
    __syncthreads();

    for (int i = tid; i < NPER; i += 256) {
        float d2 = d2_exact(p[i * 3], p[i * 3 + 1], p[i * 3 + 2], cx, cy, cz);
        if (d2 <= R2SQ) {
            unsigned bits = __float_as_uint(d2);
            int b = (int)(bits >> 21);
            unsigned am = __activemask();
            int rank = __popc(am & ((1u << lane) - 1));
            int ldr = __ffs(am) - 1;
            int base;
            if (lane == ldr) base = atomicAdd(&s_cnt, __popc(am));
            base = __shfl_sync(am, base, ldr);
            key[base + rank] = ((u64)bits << 32) | (unsigned)i;
            unsigned mm = __match_any_sync(am, b);
            if (lane == (__ffs(mm) - 1)) atomicAdd(&hist[b], __popc(mm));
        }
    }
    __syncthreads();
    const int m = s_cnt;
    const int need = (m < 64) ? m : 64;

    {
        int h0 = hist[2 * tid], h1 = hist[2 * tid + 1];
        unsigned l = (unsigned)(h0 + h1);
        unsigned v = l;
#pragma unroll
        for (int o = 1; o < 32; o <<= 1) {
            unsigned n = __shfl_up_sync(0xffffffffu, v, o);
            if (lane >= o) v += n;
        }
        if (lane == 31) s_wsum[w] = v;
        __syncthreads();
        unsigned woff = 0;
#pragma unroll
        for (int q = 0; q < 8; q++) woff += (q < w) ? s_wsum[q] : 0;
        unsigned ex = woff + v - l;
        int cum0 = (int)ex + h0;
        int cum1 = cum0 + h1;
        int cand = 0x7fffffff;
        if (cum0 >= need) cand = 2 * tid;
        else if (cum1 >= need) cand = 2 * tid + 1;
        if (cand != 0x7fffffff) atomicMin(&s_bstar, cand);
        __syncthreads();
        int bs = s_bstar;
        if (bs == 2 * tid) s_base = (int)ex;
        else if (bs == 2 * tid + 1) s_base = cum0;
        __syncthreads();
    }
    const int bstar = s_bstar;

    for (int i = tid; i < m; i += 256) {
        u64 kk = key[i];
        int b = (int)((unsigned)(kk >> 32) >> 21);
        if (b <= bstar) {
            int s = atomicAdd(&s_sel, 1);
            if (s < SELCAP) selbuf[s] = kk;
        }
    }
    __syncthreads();
    int S = s_sel; if (S > SELCAP) S = SELCAP;
    int P2 = 64; while (P2 < S) P2 <<= 1;
    for (int i = S + tid; i < P2; i += 256) selbuf[i] = ~0ull;
    __syncthreads();

    for (int k2 = 2; k2 <= P2; k2 <<= 1) {
        for (int j = k2 >> 1; j > 0; j >>= 1) {
            for (int i = tid; i < P2; i += 256) {
                int l = i ^ j;
                if (l > i) {
                    u64 a = selbuf[i], b = selbuf[l];
                    bool up = ((i & k2) == 0);
                    if (up ? (a > b) : (a < b)) { selbuf[i] = b; selbuf[l] = a; }
                }
            }
            __syncthreads();
        }
    }

    if (tid < KN2) {
        u64 kk = selbuf[tid];
        int idx = (int)(kk & 0xffffffffu);
        bool v2 = tid < m;
        g_nbr2[c * KN2 + tid] = v2 ? idx : -1;
        if (tid < KN1) {
            float d2 = __uint_as_float((unsigned)(kk >> 32));
            g_nbr1[c * KN1 + tid] = (v2 && d2 <= R1SQ) ? idx : -1;
        }
    }
}

// ---------------- MLP + max-pool: merged register-tiled GEMM ---------------
// grid 3072: bid<2048 -> branch2 (K=64,G=2,coloff=128); else branch1 (K=32,G=4).
__global__ void __launch_bounds__(128, 1) mlp_kernel(const float* __restrict__ pos,
                                                     const float* __restrict__ w11,
                                                     const float* __restrict__ b11,
                                                     const float* __restrict__ w12,
                                                     const float* __restrict__ b12,
                                                     const float* __restrict__ w13,
                                                     const float* __restrict__ b13,
                                                     const float* __restrict__ w21,
                                                     const float* __restrict__ b21,
                                                     const float* __restrict__ w22,
                                                     const float* __restrict__ b22,
                                                     const float* __restrict__ w23,
                                                     const float* __restrict__ b23,
                                                     float* __restrict__ out) {
    extern __shared__ float sm[];
    const int tid = threadIdx.x;
    const int lane = tid & 31, w = tid >> 5;
    const int rg = lane >> 3, cg = lane & 7;
    const int base_r = w * 32 + rg * 8;
    const int colA = 4 * cg, colB = 32 + 4 * cg;

    const bool br2 = blockIdx.x < 2048;
    const int bid2 = br2 ? blockIdx.x : (blockIdx.x - 2048);
    const int G = br2 ? 2 : 4;
    const int coloff = br2 ? 128 : 0;
    const float* W1 = br2 ? w21 : w11;
    const float* B1 = br2 ? b21 : b11;
    const float* W2 = br2 ? w22 : w12;
    const float* B2 = br2 ? b22 : b12;
    const float* W3 = br2 ? w23 : w13;
    const float* B3 = br2 ? b23 : b13;
    const float* Y  = g_Y[br2 ? 1 : 0];
    const int* nbr  = br2 ? g_nbr2 : g_nbr1;
    const int K     = br2 ? KN2 : KN1;

    for (int i = tid; i < 4096; i += 128) sm[OFF_W2 + (i >> 6) * 68 + (i & 63)] = W2[i];
    for (int i = tid; i < 8192; i += 128) sm[OFF_W3 + (i >> 7) * 132 + (i & 127)] = W3[i];
    if (tid < 64) {
        sm[OFF_WP + tid]        = W1[4096 + tid];
        sm[OFF_WP + 64 + tid]   = W1[4096 + 64 + tid];
        sm[OFF_WP + 128 + tid]  = W1[4096 + 128 + tid];
        sm[OFF_B1 + tid] = B1[tid];
        sm[OFF_B2 + tid] = B2[tid];
    }
    sm[OFF_B3 + tid] = B3[tid];
    int* souti = (int*)(sm + OFF_OUT);
    for (int i = tid; i < G * 128; i += 128) souti[i] = 0;
    __syncthreads();

    {
        const int ci = br2 ? (tid >> 6) : (tid >> 5);
        const int n  = tid & (K - 1);
        const int crow = bid2 * G + ci;
        const int g = crow >> 10;

        int j = nbr[crow * K + n];
        const bool valid = (j >= 0);
        if (!valid) j = 0;
        ((int*)(sm + OFF_VALID))[tid] = valid ? 1 : 0;

        const float* pg = pos + (size_t)g * NPER * 3;
        const float dx = pg[j * 3 + 0] - g_pdst[crow * 3 + 0];
        const float dy = pg[j * 3 + 1] - g_pdst[crow * 3 + 1];
        const float dz = pg[j * 3 + 2] - g_pdst[crow * 3 + 2];
        const float* yrow = Y + (size_t)(g * NPER + j) * 64;

        const u64 dx2 = pk2(dx, dx), dy2 = pk2(dy, dy), dz2 = pk2(dz, dz);

        float h1[64];
#pragma unroll
        for (int c = 0; c < 64; c += 4) {
            ulonglong2 y2 = *(const ulonglong2*)(yrow + c);
            ulonglong2 w0 = *(const ulonglong2*)(sm + OFF_WP + c);
            ulonglong2 w1 = *(const ulonglong2*)(sm + OFF_WP + 64 + c);
            ulonglong2 w2 = *(const ulonglong2*)(sm + OFF_WP + 128 + c);
            ulonglong2 bb = *(const ulonglong2*)(sm + OFF_B1 + c);
            u64 t0 = ffma2(dx2, w0.x, y2.x);
            t0 = ffma2(dy2, w1.x, t0);
            t0 = ffma2(dz2, w2.x, t0);
            t0 = fadd2(t0, bb.x);
            u64 t1 = ffma2(dx2, w0.y, y2.y);
            t1 = ffma2(dy2, w1.y, t1);
            t1 = ffma2(dz2, w2.y, t1);
            t1 = fadd2(t1, bb.y);
            float a0, a1, a2, a3;
            upk2(t0, a0, a1); upk2(t1, a2, a3);
            h1[c + 0] = fmaxf(a0, 0.f);
            h1[c + 1] = fmaxf(a1, 0.f);
            h1[c + 2] = fmaxf(a2, 0.f);
            h1[c + 3] = fmaxf(a3, 0.f);
        }
#pragma unroll
        for (int c = 0; c < 64; c++)
            sm[OFF_H + c * 132 + (tid ^ (4 * (c >> 3)))] = h1[c];
    }
    __syncthreads();

    int vld[8];
#pragma unroll
    for (int r = 0; r < 8; r++) vld[r] = ((int*)(sm + OFF_VALID))[base_r + r];

    u64 acc[8][4];
    {
        float4 bA = *(const float4*)(sm + OFF_B2 + colA);
        float4 bB = *(const float4*)(sm + OFF_B2 + colB);
        u64 i0 = pk2(bA.x, bA.y), i1 = pk2(bA.z, bA.w);
        u64 i2 = pk2(bB.x, bB.y), i3 = pk2(bB.z, bB.w);
#pragma unroll
        for (int r = 0; r < 8; r++) { acc[r][0] = i0; acc[r][1] = i1; acc[r][2] = i2; acc[r][3] = i3; }
    }
#pragma unroll 4
    for (int k = 0; k < 64; k++) {
        int sw = 4 * (k >> 3);
        const float* hrow = sm + OFF_H + k * 132;
        float4 a0 = *(const float4*)(hrow + (base_r ^ sw));
        float4 a1 = *(const float4*)(hrow + ((base_r + 4) ^ sw));
        ulonglong2 wA = *(const ulonglong2*)(sm + OFF_W2 + k * 68 + colA);
        ulonglong2 wB = *(const ulonglong2*)(sm + OFF_W2 + k * 68 + colB);
        float av[8] = {a0.x, a0.y, a0.z, a0.w, a1.x, a1.y, a1.z, a1.w};
#pragma unroll
        for (int r = 0; r < 8; r++) {
            u64 ar = pk2(av[r], av[r]);
            acc[r][0] = ffma2(ar, wA.x, acc[r][0]);
            acc[r][1] = ffma2(ar, wA.y, acc[r][1]);
            acc[r][2] = ffma2(ar, wB.x, acc[r][2]);
            acc[r][3] = ffma2(ar, wB.y, acc[r][3]);
        }
    }
    __syncthreads();
#pragma unroll
    for (int p = 0; p < 4; p++) {
        int c0 = (p < 2) ? (colA + 2 * p) : (colB + 2 * (p - 2));
        float va[8], vb[8];
#pragma unroll
        for (int r = 0; r < 8; r++) {
            float x, y; upk2(acc[r][p], x, y);
            va[r] = fmaxf(x, 0.f); vb[r] = fmaxf(y, 0.f);
        }
        int sw = 4 * (c0 >> 3);
        float* d0 = sm + OFF_H + c0 * 132;
        float* d1 = d0 + 132;
        *(float4*)(d0 + (base_r ^ sw))       = make_float4(va[0], va[1], va[2], va[3]);
        *(float4*)(d0 + ((base_r + 4) ^ sw)) = make_float4(va[4], va[5], va[6], va[7]);
        *(float4*)(d1 + (base_r ^ sw))       = make_float4(vb[0], vb[1], vb[2], vb[3]);
        *(float4*)(d1 + ((base_r + 4) ^ sw)) = make_float4(vb[4], vb[5], vb[6], vb[7]);
    }
    __syncthreads();

    const int ci = br2 ? (w >> 1) : w;
#pragma unroll
    for (int po = 0; po < 128; po += 64) {
        {
            float4 bA = *(const float4*)(sm + OFF_B3 + po + colA);
            float4 bB = *(const float4*)(sm + OFF_B3 + po + colB);
            u64 i0 = pk2(bA.x, bA.y), i1 = pk2(bA.z, bA.w);
            u64 i2 = pk2(bB.x, bB.y), i3 = pk2(bB.z, bB.w);
#pragma unroll
            for (int r = 0; r < 8; r++) { acc[r][0] = i0; acc[r][1] = i1; acc[r][2] = i2; acc[r][3] = i3; }
        }
#pragma unroll 4
        for (int k = 0; k < 64; k++) {
            int sw = 4 * (k >> 3);
            const float* hrow = sm + OFF_H + k * 132;
            float4 a0 = *(const float4*)(hrow + (base_r ^ sw));
            float4 a1 = *(const float4*)(hrow + ((base_r + 4) ^ sw));
            ulonglong2 wA = *(const ulonglong2*)(sm + OFF_W3 + k * 132 + po + colA);
            ulonglong2 wB = *(const ulonglong2*)(sm + OFF_W3 + k * 132 + po + colB);
            float av[8] = {a0.x, a0.y, a0.z, a0.w, a1.x, a1.y, a1.z, a1.w};
#pragma unroll
            for (int r = 0; r < 8; r++) {
                u64 ar = pk2(av[r], av[r]);
                acc[r][0] = ffma2(ar, wA.x, acc[r][0]);
                acc[r][1] = ffma2(ar, wA.y, acc[r][1]);
                acc[r][2] = ffma2(ar, wB.x, acc[r][2]);
                acc[r][3] = ffma2(ar, wB.y, acc[r][3]);
            }
        }
#pragma unroll
        for (int p = 0; p < 4; p++) {
            int c0 = (p < 2) ? (colA + 2 * p) : (colB + 2 * (p - 2));
            float m0 = 0.f, m1 = 0.f;
#pragma unroll
            for (int r = 0; r < 8; r++) {
                float x, y; upk2(acc[r][p], x, y);
                float fx = vld[r] ? fmaxf(x, 0.f) : 0.f;
                float fy = vld[r] ? fmaxf(y, 0.f) : 0.f;
                m0 = fmaxf(m0, fx); m1 = fmaxf(m1, fy);
            }
            m0 = fmaxf(m0, __shfl_xor_sync(0xffffffffu, m0, 8));
            m0 = fmaxf(m0, __shfl_xor_sync(0xffffffffu, m0, 16));
            m1 = fmaxf(m1, __shfl_xor_sync(0xffffffffu, m1, 8));
            m1 = fmaxf(m1, __shfl_xor_sync(0xffffffffu, m1, 16));
            if (lane < 8) {
                atomicMax(&souti[ci * 128 + po + c0],     __float_as_int(m0));
                atomicMax(&souti[ci * 128 + po + c0 + 1], __float_as_int(m1));
            }
        }
    }
    __syncthreads();
    for (int i = tid; i < G * 128; i += 128) {
        int lc = i >> 7, ch = i & 127;
        out[(size_t)(bid2 * G + lc) * 256 + coloff + ch] = __int_as_float(souti[i]);
    }
}

// ---------------- launch ----------------
extern "C" void kernel_launch(void* const* d_in, const int* in_sizes, int n_in,
                              void* d_out, int out_size) {
    const float* x   = (const float*)d_in[0];
    const float* pos = (const float*)d_in[1];
    const float* w11 = (const float*)d_in[3];
    const float* b11 = (const float*)d_in[4];
    const float* w12 = (const float*)d_in[5];
    const float* b12 = (const float*)d_in[6];
    const float* w13 = (const float*)d_in[7];
    const float* b13 = (const float*)d_in[8];
    const float* w21 = (const float*)d_in[9];
    const float* b21 = (const float*)d_in[10];
    const float* w22 = (const float*)d_in[11];
    const float* b22 = (const float*)d_in[12];
    const float* w23 = (const float*)d_in[13];
    const float* b23 = (const float*)d_in[14];
    float* out = (float*)d_out;

    const int smemM = (OFF_OUT + 512) * 4;
    cudaFuncSetAttribute((const void*)mlp_kernel,
                         cudaFuncAttributeMaxDynamicSharedMemorySize, smemM);
    cudaFuncSetAttribute((const void*)fps_ymm_kernel,
                         cudaFuncAttributeMaxDynamicSharedMemorySize, FPS_SMEM);

    fps_ymm_kernel<<<BGR + 2048, 1024, FPS_SMEM>>>(pos, x, w11, w21, out);
    select_kernel<<<BGR * MPER, 256>>>(pos);
    mlp_kernel<<<3072, 128, smemM>>>(pos, w11, b11, w12, b12, w13, b13,
                                     w21, b21, w22, b22, w23, b23, out);
}

// round 11
// speedup vs baseline: 2.8389x; 1.1175x over previous
#include <cuda_runtime.h>
#include <cuda_bf16.h>
#include <cstdint>

#define BGR 4
#define NPER 4096
#define MPER 1024
#define DIN 64
#define KN1 32
#define KN2 64
#define R1SQ 0.04f
#define R2SQ 0.16f

#define POFF (BGR*MPER*256)          // 1048576
#define BOFF (POFF + BGR*MPER*3)     // 1060864

typedef unsigned long long u64;

// role bid layout
#define YMM_BASE 4
#define YMM_N    8192
#define SEL_BASE (YMM_BASE + YMM_N)      // 8196
#define SEL_N    4096
#define MLP_BASE (SEL_BASE + SEL_N)      // 12292
#define MLP_N    3072
#define GRID_N   (MLP_BASE + MLP_N)      // 15364

// smem float offsets for mlp role
#define OFF_W2   0                   // [64][68]
#define OFF_W3   4352                // [64][132]
#define OFF_H    12800               // [64][132]
#define OFF_WP   21248               // [3][64]
#define OFF_B1   21440
#define OFF_B2   21504
#define OFF_B3   21568               // [128]
#define OFF_VALID 21696              // [128] ints
#define OFF_OUT  21824               // [up to 512] ints
#define SMEM_WORDS (OFF_OUT + 512)   // 22336 floats = 89344 B

// fps smem offsets
#define FPS_OFF_FIDX 12288
#define FPS_OFF_RED  13312           // 2*8 u64

// select params
#define HISTN 512
#define SELCAP 1024

// ---------------- scratch (device globals; zero-init; no alloc allowed) ----
__device__ float g_pdst[BGR*MPER*3];
__device__ int   g_nbr1[BGR*MPER*KN1];
__device__ int   g_nbr2[BGR*MPER*KN2];
__device__ float g_Y[2][BGR*NPER*DIN];
__device__ volatile int g_prog[BGR];          // fps centroid publication count
__device__ volatile int g_sel_flag[BGR*MPER]; // select done per centroid
__device__ int g_ymm_done[2];                 // monotone counters (never reset)

// ---------------- helpers ----------------
__device__ __forceinline__ float d2_exact(float ax, float ay, float az,
                                          float bx, float by, float bz) {
    float dx = __fsub_rn(ax, bx);
    float dy = __fsub_rn(ay, by);
    float dz = __fsub_rn(az, bz);
    return __fadd_rn(__fadd_rn(__fmul_rn(dx, dx), __fmul_rn(dy, dy)), __fmul_rn(dz, dz));
}
__device__ __forceinline__ u64 pk2(float lo, float hi) {
    u64 r; asm("mov.b64 %0,{%1,%2};" : "=l"(r) : "f"(lo), "f"(hi)); return r;
}
__device__ __forceinline__ void upk2(u64 v, float& lo, float& hi) {
    asm("mov.b64 {%0,%1}, %2;" : "=f"(lo), "=f"(hi) : "l"(v));
}
__device__ __forceinline__ u64 ffma2(u64 a, u64 b, u64 c) {
    u64 r; asm("fma.rn.f32x2 %0,%1,%2,%3;" : "=l"(r) : "l"(a), "l"(b), "l"(c)); return r;
}
__device__ __forceinline__ u64 fadd2(u64 a, u64 b) {
    u64 r; asm("add.rn.f32x2 %0,%1,%2;" : "=l"(r) : "l"(a), "l"(b)); return r;
}
__device__ __forceinline__ u64 fmul2(u64 a, u64 b) {
    u64 r; asm("mul.rn.f32x2 %0,%1,%2;" : "=l"(r) : "l"(a), "l"(b)); return r;
}
__device__ __forceinline__ unsigned redux_max(unsigned v) {
    unsigned r; asm("redux.sync.max.u32 %0, %1, 0xffffffff;" : "=r"(r) : "r"(v)); return r;
}
__device__ __forceinline__ unsigned redux_min(unsigned v) {
    unsigned r; asm("redux.sync.min.u32 %0, %1, 0xffffffff;" : "=r"(r) : "r"(v)); return r;
}

// ============================ mega kernel ==================================
__global__ void __launch_bounds__(256, 2)
mega_kernel(const float* __restrict__ pos,
            const float* __restrict__ x,
            const float* __restrict__ w11, const float* __restrict__ b11,
            const float* __restrict__ w12, const float* __restrict__ b12,
            const float* __restrict__ w13, const float* __restrict__ b13,
            const float* __restrict__ w21, const float* __restrict__ b21,
            const float* __restrict__ w22, const float* __restrict__ b22,
            const float* __restrict__ w23, const float* __restrict__ b23,
            float* __restrict__ out) {
    extern __shared__ float sm[];
    const int bid = blockIdx.x;
    const int tid = threadIdx.x;
    const int lane = tid & 31;

    // ======================= role: ymm =====================================
    if (bid >= YMM_BASE && bid < SEL_BASE) {
        int vb = bid - YMM_BASE;                 // 0..8191
        int br = (vb < 4096) ? 1 : 0;
        const float* W1 = br ? w21 : w11;
        float* sW = sm;                           // 4096 floats
        float* sx = sm + 4096;                    // 256 floats
        for (int i = tid; i < 4096; i += 256) sW[i] = W1[i];
        int p0 = (vb & 4095) * 4;
        sx[tid] = x[(size_t)p0 * 64 + tid];
        __syncthreads();
        int lp = tid >> 6, c = tid & 63;
        float acc = 0.f;
#pragma unroll
        for (int k = 0; k < 64; k++) acc += sx[lp * 64 + k] * sW[k * 64 + c];
        g_Y[br][(size_t)(p0 + lp) * 64 + c] = acc;
        __threadfence();
        __syncthreads();
        if (tid == 0) atomicAdd(&g_ymm_done[br], 1);
        return;
    }

    // ======================= role: fps =====================================
    if (bid < BGR) {
        float* fsm = sm;
        int* s_fidx = (int*)(fsm + FPS_OFF_FIDX);
        u64* s_red  = (u64*)(fsm + FPS_OFF_RED);   // [2][8]

        const int g = bid;
        const float* p = pos + (size_t)g * NPER * 3;
        const int wid = tid >> 5;

        u64 px2[8], py2[8], pz2[8];
        float dist[16];
        const float p0x = p[0], p0y = p[1], p0z = p[2];
        const u64 nw0x = pk2(-p0x, -p0x), nw0y = pk2(-p0y, -p0y), nw0z = pk2(-p0z, -p0z);
        float bbf = 0.f;
#pragma unroll
        for (int i = 0; i < 8; i++) {
            int id0 = tid + (2 * i) * 256, id1 = tid + (2 * i + 1) * 256;
            float x0 = p[id0 * 3 + 0], y0 = p[id0 * 3 + 1], z0 = p[id0 * 3 + 2];
            float x1 = p[id1 * 3 + 0], y1 = p[id1 * 3 + 1], z1 = p[id1 * 3 + 2];
            fsm[id0 * 3 + 0] = x0; fsm[id0 * 3 + 1] = y0; fsm[id0 * 3 + 2] = z0;
            fsm[id1 * 3 + 0] = x1; fsm[id1 * 3 + 1] = y1; fsm[id1 * 3 + 2] = z1;
            px2[i] = pk2(x0, x1); py2[i] = pk2(y0, y1); pz2[i] = pk2(z0, z1);
            u64 dx = fadd2(px2[i], nw0x), dy = fadd2(py2[i], nw0y), dz = fadd2(pz2[i], nw0z);
            u64 ss = fadd2(fadd2(fmul2(dx, dx), fmul2(dy, dy)), fmul2(dz, dz));
            float s0, s1; upk2(ss, s0, s1);
            dist[2 * i] = s0; dist[2 * i + 1] = s1;
            bbf = fmaxf(bbf, fmaxf(s0, s1));
        }
        if (tid == 0) {
            s_fidx[0] = 0;
            g_pdst[(g << 10) * 3 + 0] = p0x;
            g_pdst[(g << 10) * 3 + 1] = p0y;
            g_pdst[(g << 10) * 3 + 2] = p0z;
        }

        for (int s = 1; s < MPER; s++) {
            unsigned cand = 0xffffffffu;
#pragma unroll
            for (int i = 0; i < 16; i++) {
                if (dist[i] == bbf) cand = min(cand, (unsigned)(tid + i * 256));
            }
            unsigned bits = __float_as_uint(bbf);
            unsigned wbits = redux_max(bits);
            unsigned c2 = (bits == wbits) ? cand : 0xffffffffu;
            c2 = redux_min(c2);
            u64* buf = s_red + (s & 1) * 8;
            if (lane == 0) buf[wid] = ((u64)wbits << 32) | c2;
            __syncthreads();
            u64 v = (lane < 8) ? buf[lane] : 0x00000000ffffffffull;
            unsigned b8 = (unsigned)(v >> 32);
            unsigned rd = redux_max(b8);
            unsigned c3 = (b8 == rd) ? (unsigned)v : 0xffffffffu;
            unsigned widx = redux_min(c3);

            const float wx = fsm[widx * 3 + 0], wy = fsm[widx * 3 + 1], wz = fsm[widx * 3 + 2];
            if (tid == 0) {
                s_fidx[s] = (int)widx;
                int c = (g << 10) + s;
                g_pdst[c * 3 + 0] = wx;
                g_pdst[c * 3 + 1] = wy;
                g_pdst[c * 3 + 2] = wz;
                if ((s & 15) == 15) { __threadfence(); g_prog[g] = s + 1; }
            }
            const u64 nwx = pk2(-wx, -wx), nwy = pk2(-wy, -wy), nwz = pk2(-wz, -wz);
            bbf = 0.f;
#pragma unroll
            for (int i = 0; i < 8; i++) {
                u64 dx = fadd2(px2[i], nwx), dy = fadd2(py2[i], nwy), dz = fadd2(pz2[i], nwz);
                u64 ss = fadd2(fadd2(fmul2(dx, dx), fmul2(dy, dy)), fmul2(dz, dz));
                float s0, s1; upk2(ss, s0, s1);
                float n0 = fminf(dist[2 * i], s0), n1 = fminf(dist[2 * i + 1], s1);
                dist[2 * i] = n0; dist[2 * i + 1] = n1;
                bbf = fmaxf(bbf, fmaxf(n0, n1));
            }
        }
        if (tid == 0) { __threadfence(); g_prog[g] = MPER; }
        __syncthreads();

        for (int s = tid; s < MPER; s += 256) {
            int li = s_fidx[s];
            int c = (g << 10) + s;
            out[POFF + c * 3 + 0] = fsm[li * 3 + 0];
            out[POFF + c * 3 + 1] = fsm[li * 3 + 1];
            out[POFF + c * 3 + 2] = fsm[li * 3 + 2];
            out[BOFF + c] = (float)g;
        }
        return;
    }

    // ======================= role: select ==================================
    if (bid >= SEL_BASE && bid < MLP_BASE) {
        u64* key    = (u64*)sm;                    // 4096 u64
        u64* selbuf = key + NPER;                  // 1024 u64
        int* hist   = (int*)(selbuf + SELCAP);     // 512 ints
        unsigned* s_wsum = (unsigned*)(hist + HISTN);  // 8
        int* scal   = (int*)(s_wsum + 8);          // cnt, bstar, base, sel

        const int idx = bid - SEL_BASE;            // 0..4095
        const int s = idx >> 2, g = idx & 3;
        const int c = (g << 10) + s;
        const int w = tid >> 5;
        const float* p = pos + (size_t)g * NPER * 3;

        if (tid == 0) { scal[0] = 0; scal[1] = 0x7fffffff; scal[3] = 0; }
        for (int i = tid; i < HISTN; i += 256) hist[i] = 0;
        if (tid == 0) {
            while (g_prog[g] < s + 1) __nanosleep(256);
            __threadfence();
        }
        __syncthreads();

        const float cx = __ldcg(&g_pdst[c * 3 + 0]);
        const float cy = __ldcg(&g_pdst[c * 3 + 1]);
        const float cz = __ldcg(&g_pdst[c * 3 + 2]);

        for (int i = tid; i < NPER; i += 256) {
            float d2 = d2_exact(p[i * 3], p[i * 3 + 1], p[i * 3 + 2], cx, cy, cz);
            if (d2 <= R2SQ) {
                unsigned bits = __float_as_uint(d2);
                int b = (int)(bits >> 21);
                unsigned am = __activemask();
                int rank = __popc(am & ((1u << lane) - 1));
                int ldr = __ffs(am) - 1;
                int base;
                if (lane == ldr) base = atomicAdd(&scal[0], __popc(am));
                base = __shfl_sync(am, base, ldr);
                key[base + rank] = ((u64)bits << 32) | (unsigned)i;
                unsigned mm = __match_any_sync(am, b);
                if (lane == (__ffs(mm) - 1)) atomicAdd(&hist[b], __popc(mm));
            }
        }
        __syncthreads();
        const int m = scal[0];
        const int need = (m < 64) ? m : 64;

        {
            int h0 = hist[2 * tid], h1 = hist[2 * tid + 1];
            unsigned l = (unsigned)(h0 + h1);
            unsigned v = l;
#pragma unroll
            for (int o = 1; o < 32; o <<= 1) {
                unsigned n = __shfl_up_sync(0xffffffffu, v, o);
                if (lane >= o) v += n;
            }
            if (lane == 31) s_wsum[w] = v;
            __syncthreads();
            unsigned woff = 0;
#pragma unroll
            for (int q = 0; q < 8; q++) woff += (q < w) ? s_wsum[q] : 0;
            unsigned ex = woff + v - l;
            int cum0 = (int)ex + h0;
            int cum1 = cum0 + h1;
            int cand = 0x7fffffff;
            if (cum0 >= need) cand = 2 * tid;
            else if (cum1 >= need) cand = 2 * tid + 1;
            if (cand != 0x7fffffff) atomicMin(&scal[1], cand);
            __syncthreads();
        }
        const int bstar = scal[1];

        for (int i = tid; i < m; i += 256) {
            u64 kk = key[i];
            int b = (int)((unsigned)(kk >> 32) >> 21);
            if (b <= bstar) {
                int s2 = atomicAdd(&scal[3], 1);
                if (s2 < SELCAP) selbuf[s2] = kk;
            }
        }
        __syncthreads();
        int S = scal[3]; if (S > SELCAP) S = SELCAP;
        int P2 = 64; while (P2 < S) P2 <<= 1;
        for (int i = S + tid; i < P2; i += 256) selbuf[i] = ~0ull;
        __syncthreads();

        for (int k2 = 2; k2 <= P2; k2 <<= 1) {
            for (int j = k2 >> 1; j > 0; j >>= 1) {
                for (int i = tid; i < P2; i += 256) {
                    int l = i ^ j;
                    if (l > i) {
                        u64 a = selbuf[i], b = selbuf[l];
                        bool up = ((i & k2) == 0);
                        if (up ? (a > b) : (a < b)) { selbuf[i] = b; selbuf[l] = a; }
                    }
                }
                __syncthreads();
            }
        }

        if (tid < KN2) {
            u64 kk = selbuf[tid];
            int idx2 = (int)(kk & 0xffffffffu);
            bool v2 = tid < m;
            g_nbr2[c * KN2 + tid] = v2 ? idx2 : -1;
            if (tid < KN1) {
                float d2 = __uint_as_float((unsigned)(kk >> 32));
                g_nbr1[c * KN1 + tid] = (v2 && d2 <= R1SQ) ? idx2 : -1;
            }
        }
        __threadfence();
        __syncthreads();
        if (tid == 0) g_sel_flag[c] = 1;
        return;
    }

    // ======================= role: mlp =====================================
    {
        if (tid >= 128) return;     // Volta+: exited threads excluded from bar

        const int mb = bid - MLP_BASE;             // 0..3071
        const bool br2 = mb < 2048;
        int crow0, G, coloff;
        if (br2) {
            int q = mb >> 2, g0 = mb & 3;
            crow0 = (g0 << 10) + q * 2; G = 2; coloff = 128;
        } else {
            int mb2 = mb - 2048;
            int q = mb2 >> 2, g0 = mb2 & 3;
            crow0 = (g0 << 10) + q * 4; G = 4; coloff = 0;
        }
        const float* W1 = br2 ? w21 : w11;
        const float* B1 = br2 ? b21 : b11;
        const float* W2 = br2 ? w22 : w12;
        const float* B2 = br2 ? b22 : b12;
        const float* W3 = br2 ? w23 : w13;
        const float* B3 = br2 ? b23 : b13;
        const float* Y  = g_Y[br2 ? 1 : 0];
        const int* nbr  = br2 ? g_nbr2 : g_nbr1;
        const int K     = br2 ? KN2 : KN1;
        const int brIdx = br2 ? 1 : 0;

        const int w = tid >> 5;
        const int rg = lane >> 3, cg = lane & 7;
        const int base_r = w * 32 + rg * 8;
        const int colA = 4 * cg, colB = 32 + 4 * cg;

        for (int i = tid; i < 4096; i += 128) sm[OFF_W2 + (i >> 6) * 68 + (i & 63)] = W2[i];
        for (int i = tid; i < 8192; i += 128) sm[OFF_W3 + (i >> 7) * 132 + (i & 127)] = W3[i];
        if (tid < 64) {
            sm[OFF_WP + tid]        = W1[4096 + tid];
            sm[OFF_WP + 64 + tid]   = W1[4096 + 64 + tid];
            sm[OFF_WP + 128 + tid]  = W1[4096 + 128 + tid];
            sm[OFF_B1 + tid] = B1[tid];
            sm[OFF_B2 + tid] = B2[tid];
        }
        sm[OFF_B3 + tid] = B3[tid];
        int* souti = (int*)(sm + OFF_OUT);
        for (int i = tid; i < G * 128; i += 128) souti[i] = 0;

        if (tid == 0) {
            while (((volatile int*)g_ymm_done)[brIdx] < 4096) __nanosleep(256);
            for (int ci = 0; ci < G; ci++)
                while (g_sel_flag[crow0 + ci] == 0) __nanosleep(256);
            __threadfence();
        }
        __syncthreads();

        {
            const int ci = br2 ? (tid >> 6) : (tid >> 5);
            const int n  = tid & (K - 1);
            const int crow = crow0 + ci;
            const int g = crow >> 10;

            int j = nbr[crow * K + n];
            const bool valid = (j >= 0);
            if (!valid) j = 0;
            ((int*)(sm + OFF_VALID))[tid] = valid ? 1 : 0;

            const float* pg = pos + (size_t)g * NPER * 3;
            const float dx = pg[j * 3 + 0] - __ldcg(&g_pdst[crow * 3 + 0]);
            const float dy = pg[j * 3 + 1] - __ldcg(&g_pdst[crow * 3 + 1]);
            const float dz = pg[j * 3 + 2] - __ldcg(&g_pdst[crow * 3 + 2]);
            const float* yrow = Y + (size_t)(g * NPER + j) * 64;

            const u64 dx2 = pk2(dx, dx), dy2 = pk2(dy, dy), dz2 = pk2(dz, dz);

            float h1[64];
#pragma unroll
            for (int c = 0; c < 64; c += 4) {
                ulonglong2 y2 = *(const ulonglong2*)(yrow + c);
                ulonglong2 w0 = *(const ulonglong2*)(sm + OFF_WP + c);
                ulonglong2 w1 = *(const ulonglong2*)(sm + OFF_WP + 64 + c);
                ulonglong2 w2 = *(const ulonglong2*)(sm + OFF_WP + 128 + c);
                ulonglong2 bb = *(const ulonglong2*)(sm + OFF_B1 + c);
                u64 t0 = ffma2(dx2, w0.x, y2.x);
                t0 = ffma2(dy2, w1.x, t0);
                t0 = ffma2(dz2, w2.x, t0);
                t0 = fadd2(t0, bb.x);
                u64 t1 = ffma2(dx2, w0.y, y2.y);
                t1 = ffma2(dy2, w1.y, t1);
                t1 = ffma2(dz2, w2.y, t1);
                t1 = fadd2(t1, bb.y);
                float a0, a1, a2, a3;
                upk2(t0, a0, a1); upk2(t1, a2, a3);
                h1[c + 0] = fmaxf(a0, 0.f);
                h1[c + 1] = fmaxf(a1, 0.f);
                h1[c + 2] = fmaxf(a2, 0.f);
                h1[c + 3] = fmaxf(a3, 0.f);
            }
#pragma unroll
            for (int c = 0; c < 64; c++)
                sm[OFF_H + c * 132 + (tid ^ (4 * (c >> 3)))] = h1[c];
        }
        __syncthreads();

        int vld[8];
#pragma unroll
        for (int r = 0; r < 8; r++) vld[r] = ((int*)(sm + OFF_VALID))[base_r + r];

        u64 acc[8][4];
        {
            float4 bA = *(const float4*)(sm + OFF_B2 + colA);
            float4 bB = *(const float4*)(sm + OFF_B2 + colB);
            u64 i0 = pk2(bA.x, bA.y), i1 = pk2(bA.z, bA.w);
            u64 i2 = pk2(bB.x, bB.y), i3 = pk2(bB.z, bB.w);
#pragma unroll
            for (int r = 0; r < 8; r++) { acc[r][0] = i0; acc[r][1] = i1; acc[r][2] = i2; acc[r][3] = i3; }
        }
#pragma unroll 4
        for (int k = 0; k < 64; k++) {
            int sw = 4 * (k >> 3);
            const float* hrow = sm + OFF_H + k * 132;
            float4 a0 = *(const float4*)(hrow + (base_r ^ sw));
            float4 a1 = *(const float4*)(hrow + ((base_r + 4) ^ sw));
            ulonglong2 wA = *(const ulonglong2*)(sm + OFF_W2 + k * 68 + colA);
            ulonglong2 wB = *(const ulonglong2*)(sm + OFF_W2 + k * 68 + colB);
            float av[8] = {a0.x, a0.y, a0.z, a0.w, a1.x, a1.y, a1.z, a1.w};
#pragma unroll
            for (int r = 0; r < 8; r++) {
                u64 ar = pk2(av[r], av[r]);
                acc[r][0] = ffma2(ar, wA.x, acc[r][0]);
                acc[r][1] = ffma2(ar, wA.y, acc[r][1]);
                acc[r][2] = ffma2(ar, wB.x, acc[r][2]);
                acc[r][3] = ffma2(ar, wB.y, acc[r][3]);
            }
        }
        __syncthreads();
#pragma unroll
        for (int p = 0; p < 4; p++) {
            int c0 = (p < 2) ? (colA + 2 * p) : (colB + 2 * (p - 2));
            float va[8], vb[8];
#pragma unroll
            for (int r = 0; r < 8; r++) {
                float xx, yy; upk2(acc[r][p], xx, yy);
                va[r] = fmaxf(xx, 0.f); vb[r] = fmaxf(yy, 0.f);
            }
            int sw = 4 * (c0 >> 3);
            float* d0 = sm + OFF_H + c0 * 132;
            float* d1 = d0 + 132;
            *(float4*)(d0 + (base_r ^ sw))       = make_float4(va[0], va[1], va[2], va[3]);
            *(float4*)(d0 + ((base_r + 4) ^ sw)) = make_float4(va[4], va[5], va[6], va[7]);
            *(float4*)(d1 + (base_r ^ sw))       = make_float4(vb[0], vb[1], vb[2], vb[3]);
            *(float4*)(d1 + ((base_r + 4) ^ sw)) = make_float4(vb[4], vb[5], vb[6], vb[7]);
        }
        __syncthreads();

        const int ci = br2 ? (w >> 1) : w;
#pragma unroll
        for (int po = 0; po < 128; po += 64) {
            {
                float4 bA = *(const float4*)(sm + OFF_B3 + po + colA);
                float4 bB = *(const float4*)(sm + OFF_B3 + po + colB);
                u64 i0 = pk2(bA.x, bA.y), i1 = pk2(bA.z, bA.w);
                u64 i2 = pk2(bB.x, bB.y), i3 = pk2(bB.z, bB.w);
#pragma unroll
                for (int r = 0; r < 8; r++) { acc[r][0] = i0; acc[r][1] = i1; acc[r][2] = i2; acc[r][3] = i3; }
            }
#pragma unroll 4
            for (int k = 0; k < 64; k++) {
                int sw = 4 * (k >> 3);
                const float* hrow = sm + OFF_H + k * 132;
                float4 a0 = *(const float4*)(hrow + (base_r ^ sw));
                float4 a1 = *(const float4*)(hrow + ((base_r + 4) ^ sw));
                ulonglong2 wA = *(const ulonglong2*)(sm + OFF_W3 + k * 132 + po + colA);
                ulonglong2 wB = *(const ulonglong2*)(sm + OFF_W3 + k * 132 + po + colB);
                float av[8] = {a0.x, a0.y, a0.z, a0.w, a1.x, a1.y, a1.z, a1.w};
#pragma unroll
                for (int r = 0; r < 8; r++) {
                    u64 ar = pk2(av[r], av[r]);
                    acc[r][0] = ffma2(ar, wA.x, acc[r][0]);
                    acc[r][1] = ffma2(ar, wA.y, acc[r][1]);
                    acc[r][2] = ffma2(ar, wB.x, acc[r][2]);
                    acc[r][3] = ffma2(ar, wB.y, acc[r][3]);
                }
            }
#pragma unroll
            for (int p = 0; p < 4; p++) {
                int c0 = (p < 2) ? (colA + 2 * p) : (colB + 2 * (p - 2));
                float m0 = 0.f, m1 = 0.f;
#pragma unroll
                for (int r = 0; r < 8; r++) {
                    float xx, yy; upk2(acc[r][p], xx, yy);
                    float fx = vld[r] ? fmaxf(xx, 0.f) : 0.f;
                    float fy = vld[r] ? fmaxf(yy, 0.f) : 0.f;
                    m0 = fmaxf(m0, fx); m1 = fmaxf(m1, fy);
                }
                m0 = fmaxf(m0, __shfl_xor_sync(0xffffffffu, m0, 8));
                m0 = fmaxf(m0, __shfl_xor_sync(0xffffffffu, m0, 16));
                m1 = fmaxf(m1, __shfl_xor_sync(0xffffffffu, m1, 8));
                m1 = fmaxf(m1, __shfl_xor_sync(0xffffffffu, m1, 16));
                if (lane < 8) {
                    atomicMax(&souti[ci * 128 + po + c0],     __float_as_int(m0));
                    atomicMax(&souti[ci * 128 + po + c0 + 1], __float_as_int(m1));
                }
            }
        }
        __syncthreads();
        for (int i = tid; i < G * 128; i += 128) {
            int lc = i >> 7, ch = i & 127;
            out[(size_t)(crow0 + lc) * 256 + coloff + ch] = __int_as_float(souti[i]);
        }
    }
}

// ---------------- launch ----------------
extern "C" void kernel_launch(void* const* d_in, const int* in_sizes, int n_in,
                              void* d_out, int out_size) {
    const float* x   = (const float*)d_in[0];
    const float* pos = (const float*)d_in[1];
    const float* w11 = (const float*)d_in[3];
    const float* b11 = (const float*)d_in[4];
    const float* w12 = (const float*)d_in[5];
    const float* b12 = (const float*)d_in[6];
    const float* w13 = (const float*)d_in[7];
    const float* b13 = (const float*)d_in[8];
    const float* w21 = (const float*)d_in[9];
    const float* b21 = (const float*)d_in[10];
    const float* w22 = (const float*)d_in[11];
    const float* b22 = (const float*)d_in[12];
    const float* w23 = (const float*)d_in[13];
    const float* b23 = (const float*)d_in[14];
    float* out = (float*)d_out;

    const int smemB = SMEM_WORDS * 4;   // 89344
    cudaFuncSetAttribute((const void*)mega_kernel,
                         cudaFuncAttributeMaxDynamicSharedMemorySize, smemB);

    mega_kernel<<<GRID_N, 256, smemB>>>(pos, x,
                                        w11, b11, w12, b12, w13, b13,
                                        w21, b21, w22, b22, w23, b23, out);
}